// round 4
// baseline (speedup 1.0000x reference)
#include <cuda_runtime.h>

#define CC    256
#define HEADS 64
#define HD    4
#define TT    32

typedef unsigned long long u64;

// Scratch (static device globals — no allocation at run time)
__device__ __align__(16) float g_q[2785280];      // (N,C,L) per level, concat
__device__ __align__(16) float g_k[2850816];      // (n,h,pair,d,2) per level, concat
__device__ __align__(16) float g_v[2850816];
__device__ __align__(16) float g_attn[2785280];   // (N,C,L)
__device__ float g_pooled[4 * 2 * CC];

__constant__ int c_L[4]     = {4096, 1024, 256, 64};
__constant__ int c_kvoff[4] = {0, 2113536, 2654208, 2801664};

// ---- packed f32x2 helpers ----
__device__ __forceinline__ u64 pk2(float a, float b) {
    u64 r; asm("mov.b64 %0,{%1,%2};" : "=l"(r) : "f"(a), "f"(b)); return r;
}
__device__ __forceinline__ void upk2(u64 v, float& a, float& b) {
    asm("mov.b64 {%0,%1},%2;" : "=f"(a), "=f"(b) : "l"(v));
}
__device__ __forceinline__ u64 fma2(u64 a, u64 b, u64 c) {
    u64 d; asm("fma.rn.f32x2 %0,%1,%2,%3;" : "=l"(d) : "l"(a), "l"(b), "l"(c)); return d;
}
__device__ __forceinline__ u64 mul2(u64 a, u64 b) {
    u64 d; asm("mul.rn.f32x2 %0,%1,%2;" : "=l"(d) : "l"(a), "l"(b)); return d;
}
__device__ __forceinline__ u64 add2(u64 a, u64 b) {
    u64 d; asm("add.rn.f32x2 %0,%1,%2;" : "=l"(d) : "l"(a), "l"(b)); return d;
}
__device__ __forceinline__ float ex2f(float x) {
    float r; asm("ex2.approx.f32 %0,%1;" : "=f"(r) : "f"(x)); return r;
}

// ---------------- pooled = mean over H*W of ds (also zeroes ds output) ----------------
__global__ void pooled_kernel(const float* __restrict__ d0, const float* __restrict__ d1,
                              const float* __restrict__ d2, const float* __restrict__ d3,
                              float* __restrict__ dsout) {
    __shared__ float red[256];
    int lvl = blockIdx.z, n = blockIdx.y, c = blockIdx.x;
    if (lvl == 0 && n == 0 && c == 0 && threadIdx.x < 8) dsout[threadIdx.x] = 0.f;
    const float* dp = (lvl == 0) ? d0 : (lvl == 1) ? d1 : (lvl == 2) ? d2 : d3;
    int L = c_L[lvl];
    const float* p = dp + (size_t)(n * CC + c) * L;
    float s = 0.f;
    for (int i = threadIdx.x; i < L; i += blockDim.x) s += p[i];
    red[threadIdx.x] = s;
    __syncthreads();
    for (int st = blockDim.x >> 1; st > 0; st >>= 1) {
        if (threadIdx.x < st) red[threadIdx.x] += red[threadIdx.x + st];
        __syncthreads();
    }
    if (threadIdx.x == 0) g_pooled[(lvl * 2 + n) * CC + c] = red[0] / (float)L;
}

// ---------------- ds token projections -> tail of k/v ----------------
__global__ void token_kernel(const float* __restrict__ Wdsk, const float* __restrict__ bdsk,
                             const float* __restrict__ Wdsv, const float* __restrict__ bdsv,
                             const float* __restrict__ gate) {
    int kind = blockIdx.y;                 // 0 = key, 1 = val
    int lvl = blockIdx.z >> 1, n = blockIdx.z & 1;
    int warp = threadIdx.x >> 5, lane = threadIdx.x & 31;
    int j = blockIdx.x * 8 + warp;         // 0..8191
    const float* Wr = (kind ? Wdsv : Wdsk) + (size_t)(lvl * 8192 + j) * 256;
    const float* pl = g_pooled + (lvl * 2 + n) * CC;
    float s = 0.f;
#pragma unroll
    for (int c = lane; c < 256; c += 32) s += Wr[c] * pl[c];
#pragma unroll
    for (int off = 16; off > 0; off >>= 1) s += __shfl_down_sync(0xffffffffu, s, off);
    if (lane == 0) {
        s += (kind ? bdsv : bdsk)[lvl * 8192 + j];
        if (kind) s *= 1.0f / (1.0f + __expf(-gate[lvl]));
        int h = j >> 7, d = (j >> 5) & 3, t = j & 31;
        int L = c_L[lvl], M = L + TT;
        int m = L + t;
        // pair layout: base + ((n*H+h)*(M/2) + m/2)*8 + d*2 + (m&1)
        size_t idx = (size_t)c_kvoff[lvl]
                   + ((size_t)((n * HEADS + h) * (M >> 1)) + (m >> 1)) * 8 + d * 2 + (m & 1);
        if (kind) g_v[idx] = s; else g_k[idx] = s;
    }
}

// ---------------- 256-K GEMM: OUT = W(256x256) @ X(256xL) + bias ----------------
__global__ void gemm256(const float* __restrict__ W, const float* __restrict__ bias,
                        const float* __restrict__ Xext, const float* __restrict__ res,
                        float* __restrict__ dext,
                        int L, int M, int off, int xoff, int outsel) {
    __shared__ float As[16][68];
    __shared__ float Bs[16][68];
    int n = blockIdx.z;
    int o0 = blockIdx.y * 64, l0 = blockIdx.x * 64;
    const float* X = (outsel == 3) ? (g_attn + xoff + (size_t)n * CC * L)
                                   : (Xext + (size_t)n * CC * L);
    int tx = threadIdx.x, ty = threadIdx.y;
    int t = ty * 16 + tx;
    float acc[4][4];
#pragma unroll
    for (int i = 0; i < 4; i++)
#pragma unroll
        for (int j = 0; j < 4; j++) acc[i][j] = 0.f;

    for (int k0 = 0; k0 < 256; k0 += 16) {
#pragma unroll
        for (int r = 0; r < 4; r++) {
            int idx = t + r * 256;
            As[idx & 15][idx >> 4] = W[(size_t)(o0 + (idx >> 4)) * 256 + k0 + (idx & 15)];
        }
#pragma unroll
        for (int r = 0; r < 4; r++) {
            int idx = t + r * 256;
            Bs[idx >> 6][idx & 63] = X[(size_t)(k0 + (idx >> 6)) * L + l0 + (idx & 63)];
        }
        __syncthreads();
#pragma unroll
        for (int kk = 0; kk < 16; kk++) {
            float a0 = As[kk][ty * 4], a1 = As[kk][ty * 4 + 1];
            float a2 = As[kk][ty * 4 + 2], a3 = As[kk][ty * 4 + 3];
            float b0 = Bs[kk][tx * 4], b1 = Bs[kk][tx * 4 + 1];
            float b2 = Bs[kk][tx * 4 + 2], b3 = Bs[kk][tx * 4 + 3];
            acc[0][0] += a0 * b0; acc[0][1] += a0 * b1; acc[0][2] += a0 * b2; acc[0][3] += a0 * b3;
            acc[1][0] += a1 * b0; acc[1][1] += a1 * b1; acc[1][2] += a1 * b2; acc[1][3] += a1 * b3;
            acc[2][0] += a2 * b0; acc[2][1] += a2 * b1; acc[2][2] += a2 * b2; acc[2][3] += a2 * b3;
            acc[3][0] += a3 * b0; acc[3][1] += a3 * b1; acc[3][2] += a3 * b2; acc[3][3] += a3 * b3;
        }
        __syncthreads();
    }
#pragma unroll
    for (int i = 0; i < 4; i++) {
        int o = o0 + ty * 4 + i;
        float bv = bias[o];
#pragma unroll
        for (int j = 0; j < 4; j++) {
            int l = l0 + tx * 4 + j;
            float v = acc[i][j] + bv;
            if (outsel == 0)
                g_q[off + (size_t)(n * CC + o) * L + l] = v;
            else if (outsel == 1 || outsel == 2) {
                int h = o >> 2, d = o & 3;
                size_t idx = (size_t)off
                           + ((size_t)((n * HEADS + h) * (M >> 1)) + (l >> 1)) * 8 + d * 2 + (l & 1);
                if (outsel == 1) g_k[idx] = v; else g_v[idx] = v;
            } else
                dext[off + (size_t)(n * CC + o) * L + l] = v + res[(size_t)(n * CC + o) * L + l];
        }
    }
}

// ---------------- fused streaming attention (packed f32x2, double-buffered KV) ----------------
// One thread per query, block = 256 threads. KV tiles of 256 keys are
// register-prefetched one tile ahead and staged through alternating smem buffers.
__global__ void __launch_bounds__(256) attn_kernel(int qoff, int kvoff, int L, int M,
                                                   float* __restrict__ dsout,
                                                   float inv_hl, int lvl) {
    __shared__ ulonglong2 sk[2][256];
    __shared__ ulonglong2 sv[2][256];
    __shared__ float red[8];
    int n = blockIdx.z, h = blockIdx.y;
    int lraw = blockIdx.x * 256 + threadIdx.x;
    int l = (lraw < L) ? lraw : (L - 1);
    const float SC = 0.5f * 1.4426950408889634f;   // scale * log2(e), folded into q
    size_t qb = (size_t)qoff + (size_t)(n * CC + h * HD) * L + l;
    float t0 = g_q[qb] * SC;                 u64 q0 = pk2(t0, t0);
    float t1 = g_q[qb + (size_t)L] * SC;     u64 q1 = pk2(t1, t1);
    float t2 = g_q[qb + 2 * (size_t)L] * SC; u64 q2 = pk2(t2, t2);
    float t3 = g_q[qb + 3 * (size_t)L] * SC; u64 q3 = pk2(t3, t3);
    const ulonglong2* kp = reinterpret_cast<const ulonglong2*>(g_k) + (kvoff >> 2)
                         + (size_t)(n * HEADS + h) * M;
    const ulonglong2* vp = reinterpret_cast<const ulonglong2*>(g_v) + (kvoff >> 2)
                         + (size_t)(n * HEADS + h) * M;
    u64 A0 = 0, A1 = 0, A2 = 0, A3 = 0, den2 = 0, ds2 = 0;

    int tiles = (M + 255) >> 8;
    // prologue: fetch tile 0 and stage it in buffer 0
    ulonglong2 rk = make_ulonglong2(0, 0), rv = make_ulonglong2(0, 0);
    if ((int)threadIdx.x < M) { rk = kp[threadIdx.x]; rv = vp[threadIdx.x]; }
    if ((int)threadIdx.x < min(256, M)) { sk[0][threadIdx.x] = rk; sv[0][threadIdx.x] = rv; }
    __syncthreads();

    int buf = 0;
    for (int t = 0; t < tiles; t++) {
        int base = t * 256;
        int cnt = min(256, M - base);
        // prefetch next tile into registers (latency overlapped with compute below)
        int nbase = base + 256;
        bool pf = (nbase < M) && ((int)threadIdx.x < (M - nbase));
        if (pf) { rk = kp[nbase + threadIdx.x]; rv = vp[nbase + threadIdx.x]; }

        const ulonglong2* skb = sk[buf];
        const ulonglong2* svb = sv[buf];
        int ts = L - base;
        if (ts > cnt) ts = cnt;
        if (ts < 0) ts = 0;
        int tp = ts >> 1, np = cnt >> 1;
#pragma unroll 4
        for (int p = 0; p < tp; p++) {
            ulonglong2 ka = skb[2 * p], kb = skb[2 * p + 1];
            u64 lg = fma2(q3, kb.y, fma2(q2, kb.x, fma2(q1, ka.y, mul2(q0, ka.x))));
            float x0, x1; upk2(lg, x0, x1);
            u64 w = pk2(ex2f(x0), ex2f(x1));
            ulonglong2 va = svb[2 * p], vb = svb[2 * p + 1];
            A0 = fma2(w, va.x, A0); A1 = fma2(w, va.y, A1);
            A2 = fma2(w, vb.x, A2); A3 = fma2(w, vb.y, A3);
            den2 = add2(den2, w);
        }
#pragma unroll 2
        for (int p = tp; p < np; p++) {
            ulonglong2 ka = skb[2 * p], kb = skb[2 * p + 1];
            u64 lg = fma2(q3, kb.y, fma2(q2, kb.x, fma2(q1, ka.y, mul2(q0, ka.x))));
            float x0, x1; upk2(lg, x0, x1);
            u64 w = pk2(ex2f(x0), ex2f(x1));
            ulonglong2 va = svb[2 * p], vb = svb[2 * p + 1];
            A0 = fma2(w, va.x, A0); A1 = fma2(w, va.y, A1);
            A2 = fma2(w, vb.x, A2); A3 = fma2(w, vb.y, A3);
            den2 = add2(den2, w);
            ds2 = add2(ds2, w);
        }
        // stage prefetched tile into the other buffer (no conflict with reads of buf)
        if (pf) { sk[buf ^ 1][threadIdx.x] = rk; sv[buf ^ 1][threadIdx.x] = rv; }
        __syncthreads();
        buf ^= 1;
    }

    float dl, dh; upk2(den2, dl, dh);
    float r = 1.0f / (dl + dh);   // ref clips total at 1e-6; ratio identical (scale cancels)
    if (lraw < L) {
        float a, b;
        upk2(A0, a, b); g_attn[qb] = (a + b) * r;
        upk2(A1, a, b); g_attn[qb + (size_t)L] = (a + b) * r;
        upk2(A2, a, b); g_attn[qb + 2 * (size_t)L] = (a + b) * r;
        upk2(A3, a, b); g_attn[qb + 3 * (size_t)L] = (a + b) * r;
    }
    float sl, sh; upk2(ds2, sl, sh);
    float contrib = (lraw < L) ? (sl + sh) * r : 0.f;
#pragma unroll
    for (int off = 16; off > 0; off >>= 1) contrib += __shfl_down_sync(0xffffffffu, contrib, off);
    int warp = threadIdx.x >> 5, lane = threadIdx.x & 31;
    if (lane == 0) red[warp] = contrib;
    __syncthreads();
    if (threadIdx.x == 0) {
        float s = 0.f;
#pragma unroll
        for (int i = 0; i < 8; i++) s += red[i];
        atomicAdd(&dsout[lvl * 2 + n], s * inv_hl);
    }
}

// ---------------- launch ----------------
extern "C" void kernel_launch(void* const* d_in, const int* in_sizes, int n_in,
                              void* d_out, int out_size) {
    const float* sp[4]; const float* iv[4]; const float* dd[4];
    for (int i = 0; i < 4; i++) {
        sp[i] = (const float*)d_in[i];
        iv[i] = (const float*)d_in[4 + i];
        dd[i] = (const float*)d_in[8 + i];
    }
    const float* Wq  = (const float*)d_in[12]; const float* bq  = (const float*)d_in[13];
    const float* Wk  = (const float*)d_in[14]; const float* bk  = (const float*)d_in[15];
    const float* Wv  = (const float*)d_in[16]; const float* bv  = (const float*)d_in[17];
    const float* Wo  = (const float*)d_in[18]; const float* bo  = (const float*)d_in[19];
    const float* Wdsk = (const float*)d_in[20]; const float* bdsk = (const float*)d_in[21];
    const float* Wdsv = (const float*)d_in[22]; const float* bdsv = (const float*)d_in[23];
    const float* gate = (const float*)d_in[24];
    float* out = (float*)d_out;

    static const int Lt[4]    = {4096, 1024, 256, 64};
    static const int qoff[4]  = {0, 2097152, 2621440, 2752512};
    static const int kvoff[4] = {0, 2113536, 2654208, 2801664};
    float* dsout = out + (out_size - 8);

    // Launch order puts attn(level 0) at launch index 5 so ncu (-s 5 -c 1) profiles it.
    pooled_kernel<<<dim3(256, 2, 4), 256>>>(dd[0], dd[1], dd[2], dd[3], dsout);
    token_kernel<<<dim3(1024, 2, 8), 256>>>(Wdsk, bdsk, Wdsv, bdsv, gate);

    for (int lv = 0; lv < 4; lv++) {
        int L = Lt[lv], M = L + 32;
        dim3 grid(L / 64, 4, 2), blk(16, 16);
        gemm256<<<grid, blk>>>(Wq + lv * 65536, bq + lv * 256, sp[lv], nullptr, nullptr,
                               L, M, qoff[lv], 0, 0);
        gemm256<<<grid, blk>>>(Wk + lv * 65536, bk + lv * 256, iv[lv], nullptr, nullptr,
                               L, M, kvoff[lv], 0, 1);
        gemm256<<<grid, blk>>>(Wv + lv * 65536, bv + lv * 256, iv[lv], nullptr, nullptr,
                               L, M, kvoff[lv], 0, 2);
        int gx = (L + 255) / 256; if (gx < 1) gx = 1;
        attn_kernel<<<dim3(gx, HEADS, 2), 256>>>(qoff[lv], kvoff[lv], L, M,
                                                 dsout, 1.0f / (64.0f * (float)L), lv);
    }
    for (int lv = 0; lv < 4; lv++) {
        int L = Lt[lv], M = L + 32;
        dim3 grid(L / 64, 4, 2), blk(16, 16);
        gemm256<<<grid, blk>>>(Wo + lv * 65536, bo + lv * 256, nullptr, sp[lv], out,
                               L, M, qoff[lv], qoff[lv], 3);
    }
}

// round 8
// speedup vs baseline: 1.1467x; 1.1467x over previous
#include <cuda_runtime.h>
#include <cuda_bf16.h>

#define CC    256
#define HEADS 64
#define HD    4
#define TT    32

typedef unsigned long long u64;
typedef unsigned int u32;

__device__ __align__(16) float g_q[2785280];      // (N,C,L) per level
__device__ __align__(16) float g_k[2850816];      // (n,h,m,4) per level
__device__ __align__(16) float g_v[2850816];
__device__ __align__(16) float g_attn[2785280];
__device__ float g_pooled[4 * 2 * CC];

__constant__ int c_L[4]     = {4096, 1024, 256, 64};
__constant__ int c_kvoff[4] = {0, 2113536, 2654208, 2801664};

__device__ __forceinline__ float ex2f(float x) {
    float r; asm("ex2.approx.f32 %0,%1;" : "=f"(r) : "f"(x)); return r;
}
__device__ __forceinline__ u32 pkbf(float lo, float hi) {   // low half = lo, high half = hi
    u32 r; asm("cvt.rn.bf16x2.f32 %0, %1, %2;" : "=r"(r) : "f"(hi), "f"(lo)); return r;
}
__device__ __forceinline__ float lowbf(u32 u)  { return __uint_as_float(u << 16); }
__device__ __forceinline__ float highbf(u32 u) { return __uint_as_float(u & 0xffff0000u); }
__device__ __forceinline__ u32 smem_u32(const void* p) {
    u32 a; asm("{.reg .u64 t; cvta.to.shared.u64 t, %1; cvt.u32.u64 %0, t;}" : "=r"(a) : "l"(p));
    return a;
}

// ---------------- pooled mean (also zeroes ds output) ----------------
__global__ void pooled_kernel(const float* __restrict__ d0, const float* __restrict__ d1,
                              const float* __restrict__ d2, const float* __restrict__ d3,
                              float* __restrict__ dsout) {
    __shared__ float red[256];
    int lvl = blockIdx.z, n = blockIdx.y, c = blockIdx.x;
    if (lvl == 0 && n == 0 && c == 0 && threadIdx.x < 8) dsout[threadIdx.x] = 0.f;
    const float* dp = (lvl == 0) ? d0 : (lvl == 1) ? d1 : (lvl == 2) ? d2 : d3;
    int L = c_L[lvl];
    const float* p = dp + (size_t)(n * CC + c) * L;
    float s = 0.f;
    for (int i = threadIdx.x; i < L; i += blockDim.x) s += p[i];
    red[threadIdx.x] = s;
    __syncthreads();
    for (int st = blockDim.x >> 1; st > 0; st >>= 1) {
        if (threadIdx.x < st) red[threadIdx.x] += red[threadIdx.x + st];
        __syncthreads();
    }
    if (threadIdx.x == 0) g_pooled[(lvl * 2 + n) * CC + c] = red[0] / (float)L;
}

// ---------------- ds token projections -> tail of k/v ----------------
__global__ void token_kernel(const float* __restrict__ Wdsk, const float* __restrict__ bdsk,
                             const float* __restrict__ Wdsv, const float* __restrict__ bdsv,
                             const float* __restrict__ gate) {
    int kind = blockIdx.y;
    int lvl = blockIdx.z >> 1, n = blockIdx.z & 1;
    int warp = threadIdx.x >> 5, lane = threadIdx.x & 31;
    int j = blockIdx.x * 8 + warp;
    const float* Wr = (kind ? Wdsv : Wdsk) + (size_t)(lvl * 8192 + j) * 256;
    const float* pl = g_pooled + (lvl * 2 + n) * CC;
    float s = 0.f;
#pragma unroll
    for (int c = lane; c < 256; c += 32) s += Wr[c] * pl[c];
#pragma unroll
    for (int off = 16; off > 0; off >>= 1) s += __shfl_down_sync(0xffffffffu, s, off);
    if (lane == 0) {
        s += (kind ? bdsv : bdsk)[lvl * 8192 + j];
        if (kind) s *= 1.0f / (1.0f + __expf(-gate[lvl]));
        int h = j >> 7, d = (j >> 5) & 3, t = j & 31;
        int L = c_L[lvl], M = L + TT;
        size_t idx = (size_t)c_kvoff[lvl] + ((size_t)((n * HEADS + h) * M) + (L + t)) * HD + d;
        if (kind) g_v[idx] = s; else g_k[idx] = s;
    }
}

// ---------------- 256-K GEMM ----------------
__global__ void gemm256(const float* __restrict__ W, const float* __restrict__ bias,
                        const float* __restrict__ Xext, const float* __restrict__ res,
                        float* __restrict__ dext,
                        int L, int M, int off, int xoff, int outsel) {
    __shared__ float As[16][68];
    __shared__ float Bs[16][68];
    int n = blockIdx.z;
    int o0 = blockIdx.y * 64, l0 = blockIdx.x * 64;
    const float* X = (outsel == 3) ? (g_attn + xoff + (size_t)n * CC * L)
                                   : (Xext + (size_t)n * CC * L);
    int tx = threadIdx.x, ty = threadIdx.y;
    int t = ty * 16 + tx;
    float acc[4][4];
#pragma unroll
    for (int i = 0; i < 4; i++)
#pragma unroll
        for (int j = 0; j < 4; j++) acc[i][j] = 0.f;
    for (int k0 = 0; k0 < 256; k0 += 16) {
#pragma unroll
        for (int r = 0; r < 4; r++) {
            int idx = t + r * 256;
            As[idx & 15][idx >> 4] = W[(size_t)(o0 + (idx >> 4)) * 256 + k0 + (idx & 15)];
        }
#pragma unroll
        for (int r = 0; r < 4; r++) {
            int idx = t + r * 256;
            Bs[idx >> 6][idx & 63] = X[(size_t)(k0 + (idx >> 6)) * L + l0 + (idx & 63)];
        }
        __syncthreads();
#pragma unroll
        for (int kk = 0; kk < 16; kk++) {
            float a0 = As[kk][ty * 4], a1 = As[kk][ty * 4 + 1];
            float a2 = As[kk][ty * 4 + 2], a3 = As[kk][ty * 4 + 3];
            float b0 = Bs[kk][tx * 4], b1 = Bs[kk][tx * 4 + 1];
            float b2 = Bs[kk][tx * 4 + 2], b3 = Bs[kk][tx * 4 + 3];
            acc[0][0] += a0 * b0; acc[0][1] += a0 * b1; acc[0][2] += a0 * b2; acc[0][3] += a0 * b3;
            acc[1][0] += a1 * b0; acc[1][1] += a1 * b1; acc[1][2] += a1 * b2; acc[1][3] += a1 * b3;
            acc[2][0] += a2 * b0; acc[2][1] += a2 * b1; acc[2][2] += a2 * b2; acc[2][3] += a2 * b3;
            acc[3][0] += a3 * b0; acc[3][1] += a3 * b1; acc[3][2] += a3 * b2; acc[3][3] += a3 * b3;
        }
        __syncthreads();
    }
#pragma unroll
    for (int i = 0; i < 4; i++) {
        int o = o0 + ty * 4 + i;
        float bv = bias[o];
#pragma unroll
        for (int j = 0; j < 4; j++) {
            int l = l0 + tx * 4 + j;
            float v = acc[i][j] + bv;
            if (outsel == 0)
                g_q[off + (size_t)(n * CC + o) * L + l] = v;
            else if (outsel == 1)
                g_k[off + ((size_t)((n * HEADS + (o >> 2)) * M) + l) * HD + (o & 3)] = v;
            else if (outsel == 2)
                g_v[off + ((size_t)((n * HEADS + (o >> 2)) * M) + l) * HD + (o & 3)] = v;
            else
                dext[off + (size_t)(n * CC + o) * L + l] = v + res[(size_t)(n * CC + o) * L + l];
        }
    }
}

// ---------------- HMMA attention: CTA = (n, h, 64-query tile), 4 warps x 16 queries ---
// S-mma m16n8k16 (compensated bf16 split of Q,K). Weights w split into
// w_hi + w_lo (bf16); V split into v_hi + v_lo. Two O-mmas (m16n8k16):
//   O += [w_hi|w_lo] x [v_hi;v_hi]  and  O += [w_hi|w_lo] x [v_lo;v_lo]
// => O = w*v to ~2^-16. V cols = [v0..v3, 1, ds-indicator, 0, 0]; OOB rows zero.
__global__ void __launch_bounds__(128) attn_mma(int qoff, int kvoff, int L, int M,
                                                float* __restrict__ dsout,
                                                float inv_hl, int lvl) {
    __shared__ __align__(16) uint4 s_k[128];    // per key: [khi01, klo01, khi23, klo23]
    __shared__ __align__(16) uint4 s_vh[128];   // per pair: hi channels [c0..c3],[1,ds,0,0]
    __shared__ __align__(16) uint4 s_vl[128];   // per pair: lo channels [c0..c3],[0,0,0,0]
    __shared__ float s_red[4];

    int tid = threadIdx.x, wid = tid >> 5, lane = tid & 31;
    int g = lane >> 2, tg = lane & 3;
    int n = blockIdx.z, h = blockIdx.y;
    int qlo = blockIdx.x * 64 + wid * 16 + g;      // rows g and g+8 of this warp's tile
    int qhi = qlo + 8;

    const float SCALE = 0.5f * 1.4426950408889634f;
    size_t qbase = (size_t)qoff + ((size_t)(n * CC) + h * HD) * L;   // FIX: include qoff

    // Build S-mma A fragment (register-resident, reused every block)
    u32 a0, a1, a2, a3;
    {
        float hlo[4], llo[4], hhi[4], lhi[4];
#pragma unroll
        for (int d = 0; d < 4; d++) {
            float v = g_q[qbase + (size_t)d * L + qlo] * SCALE;
            float hf = __bfloat162float(__float2bfloat16(v));
            hlo[d] = hf; llo[d] = v - hf;
            v = g_q[qbase + (size_t)d * L + qhi] * SCALE;
            hf = __bfloat162float(__float2bfloat16(v));
            hhi[d] = hf; lhi[d] = v - hf;
        }
        a0 = (tg == 0) ? pkbf(hlo[0], hlo[1]) : (tg == 1) ? pkbf(hlo[2], hlo[3])
           : (tg == 2) ? pkbf(llo[0], llo[1]) : pkbf(llo[2], llo[3]);
        a1 = (tg == 0) ? pkbf(hhi[0], hhi[1]) : (tg == 1) ? pkbf(hhi[2], hhi[3])
           : (tg == 2) ? pkbf(lhi[0], lhi[1]) : pkbf(lhi[2], lhi[3]);
        a2 = (tg < 2) ? a0 : 0u;
        a3 = (tg < 2) ? a1 : 0u;
    }

    const float4* kp = (const float4*)g_k + (kvoff >> 2) + (size_t)(n * HEADS + h) * M;
    const float4* vp = (const float4*)g_v + (kvoff >> 2) + (size_t)(n * HEADS + h) * M;

    float o0 = 0.f, o1 = 0.f, o2 = 0.f, o3 = 0.f;
    u32 skb = smem_u32(s_k), svhb = smem_u32(s_vh), svlb = smem_u32(s_vl);

    for (int base = 0; base < M; base += 128) {
        // ---- stage 128 keys + value hi/lo splits ----
        {
            int m = base + tid;
            float4 kk = (m < M) ? kp[m] : make_float4(0.f, 0.f, 0.f, 0.f);
            float k0h = __bfloat162float(__float2bfloat16(kk.x));
            float k1h = __bfloat162float(__float2bfloat16(kk.y));
            float k2h = __bfloat162float(__float2bfloat16(kk.z));
            float k3h = __bfloat162float(__float2bfloat16(kk.w));
            s_k[tid] = make_uint4(pkbf(k0h, k1h), pkbf(kk.x - k0h, kk.y - k1h),
                                  pkbf(k2h, k3h), pkbf(kk.z - k2h, kk.w - k3h));
            if (tid < 64) {
                int m0 = base + 2 * tid, m1 = m0 + 1;
                float4 v0 = (m0 < M) ? vp[m0] : make_float4(0.f, 0.f, 0.f, 0.f);
                float4 v1 = (m1 < M) ? vp[m1] : make_float4(0.f, 0.f, 0.f, 0.f);
                float one0 = (m0 < M) ? 1.f : 0.f, one1 = (m1 < M) ? 1.f : 0.f;
                float dsi0 = (m0 >= L && m0 < M) ? 1.f : 0.f;
                float dsi1 = (m1 >= L && m1 < M) ? 1.f : 0.f;
                u32 hx = pkbf(v0.x, v1.x), hy = pkbf(v0.y, v1.y);
                u32 hz = pkbf(v0.z, v1.z), hw = pkbf(v0.w, v1.w);
                s_vh[2 * tid]     = make_uint4(hx, hy, hz, hw);
                s_vh[2 * tid + 1] = make_uint4(pkbf(one0, one1), pkbf(dsi0, dsi1), 0u, 0u);
                s_vl[2 * tid]     = make_uint4(
                    pkbf(v0.x - lowbf(hx), v1.x - highbf(hx)),
                    pkbf(v0.y - lowbf(hy), v1.y - highbf(hy)),
                    pkbf(v0.z - lowbf(hz), v1.z - highbf(hz)),
                    pkbf(v0.w - lowbf(hw), v1.w - highbf(hw)));
                s_vl[2 * tid + 1] = make_uint4(0u, 0u, 0u, 0u);
            }
        }
        __syncthreads();
        // ---- 16 blocks of 8 keys ----
#pragma unroll
        for (int blk = 0; blk < 16; blk++) {
            u32 b0, b1;
            u32 addr = skb + ((u32)(blk * 8 + g) << 4) + ((u32)(tg & 1) << 3);
            asm("ld.shared.v2.u32 {%0,%1},[%2];" : "=r"(b0), "=r"(b1) : "r"(addr));
            b1 = (tg < 2) ? b1 : 0u;
            float c0, c1, c2, c3;
            asm("mma.sync.aligned.m16n8k16.row.col.f32.bf16.bf16.f32 "
                "{%0,%1,%2,%3},{%4,%5,%6,%7},{%8,%9},{%10,%11,%12,%13};"
                : "=f"(c0), "=f"(c1), "=f"(c2), "=f"(c3)
                : "r"(a0), "r"(a1), "r"(a2), "r"(a3), "r"(b0), "r"(b1),
                  "f"(0.f), "f"(0.f), "f"(0.f), "f"(0.f));
            float w0 = ex2f(c0), w1 = ex2f(c1), w2 = ex2f(c2), w3 = ex2f(c3);
            u32 wa0 = pkbf(w0, w1), wa1 = pkbf(w2, w3);
            u32 wl0 = pkbf(w0 - lowbf(wa0), w1 - highbf(wa0));
            u32 wl1 = pkbf(w2 - lowbf(wa1), w3 - highbf(wa1));
            u32 voff = ((u32)((blk * 4 + tg) * 8 + g) << 2);
            u32 vh, vl;
            asm("ld.shared.u32 %0,[%1];" : "=r"(vh) : "r"(svhb + voff));
            asm("ld.shared.u32 %0,[%1];" : "=r"(vl) : "r"(svlb + voff));
            asm("mma.sync.aligned.m16n8k16.row.col.f32.bf16.bf16.f32 "
                "{%0,%1,%2,%3},{%4,%5,%6,%7},{%8,%8},{%0,%1,%2,%3};"
                : "+f"(o0), "+f"(o1), "+f"(o2), "+f"(o3)
                : "r"(wa0), "r"(wa1), "r"(wl0), "r"(wl1), "r"(vh));
            asm("mma.sync.aligned.m16n8k16.row.col.f32.bf16.bf16.f32 "
                "{%0,%1,%2,%3},{%4,%5,%6,%7},{%8,%8},{%0,%1,%2,%3};"
                : "+f"(o0), "+f"(o1), "+f"(o2), "+f"(o3)
                : "r"(wa0), "r"(wa1), "r"(wl0), "r"(wl1), "r"(vl));
        }
        __syncthreads();
    }

    // ---- epilogue ----
    // Thread(tg) holds O cols 2tg,2tg+1 for rows g (o0,o1) and g+8 (o2,o3).
    // den (col 4) and ds (col 5) live on tg==2 threads.
    u32 full = 0xffffffffu;
    int src = (lane & 0x1c) | 2;
    float den_lo = __shfl_sync(full, o0, src);
    float den_hi = __shfl_sync(full, o2, src);
    if (tg < 2) {
        float rl = 1.0f / den_lo, rh = 1.0f / den_hi;
        int d0 = tg * 2, d1 = tg * 2 + 1;
        g_attn[qbase + (size_t)d0 * L + qlo] = o0 * rl;
        g_attn[qbase + (size_t)d1 * L + qlo] = o1 * rl;
        g_attn[qbase + (size_t)d0 * L + qhi] = o2 * rh;
        g_attn[qbase + (size_t)d1 * L + qhi] = o3 * rh;
    }
    float contrib = (tg == 2) ? (o1 / o0 + o3 / o2) : 0.f;
#pragma unroll
    for (int off = 16; off > 0; off >>= 1) contrib += __shfl_down_sync(full, contrib, off);
    if (lane == 0) s_red[wid] = contrib;
    __syncthreads();
    if (tid == 0)
        atomicAdd(&dsout[lvl * 2 + n], (s_red[0] + s_red[1] + s_red[2] + s_red[3]) * inv_hl);
}

// ---------------- launch ----------------
extern "C" void kernel_launch(void* const* d_in, const int* in_sizes, int n_in,
                              void* d_out, int out_size) {
    const float* sp[4]; const float* iv[4]; const float* dd[4];
    for (int i = 0; i < 4; i++) {
        sp[i] = (const float*)d_in[i];
        iv[i] = (const float*)d_in[4 + i];
        dd[i] = (const float*)d_in[8 + i];
    }
    const float* Wq  = (const float*)d_in[12]; const float* bq  = (const float*)d_in[13];
    const float* Wk  = (const float*)d_in[14]; const float* bk  = (const float*)d_in[15];
    const float* Wv  = (const float*)d_in[16]; const float* bv  = (const float*)d_in[17];
    const float* Wo  = (const float*)d_in[18]; const float* bo  = (const float*)d_in[19];
    const float* Wdsk = (const float*)d_in[20]; const float* bdsk = (const float*)d_in[21];
    const float* Wdsv = (const float*)d_in[22]; const float* bdsv = (const float*)d_in[23];
    const float* gate = (const float*)d_in[24];
    float* out = (float*)d_out;

    static const int Lt[4]    = {4096, 1024, 256, 64};
    static const int qoff[4]  = {0, 2097152, 2621440, 2752512};
    static const int kvoff[4] = {0, 2113536, 2654208, 2801664};
    float* dsout = out + (out_size - 8);

    pooled_kernel<<<dim3(256, 2, 4), 256>>>(dd[0], dd[1], dd[2], dd[3], dsout);
    token_kernel<<<dim3(1024, 2, 8), 256>>>(Wdsk, bdsk, Wdsv, bdsv, gate);

    for (int lv = 0; lv < 4; lv++) {
        int L = Lt[lv], M = L + 32;
        dim3 grid(L / 64, 4, 2), blk(16, 16);
        gemm256<<<grid, blk>>>(Wq + lv * 65536, bq + lv * 256, sp[lv], nullptr, nullptr,
                               L, M, qoff[lv], 0, 0);
        gemm256<<<grid, blk>>>(Wk + lv * 65536, bk + lv * 256, iv[lv], nullptr, nullptr,
                               L, M, kvoff[lv], 0, 1);
        gemm256<<<grid, blk>>>(Wv + lv * 65536, bv + lv * 256, iv[lv], nullptr, nullptr,
                               L, M, kvoff[lv], 0, 2);
        attn_mma<<<dim3(L / 64, HEADS, 2), 128>>>(qoff[lv], kvoff[lv], L, M,
                                                  dsout, 1.0f / (64.0f * (float)L), lv);
    }
    for (int lv = 0; lv < 4; lv++) {
        int L = Lt[lv], M = L + 32;
        dim3 grid(L / 64, 4, 2), blk(16, 16);
        gemm256<<<grid, blk>>>(Wo + lv * 65536, bo + lv * 256, nullptr, sp[lv], out,
                               L, M, qoff[lv], qoff[lv], 3);
    }
}

// round 9
// speedup vs baseline: 1.5886x; 1.3854x over previous
#include <cuda_runtime.h>
#include <cuda_bf16.h>

#define CC    256
#define HEADS 64
#define HD    4
#define TT    32

typedef unsigned long long u64;
typedef unsigned int u32;

__device__ __align__(16) float g_q[2785280];      // (N,C,L) per level
__device__ __align__(16) float g_k[2850816];      // (n,h,m,4) per level
__device__ __align__(16) float g_v[2850816];
__device__ __align__(16) float g_attn[2785280];
__device__ float g_pooled[4 * 2 * CC];

__constant__ int c_L[4]     = {4096, 1024, 256, 64};
__constant__ int c_kvoff[4] = {0, 2113536, 2654208, 2801664};

__device__ __forceinline__ float ex2f(float x) {
    float r; asm("ex2.approx.f32 %0,%1;" : "=f"(r) : "f"(x)); return r;
}
__device__ __forceinline__ u32 pkbf(float lo, float hi) {   // low half = lo, high half = hi
    u32 r; asm("cvt.rn.bf16x2.f32 %0, %1, %2;" : "=r"(r) : "f"(hi), "f"(lo)); return r;
}
__device__ __forceinline__ u32 smem_u32(const void* p) {
    u32 a; asm("{.reg .u64 t; cvta.to.shared.u64 t, %1; cvt.u32.u64 %0, t;}" : "=r"(a) : "l"(p));
    return a;
}

// ---------------- pooled mean (also zeroes ds output) ----------------
__global__ void pooled_kernel(const float* __restrict__ d0, const float* __restrict__ d1,
                              const float* __restrict__ d2, const float* __restrict__ d3,
                              float* __restrict__ dsout) {
    __shared__ float red[256];
    int lvl = blockIdx.z, n = blockIdx.y, c = blockIdx.x;
    if (lvl == 0 && n == 0 && c == 0 && threadIdx.x < 8) dsout[threadIdx.x] = 0.f;
    const float* dp = (lvl == 0) ? d0 : (lvl == 1) ? d1 : (lvl == 2) ? d2 : d3;
    int L = c_L[lvl];
    const float* p = dp + (size_t)(n * CC + c) * L;
    float s = 0.f;
    for (int i = threadIdx.x; i < L; i += blockDim.x) s += p[i];
    red[threadIdx.x] = s;
    __syncthreads();
    for (int st = blockDim.x >> 1; st > 0; st >>= 1) {
        if (threadIdx.x < st) red[threadIdx.x] += red[threadIdx.x + st];
        __syncthreads();
    }
    if (threadIdx.x == 0) g_pooled[(lvl * 2 + n) * CC + c] = red[0] / (float)L;
}

// ---------------- ds token projections -> tail of k/v ----------------
__global__ void token_kernel(const float* __restrict__ Wdsk, const float* __restrict__ bdsk,
                             const float* __restrict__ Wdsv, const float* __restrict__ bdsv,
                             const float* __restrict__ gate) {
    int kind = blockIdx.y;
    int lvl = blockIdx.z >> 1, n = blockIdx.z & 1;
    int warp = threadIdx.x >> 5, lane = threadIdx.x & 31;
    int j = blockIdx.x * 8 + warp;
    const float* Wr = (kind ? Wdsv : Wdsk) + (size_t)(lvl * 8192 + j) * 256;
    const float* pl = g_pooled + (lvl * 2 + n) * CC;
    float s = 0.f;
#pragma unroll
    for (int c = lane; c < 256; c += 32) s += Wr[c] * pl[c];
#pragma unroll
    for (int off = 16; off > 0; off >>= 1) s += __shfl_down_sync(0xffffffffu, s, off);
    if (lane == 0) {
        s += (kind ? bdsv : bdsk)[lvl * 8192 + j];
        if (kind) s *= 1.0f / (1.0f + __expf(-gate[lvl]));
        int h = j >> 7, d = (j >> 5) & 3, t = j & 31;
        int L = c_L[lvl], M = L + TT;
        size_t idx = (size_t)c_kvoff[lvl] + ((size_t)((n * HEADS + h) * M) + (L + t)) * HD + d;
        if (kind) g_v[idx] = s; else g_k[idx] = s;
    }
}

// ---------------- 256-K GEMM ----------------
__global__ void gemm256(const float* __restrict__ W, const float* __restrict__ bias,
                        const float* __restrict__ Xext, const float* __restrict__ res,
                        float* __restrict__ dext,
                        int L, int M, int off, int xoff, int outsel) {
    __shared__ float As[16][68];
    __shared__ float Bs[16][68];
    int n = blockIdx.z;
    int o0 = blockIdx.y * 64, l0 = blockIdx.x * 64;
    const float* X = (outsel == 3) ? (g_attn + xoff + (size_t)n * CC * L)
                                   : (Xext + (size_t)n * CC * L);
    int tx = threadIdx.x, ty = threadIdx.y;
    int t = ty * 16 + tx;
    float acc[4][4];
#pragma unroll
    for (int i = 0; i < 4; i++)
#pragma unroll
        for (int j = 0; j < 4; j++) acc[i][j] = 0.f;
    for (int k0 = 0; k0 < 256; k0 += 16) {
#pragma unroll
        for (int r = 0; r < 4; r++) {
            int idx = t + r * 256;
            As[idx & 15][idx >> 4] = W[(size_t)(o0 + (idx >> 4)) * 256 + k0 + (idx & 15)];
        }
#pragma unroll
        for (int r = 0; r < 4; r++) {
            int idx = t + r * 256;
            Bs[idx >> 6][idx & 63] = X[(size_t)(k0 + (idx >> 6)) * L + l0 + (idx & 63)];
        }
        __syncthreads();
#pragma unroll
        for (int kk = 0; kk < 16; kk++) {
            float a0 = As[kk][ty * 4], a1 = As[kk][ty * 4 + 1];
            float a2 = As[kk][ty * 4 + 2], a3 = As[kk][ty * 4 + 3];
            float b0 = Bs[kk][tx * 4], b1 = Bs[kk][tx * 4 + 1];
            float b2 = Bs[kk][tx * 4 + 2], b3 = Bs[kk][tx * 4 + 3];
            acc[0][0] += a0 * b0; acc[0][1] += a0 * b1; acc[0][2] += a0 * b2; acc[0][3] += a0 * b3;
            acc[1][0] += a1 * b0; acc[1][1] += a1 * b1; acc[1][2] += a1 * b2; acc[1][3] += a1 * b3;
            acc[2][0] += a2 * b0; acc[2][1] += a2 * b1; acc[2][2] += a2 * b2; acc[2][3] += a2 * b3;
            acc[3][0] += a3 * b0; acc[3][1] += a3 * b1; acc[3][2] += a3 * b2; acc[3][3] += a3 * b3;
        }
        __syncthreads();
    }
#pragma unroll
    for (int i = 0; i < 4; i++) {
        int o = o0 + ty * 4 + i;
        float bv = bias[o];
#pragma unroll
        for (int j = 0; j < 4; j++) {
            int l = l0 + tx * 4 + j;
            float v = acc[i][j] + bv;
            if (outsel == 0)
                g_q[off + (size_t)(n * CC + o) * L + l] = v;
            else if (outsel == 1)
                g_k[off + ((size_t)((n * HEADS + (o >> 2)) * M) + l) * HD + (o & 3)] = v;
            else if (outsel == 2)
                g_v[off + ((size_t)((n * HEADS + (o >> 2)) * M) + l) * HD + (o & 3)] = v;
            else
                dext[off + (size_t)(n * CC + o) * L + l] = v + res[(size_t)(n * CC + o) * L + l];
        }
    }
}

// ---------------- HMMA attention: CTA = (n, h, 64-query tile), 4 warps x 16 queries ---
// S-mma m16n8k16 (compensated bf16 split of Q,K -> ~fp32 logits).
// Single O-mma m16n8k8, bf16 weights and values. den computed from the SAME
// bf16-rounded weights via a ones column -> consistent normalization; precision
// component ~4e-5 global (measured round 6/7 differencing). V cols =
// [v0..v3, 1, ds-indicator, 0, 0]; OOB key rows are all-zero (self-masking).
__global__ void __launch_bounds__(128) attn_mma(int qoff, int kvoff, int L, int M,
                                                float* __restrict__ dsout,
                                                float inv_hl, int lvl) {
    __shared__ __align__(16) uint4 s_k[128];   // per key: [khi01, klo01, khi23, klo23]
    __shared__ __align__(16) uint4 s_v[128];   // per pair: [c01,c11,c21,c31],[den,ds,0,0]
    __shared__ float s_red[4];

    int tid = threadIdx.x, wid = tid >> 5, lane = tid & 31;
    int g = lane >> 2, tg = lane & 3;
    int n = blockIdx.z, h = blockIdx.y;
    int qlo = blockIdx.x * 64 + wid * 16 + g;      // rows g and g+8 of this warp's tile
    int qhi = qlo + 8;

    const float SCALE = 0.5f * 1.4426950408889634f;
    size_t qbase = (size_t)qoff + ((size_t)(n * CC) + h * HD) * L;

    // Build S-mma A fragment (register-resident, reused every block)
    u32 a0, a1, a2, a3;
    {
        float hlo[4], llo[4], hhi[4], lhi[4];
#pragma unroll
        for (int d = 0; d < 4; d++) {
            float v = g_q[qbase + (size_t)d * L + qlo] * SCALE;
            float hf = __bfloat162float(__float2bfloat16(v));
            hlo[d] = hf; llo[d] = v - hf;
            v = g_q[qbase + (size_t)d * L + qhi] * SCALE;
            hf = __bfloat162float(__float2bfloat16(v));
            hhi[d] = hf; lhi[d] = v - hf;
        }
        a0 = (tg == 0) ? pkbf(hlo[0], hlo[1]) : (tg == 1) ? pkbf(hlo[2], hlo[3])
           : (tg == 2) ? pkbf(llo[0], llo[1]) : pkbf(llo[2], llo[3]);
        a1 = (tg == 0) ? pkbf(hhi[0], hhi[1]) : (tg == 1) ? pkbf(hhi[2], hhi[3])
           : (tg == 2) ? pkbf(lhi[0], lhi[1]) : pkbf(lhi[2], lhi[3]);
        a2 = (tg < 2) ? a0 : 0u;
        a3 = (tg < 2) ? a1 : 0u;
    }

    const float4* kp = (const float4*)g_k + (kvoff >> 2) + (size_t)(n * HEADS + h) * M;
    const float4* vp = (const float4*)g_v + (kvoff >> 2) + (size_t)(n * HEADS + h) * M;

    float o0 = 0.f, o1 = 0.f, o2 = 0.f, o3 = 0.f;
    u32 skb = smem_u32(s_k), svb = smem_u32(s_v);

    for (int base = 0; base < M; base += 128) {
        // ---- stage 128 keys + values ----
        {
            int m = base + tid;
            float4 kk = (m < M) ? kp[m] : make_float4(0.f, 0.f, 0.f, 0.f);
            float k0h = __bfloat162float(__float2bfloat16(kk.x));
            float k1h = __bfloat162float(__float2bfloat16(kk.y));
            float k2h = __bfloat162float(__float2bfloat16(kk.z));
            float k3h = __bfloat162float(__float2bfloat16(kk.w));
            s_k[tid] = make_uint4(pkbf(k0h, k1h), pkbf(kk.x - k0h, kk.y - k1h),
                                  pkbf(k2h, k3h), pkbf(kk.z - k2h, kk.w - k3h));
            if (tid < 64) {
                int m0 = base + 2 * tid, m1 = m0 + 1;
                float4 v0 = (m0 < M) ? vp[m0] : make_float4(0.f, 0.f, 0.f, 0.f);
                float4 v1 = (m1 < M) ? vp[m1] : make_float4(0.f, 0.f, 0.f, 0.f);
                float one0 = (m0 < M) ? 1.f : 0.f, one1 = (m1 < M) ? 1.f : 0.f;
                float dsi0 = (m0 >= L && m0 < M) ? 1.f : 0.f;
                float dsi1 = (m1 >= L && m1 < M) ? 1.f : 0.f;
                s_v[2 * tid]     = make_uint4(pkbf(v0.x, v1.x), pkbf(v0.y, v1.y),
                                              pkbf(v0.z, v1.z), pkbf(v0.w, v1.w));
                s_v[2 * tid + 1] = make_uint4(pkbf(one0, one1), pkbf(dsi0, dsi1), 0u, 0u);
            }
        }
        __syncthreads();
        // ---- 16 blocks of 8 keys ----
#pragma unroll
        for (int blk = 0; blk < 16; blk++) {
            u32 b0, b1;
            u32 addr = skb + ((u32)(blk * 8 + g) << 4) + ((u32)(tg & 1) << 3);
            asm("ld.shared.v2.u32 {%0,%1},[%2];" : "=r"(b0), "=r"(b1) : "r"(addr));
            b1 = (tg < 2) ? b1 : 0u;
            float c0, c1, c2, c3;
            asm("mma.sync.aligned.m16n8k16.row.col.f32.bf16.bf16.f32 "
                "{%0,%1,%2,%3},{%4,%5,%6,%7},{%8,%9},{%10,%11,%12,%13};"
                : "=f"(c0), "=f"(c1), "=f"(c2), "=f"(c3)
                : "r"(a0), "r"(a1), "r"(a2), "r"(a3), "r"(b0), "r"(b1),
                  "f"(0.f), "f"(0.f), "f"(0.f), "f"(0.f));
            u32 wa0 = pkbf(ex2f(c0), ex2f(c1));
            u32 wa1 = pkbf(ex2f(c2), ex2f(c3));
            u32 vb;
            u32 vaddr = svb + ((u32)((blk * 4 + tg) * 8 + g) << 2);
            asm("ld.shared.u32 %0,[%1];" : "=r"(vb) : "r"(vaddr));
            asm("mma.sync.aligned.m16n8k8.row.col.f32.bf16.bf16.f32 "
                "{%0,%1,%2,%3},{%4,%5},{%6},{%0,%1,%2,%3};"
                : "+f"(o0), "+f"(o1), "+f"(o2), "+f"(o3)
                : "r"(wa0), "r"(wa1), "r"(vb));
        }
        __syncthreads();
    }

    // ---- epilogue ----
    // Thread(tg) holds O cols 2tg,2tg+1 for rows g (o0,o1) and g+8 (o2,o3).
    // den (col 4) and ds (col 5) live on tg==2 threads.
    u32 full = 0xffffffffu;
    int src = (lane & 0x1c) | 2;
    float den_lo = __shfl_sync(full, o0, src);
    float den_hi = __shfl_sync(full, o2, src);
    if (tg < 2) {
        float rl = 1.0f / den_lo, rh = 1.0f / den_hi;
        int d0 = tg * 2, d1 = tg * 2 + 1;
        g_attn[qbase + (size_t)d0 * L + qlo] = o0 * rl;
        g_attn[qbase + (size_t)d1 * L + qlo] = o1 * rl;
        g_attn[qbase + (size_t)d0 * L + qhi] = o2 * rh;
        g_attn[qbase + (size_t)d1 * L + qhi] = o3 * rh;
    }
    float contrib = (tg == 2) ? (o1 / o0 + o3 / o2) : 0.f;
#pragma unroll
    for (int off = 16; off > 0; off >>= 1) contrib += __shfl_down_sync(full, contrib, off);
    if (lane == 0) s_red[wid] = contrib;
    __syncthreads();
    if (tid == 0)
        atomicAdd(&dsout[lvl * 2 + n], (s_red[0] + s_red[1] + s_red[2] + s_red[3]) * inv_hl);
}

// ---------------- launch ----------------
extern "C" void kernel_launch(void* const* d_in, const int* in_sizes, int n_in,
                              void* d_out, int out_size) {
    const float* sp[4]; const float* iv[4]; const float* dd[4];
    for (int i = 0; i < 4; i++) {
        sp[i] = (const float*)d_in[i];
        iv[i] = (const float*)d_in[4 + i];
        dd[i] = (const float*)d_in[8 + i];
    }
    const float* Wq  = (const float*)d_in[12]; const float* bq  = (const float*)d_in[13];
    const float* Wk  = (const float*)d_in[14]; const float* bk  = (const float*)d_in[15];
    const float* Wv  = (const float*)d_in[16]; const float* bv  = (const float*)d_in[17];
    const float* Wo  = (const float*)d_in[18]; const float* bo  = (const float*)d_in[19];
    const float* Wdsk = (const float*)d_in[20]; const float* bdsk = (const float*)d_in[21];
    const float* Wdsv = (const float*)d_in[22]; const float* bdsv = (const float*)d_in[23];
    const float* gate = (const float*)d_in[24];
    float* out = (float*)d_out;

    static const int Lt[4]    = {4096, 1024, 256, 64};
    static const int qoff[4]  = {0, 2097152, 2621440, 2752512};
    static const int kvoff[4] = {0, 2113536, 2654208, 2801664};
    float* dsout = out + (out_size - 8);

    pooled_kernel<<<dim3(256, 2, 4), 256>>>(dd[0], dd[1], dd[2], dd[3], dsout);
    token_kernel<<<dim3(1024, 2, 8), 256>>>(Wdsk, bdsk, Wdsv, bdsv, gate);

    for (int lv = 0; lv < 4; lv++) {
        int L = Lt[lv], M = L + 32;
        dim3 grid(L / 64, 4, 2), blk(16, 16);
        gemm256<<<grid, blk>>>(Wq + lv * 65536, bq + lv * 256, sp[lv], nullptr, nullptr,
                               L, M, qoff[lv], 0, 0);
        gemm256<<<grid, blk>>>(Wk + lv * 65536, bk + lv * 256, iv[lv], nullptr, nullptr,
                               L, M, kvoff[lv], 0, 1);
        gemm256<<<grid, blk>>>(Wv + lv * 65536, bv + lv * 256, iv[lv], nullptr, nullptr,
                               L, M, kvoff[lv], 0, 2);
        attn_mma<<<dim3(L / 64, HEADS, 2), 128>>>(qoff[lv], kvoff[lv], L, M,
                                                  dsout, 1.0f / (64.0f * (float)L), lv);
    }
    for (int lv = 0; lv < 4; lv++) {
        int L = Lt[lv], M = L + 32;
        dim3 grid(L / 64, 4, 2), blk(16, 16);
        gemm256<<<grid, blk>>>(Wo + lv * 65536, bo + lv * 256, nullptr, sp[lv], out,
                               L, M, qoff[lv], qoff[lv], 3);
    }
}

// round 10
// speedup vs baseline: 1.7633x; 1.1099x over previous
#include <cuda_runtime.h>
#include <cuda_bf16.h>

#define CC    256
#define HEADS 64
#define HD    4
#define TT    32

typedef unsigned long long u64;
typedef unsigned int u32;

__device__ __align__(16) float g_q[2785280];      // (N,C,L) per level
__device__ __align__(16) float g_k[2850816];      // (n,h,m,4) per level
__device__ __align__(16) float g_v[2850816];
__device__ __align__(16) float g_attn[2785280];
__device__ float g_pooled[4 * 2 * CC];

__constant__ int c_L[4]     = {4096, 1024, 256, 64};
__constant__ int c_kvoff[4] = {0, 2113536, 2654208, 2801664};

__device__ __forceinline__ float ex2f(float x) {
    float r; asm("ex2.approx.f32 %0,%1;" : "=f"(r) : "f"(x)); return r;
}
__device__ __forceinline__ u32 pkbf(float lo, float hi) {   // low half = lo, high half = hi
    u32 r; asm("cvt.rn.bf16x2.f32 %0, %1, %2;" : "=r"(r) : "f"(hi), "f"(lo)); return r;
}
__device__ __forceinline__ float tf32f(float x) {
    u32 r; asm("cvt.rna.tf32.f32 %0,%1;" : "=r"(r) : "f"(x));
    return __uint_as_float(r);
}
__device__ __forceinline__ u32 smem_u32(const void* p) {
    u32 a; asm("{.reg .u64 t; cvta.to.shared.u64 t, %1; cvt.u32.u64 %0, t;}" : "=r"(a) : "l"(p));
    return a;
}

// ---------------- pooled mean (also zeroes ds output) ----------------
__global__ void pooled_kernel(const float* __restrict__ d0, const float* __restrict__ d1,
                              const float* __restrict__ d2, const float* __restrict__ d3,
                              float* __restrict__ dsout) {
    __shared__ float red[256];
    int lvl = blockIdx.z, n = blockIdx.y, c = blockIdx.x;
    if (lvl == 0 && n == 0 && c == 0 && threadIdx.x < 8) dsout[threadIdx.x] = 0.f;
    const float* dp = (lvl == 0) ? d0 : (lvl == 1) ? d1 : (lvl == 2) ? d2 : d3;
    int L = c_L[lvl];
    const float* p = dp + (size_t)(n * CC + c) * L;
    float s = 0.f;
    for (int i = threadIdx.x; i < L; i += blockDim.x) s += p[i];
    red[threadIdx.x] = s;
    __syncthreads();
    for (int st = blockDim.x >> 1; st > 0; st >>= 1) {
        if (threadIdx.x < st) red[threadIdx.x] += red[threadIdx.x + st];
        __syncthreads();
    }
    if (threadIdx.x == 0) g_pooled[(lvl * 2 + n) * CC + c] = red[0] / (float)L;
}

// ---------------- ds token projections -> tail of k/v ----------------
__global__ void token_kernel(const float* __restrict__ Wdsk, const float* __restrict__ bdsk,
                             const float* __restrict__ Wdsv, const float* __restrict__ bdsv,
                             const float* __restrict__ gate) {
    int kind = blockIdx.y;
    int lvl = blockIdx.z >> 1, n = blockIdx.z & 1;
    int warp = threadIdx.x >> 5, lane = threadIdx.x & 31;
    int j = blockIdx.x * 8 + warp;
    const float* Wr = (kind ? Wdsv : Wdsk) + (size_t)(lvl * 8192 + j) * 256;
    const float* pl = g_pooled + (lvl * 2 + n) * CC;
    float s = 0.f;
#pragma unroll
    for (int c = lane; c < 256; c += 32) s += Wr[c] * pl[c];
#pragma unroll
    for (int off = 16; off > 0; off >>= 1) s += __shfl_down_sync(0xffffffffu, s, off);
    if (lane == 0) {
        s += (kind ? bdsv : bdsk)[lvl * 8192 + j];
        if (kind) s *= 1.0f / (1.0f + __expf(-gate[lvl]));
        int h = j >> 7, d = (j >> 5) & 3, t = j & 31;
        int L = c_L[lvl], M = L + TT;
        size_t idx = (size_t)c_kvoff[lvl] + ((size_t)((n * HEADS + h) * M) + (L + t)) * HD + d;
        if (kind) g_v[idx] = s; else g_k[idx] = s;
    }
}

// ---------------- tf32 tensor-core GEMM: OUT(256xL) = W(256x256) @ X(256xL) + b ------
// CTA = 64 O-rows x 64 L-cols, 128 threads (4 warps); warp w -> rows [w*16, w*16+16).
// K staged in 16-wide chunks, tf32-converted at staging. m16n8k8 HMMA.
__global__ void __launch_bounds__(128) gemm_tc(const float* __restrict__ W,
                                               const float* __restrict__ bias,
                                               const float* __restrict__ Xext,
                                               const float* __restrict__ res,
                                               float* __restrict__ dext,
                                               int L, int M, int off, int xoff, int outsel) {
    __shared__ float As[16][72];   // [k][o]   (72 pad: 8*tg+g -> conflict-free frags)
    __shared__ float Bs[16][72];   // [k][l]
    int n = blockIdx.z;
    int o0 = blockIdx.y * 64, l0 = blockIdx.x * 64;
    const float* X = (outsel == 3) ? (g_attn + xoff + (size_t)n * CC * L)
                                   : (Xext + (size_t)n * CC * L);
    int tid = threadIdx.x, wid = tid >> 5, lane = tid & 31;
    int g = lane >> 2, tg = lane & 3;

    float acc[8][4];
#pragma unroll
    for (int i = 0; i < 8; i++)
#pragma unroll
        for (int j = 0; j < 4; j++) acc[i][j] = 0.f;

    for (int k0 = 0; k0 < 256; k0 += 16) {
        // stage W tile 64(o) x 16(k), transposed into As[k][o]
#pragma unroll
        for (int r = 0; r < 2; r++) {
            int idx = tid + r * 128;
            int row = idx >> 2, kk = (idx & 3) << 2;
            float4 w4 = *(const float4*)&W[(size_t)(o0 + row) * 256 + k0 + kk];
            As[kk][row]     = tf32f(w4.x);
            As[kk + 1][row] = tf32f(w4.y);
            As[kk + 2][row] = tf32f(w4.z);
            As[kk + 3][row] = tf32f(w4.w);
        }
        // stage X tile 16(k) x 64(l)
#pragma unroll
        for (int r = 0; r < 2; r++) {
            int idx = tid + r * 128;
            int row = idx >> 4, cc = (idx & 15) << 2;
            float4 x4 = *(const float4*)&X[(size_t)(k0 + row) * L + l0 + cc];
            Bs[row][cc]     = tf32f(x4.x);
            Bs[row][cc + 1] = tf32f(x4.y);
            Bs[row][cc + 2] = tf32f(x4.z);
            Bs[row][cc + 3] = tf32f(x4.w);
        }
        __syncthreads();
#pragma unroll
        for (int ks = 0; ks < 2; ks++) {
            int kb = ks * 8;
            u32 a0 = __float_as_uint(As[kb + tg][wid * 16 + g]);
            u32 a1 = __float_as_uint(As[kb + tg][wid * 16 + g + 8]);
            u32 a2 = __float_as_uint(As[kb + tg + 4][wid * 16 + g]);
            u32 a3 = __float_as_uint(As[kb + tg + 4][wid * 16 + g + 8]);
#pragma unroll
            for (int nt = 0; nt < 8; nt++) {
                u32 b0 = __float_as_uint(Bs[kb + tg][nt * 8 + g]);
                u32 b1 = __float_as_uint(Bs[kb + tg + 4][nt * 8 + g]);
                asm("mma.sync.aligned.m16n8k8.row.col.f32.tf32.tf32.f32 "
                    "{%0,%1,%2,%3},{%4,%5,%6,%7},{%8,%9},{%0,%1,%2,%3};"
                    : "+f"(acc[nt][0]), "+f"(acc[nt][1]), "+f"(acc[nt][2]), "+f"(acc[nt][3])
                    : "r"(a0), "r"(a1), "r"(a2), "r"(a3), "r"(b0), "r"(b1));
            }
        }
        __syncthreads();
    }

    // ---- epilogue: thread holds rows r0=o0+wid*16+g, r1=r0+8; cols 2tg,2tg+1 per nt
    int r0 = o0 + wid * 16 + g, r1 = r0 + 8;
    float b0v = bias[r0], b1v = bias[r1];
#pragma unroll
    for (int nt = 0; nt < 8; nt++) {
        int l = l0 + nt * 8 + 2 * tg;
        float v00 = acc[nt][0] + b0v, v01 = acc[nt][1] + b0v;
        float v10 = acc[nt][2] + b1v, v11 = acc[nt][3] + b1v;
        if (outsel == 0) {
            g_q[off + (size_t)(n * CC + r0) * L + l]     = v00;
            g_q[off + (size_t)(n * CC + r0) * L + l + 1] = v01;
            g_q[off + (size_t)(n * CC + r1) * L + l]     = v10;
            g_q[off + (size_t)(n * CC + r1) * L + l + 1] = v11;
        } else if (outsel == 1 || outsel == 2) {
            float* dst = (outsel == 1) ? g_k : g_v;
            size_t i00 = (size_t)off + ((size_t)((n * HEADS + (r0 >> 2)) * M) + l) * HD + (r0 & 3);
            size_t i10 = (size_t)off + ((size_t)((n * HEADS + (r1 >> 2)) * M) + l) * HD + (r1 & 3);
            dst[i00] = v00; dst[i00 + HD] = v01;
            dst[i10] = v10; dst[i10 + HD] = v11;
        } else {
            size_t b = (size_t)(n * CC + r0) * L + l;
            size_t c = (size_t)(n * CC + r1) * L + l;
            dext[off + b]     = v00 + res[b];
            dext[off + b + 1] = v01 + res[b + 1];
            dext[off + c]     = v10 + res[c];
            dext[off + c + 1] = v11 + res[c + 1];
        }
    }
}

// ---------------- HMMA attention: CTA = (n, h, 64-query tile), 4 warps x 16 queries ---
// S-mma m16n8k16 (compensated bf16 split of Q,K -> ~fp32 logits).
// Single O-mma m16n8k8, bf16 weights and values; den from ones column keeps
// normalization consistent. V cols = [v0..v3, 1, ds-indicator, 0, 0]; OOB rows zero.
__global__ void __launch_bounds__(128) attn_mma(int qoff, int kvoff, int L, int M,
                                                float* __restrict__ dsout,
                                                float inv_hl, int lvl) {
    __shared__ __align__(16) uint4 s_k[128];   // per key: [khi01, klo01, khi23, klo23]
    __shared__ __align__(16) uint4 s_v[128];   // per pair: [c01,c11,c21,c31],[den,ds,0,0]
    __shared__ float s_red[4];

    int tid = threadIdx.x, wid = tid >> 5, lane = tid & 31;
    int g = lane >> 2, tg = lane & 3;
    int n = blockIdx.z, h = blockIdx.y;
    int qlo = blockIdx.x * 64 + wid * 16 + g;      // rows g and g+8 of this warp's tile
    int qhi = qlo + 8;

    const float SCALE = 0.5f * 1.4426950408889634f;
    size_t qbase = (size_t)qoff + ((size_t)(n * CC) + h * HD) * L;

    // Build S-mma A fragment (register-resident, reused every block)
    u32 a0, a1, a2, a3;
    {
        float hlo[4], llo[4], hhi[4], lhi[4];
#pragma unroll
        for (int d = 0; d < 4; d++) {
            float v = g_q[qbase + (size_t)d * L + qlo] * SCALE;
            float hf = __bfloat162float(__float2bfloat16(v));
            hlo[d] = hf; llo[d] = v - hf;
            v = g_q[qbase + (size_t)d * L + qhi] * SCALE;
            hf = __bfloat162float(__float2bfloat16(v));
            hhi[d] = hf; lhi[d] = v - hf;
        }
        a0 = (tg == 0) ? pkbf(hlo[0], hlo[1]) : (tg == 1) ? pkbf(hlo[2], hlo[3])
           : (tg == 2) ? pkbf(llo[0], llo[1]) : pkbf(llo[2], llo[3]);
        a1 = (tg == 0) ? pkbf(hhi[0], hhi[1]) : (tg == 1) ? pkbf(hhi[2], hhi[3])
           : (tg == 2) ? pkbf(lhi[0], lhi[1]) : pkbf(lhi[2], lhi[3]);
        a2 = (tg < 2) ? a0 : 0u;
        a3 = (tg < 2) ? a1 : 0u;
    }

    const float4* kp = (const float4*)g_k + (kvoff >> 2) + (size_t)(n * HEADS + h) * M;
    const float4* vp = (const float4*)g_v + (kvoff >> 2) + (size_t)(n * HEADS + h) * M;

    float o0 = 0.f, o1 = 0.f, o2 = 0.f, o3 = 0.f;
    u32 skb = smem_u32(s_k), svb = smem_u32(s_v);

    for (int base = 0; base < M; base += 128) {
        // ---- stage 128 keys + values ----
        {
            int m = base + tid;
            float4 kk = (m < M) ? kp[m] : make_float4(0.f, 0.f, 0.f, 0.f);
            float k0h = __bfloat162float(__float2bfloat16(kk.x));
            float k1h = __bfloat162float(__float2bfloat16(kk.y));
            float k2h = __bfloat162float(__float2bfloat16(kk.z));
            float k3h = __bfloat162float(__float2bfloat16(kk.w));
            s_k[tid] = make_uint4(pkbf(k0h, k1h), pkbf(kk.x - k0h, kk.y - k1h),
                                  pkbf(k2h, k3h), pkbf(kk.z - k2h, kk.w - k3h));
            if (tid < 64) {
                int m0 = base + 2 * tid, m1 = m0 + 1;
                float4 v0 = (m0 < M) ? vp[m0] : make_float4(0.f, 0.f, 0.f, 0.f);
                float4 v1 = (m1 < M) ? vp[m1] : make_float4(0.f, 0.f, 0.f, 0.f);
                float one0 = (m0 < M) ? 1.f : 0.f, one1 = (m1 < M) ? 1.f : 0.f;
                float dsi0 = (m0 >= L && m0 < M) ? 1.f : 0.f;
                float dsi1 = (m1 >= L && m1 < M) ? 1.f : 0.f;
                s_v[2 * tid]     = make_uint4(pkbf(v0.x, v1.x), pkbf(v0.y, v1.y),
                                              pkbf(v0.z, v1.z), pkbf(v0.w, v1.w));
                s_v[2 * tid + 1] = make_uint4(pkbf(one0, one1), pkbf(dsi0, dsi1), 0u, 0u);
            }
        }
        __syncthreads();
        // ---- 16 blocks of 8 keys ----
#pragma unroll
        for (int blk = 0; blk < 16; blk++) {
            u32 b0, b1;
            u32 addr = skb + ((u32)(blk * 8 + g) << 4) + ((u32)(tg & 1) << 3);
            asm("ld.shared.v2.u32 {%0,%1},[%2];" : "=r"(b0), "=r"(b1) : "r"(addr));
            b1 = (tg < 2) ? b1 : 0u;
            float c0, c1, c2, c3;
            asm("mma.sync.aligned.m16n8k16.row.col.f32.bf16.bf16.f32 "
                "{%0,%1,%2,%3},{%4,%5,%6,%7},{%8,%9},{%10,%11,%12,%13};"
                : "=f"(c0), "=f"(c1), "=f"(c2), "=f"(c3)
                : "r"(a0), "r"(a1), "r"(a2), "r"(a3), "r"(b0), "r"(b1),
                  "f"(0.f), "f"(0.f), "f"(0.f), "f"(0.f));
            u32 wa0 = pkbf(ex2f(c0), ex2f(c1));
            u32 wa1 = pkbf(ex2f(c2), ex2f(c3));
            u32 vb;
            u32 vaddr = svb + ((u32)((blk * 4 + tg) * 8 + g) << 2);
            asm("ld.shared.u32 %0,[%1];" : "=r"(vb) : "r"(vaddr));
            asm("mma.sync.aligned.m16n8k8.row.col.f32.bf16.bf16.f32 "
                "{%0,%1,%2,%3},{%4,%5},{%6},{%0,%1,%2,%3};"
                : "+f"(o0), "+f"(o1), "+f"(o2), "+f"(o3)
                : "r"(wa0), "r"(wa1), "r"(vb));
        }
        __syncthreads();
    }

    // ---- epilogue ----
    u32 full = 0xffffffffu;
    int src = (lane & 0x1c) | 2;
    float den_lo = __shfl_sync(full, o0, src);
    float den_hi = __shfl_sync(full, o2, src);
    if (tg < 2) {
        float rl = 1.0f / den_lo, rh = 1.0f / den_hi;
        int d0 = tg * 2, d1 = tg * 2 + 1;
        g_attn[qbase + (size_t)d0 * L + qlo] = o0 * rl;
        g_attn[qbase + (size_t)d1 * L + qlo] = o1 * rl;
        g_attn[qbase + (size_t)d0 * L + qhi] = o2 * rh;
        g_attn[qbase + (size_t)d1 * L + qhi] = o3 * rh;
    }
    float contrib = (tg == 2) ? (o1 / o0 + o3 / o2) : 0.f;
#pragma unroll
    for (int off = 16; off > 0; off >>= 1) contrib += __shfl_down_sync(full, contrib, off);
    if (lane == 0) s_red[wid] = contrib;
    __syncthreads();
    if (tid == 0)
        atomicAdd(&dsout[lvl * 2 + n], (s_red[0] + s_red[1] + s_red[2] + s_red[3]) * inv_hl);
}

// ---------------- launch ----------------
extern "C" void kernel_launch(void* const* d_in, const int* in_sizes, int n_in,
                              void* d_out, int out_size) {
    const float* sp[4]; const float* iv[4]; const float* dd[4];
    for (int i = 0; i < 4; i++) {
        sp[i] = (const float*)d_in[i];
        iv[i] = (const float*)d_in[4 + i];
        dd[i] = (const float*)d_in[8 + i];
    }
    const float* Wq  = (const float*)d_in[12]; const float* bq  = (const float*)d_in[13];
    const float* Wk  = (const float*)d_in[14]; const float* bk  = (const float*)d_in[15];
    const float* Wv  = (const float*)d_in[16]; const float* bv  = (const float*)d_in[17];
    const float* Wo  = (const float*)d_in[18]; const float* bo  = (const float*)d_in[19];
    const float* Wdsk = (const float*)d_in[20]; const float* bdsk = (const float*)d_in[21];
    const float* Wdsv = (const float*)d_in[22]; const float* bdsv = (const float*)d_in[23];
    const float* gate = (const float*)d_in[24];
    float* out = (float*)d_out;

    static const int Lt[4]    = {4096, 1024, 256, 64};
    static const int qoff[4]  = {0, 2097152, 2621440, 2752512};
    static const int kvoff[4] = {0, 2113536, 2654208, 2801664};
    float* dsout = out + (out_size - 8);

    pooled_kernel<<<dim3(256, 2, 4), 256>>>(dd[0], dd[1], dd[2], dd[3], dsout);
    token_kernel<<<dim3(1024, 2, 8), 256>>>(Wdsk, bdsk, Wdsv, bdsv, gate);

    for (int lv = 0; lv < 4; lv++) {
        int L = Lt[lv], M = L + 32;
        dim3 grid(L / 64, 4, 2);
        gemm_tc<<<grid, 128>>>(Wq + lv * 65536, bq + lv * 256, sp[lv], nullptr, nullptr,
                               L, M, qoff[lv], 0, 0);
        gemm_tc<<<grid, 128>>>(Wk + lv * 65536, bk + lv * 256, iv[lv], nullptr, nullptr,
                               L, M, kvoff[lv], 0, 1);
        gemm_tc<<<grid, 128>>>(Wv + lv * 65536, bv + lv * 256, iv[lv], nullptr, nullptr,
                               L, M, kvoff[lv], 0, 2);
        attn_mma<<<dim3(L / 64, HEADS, 2), 128>>>(qoff[lv], kvoff[lv], L, M,
                                                  dsout, 1.0f / (64.0f * (float)L), lv);
    }
    for (int lv = 0; lv < 4; lv++) {
        int L = Lt[lv], M = L + 32;
        dim3 grid(L / 64, 4, 2);
        gemm_tc<<<grid, 128>>>(Wo + lv * 65536, bo + lv * 256, nullptr, sp[lv], out,
                               L, M, qoff[lv], qoff[lv], 3);
    }
}

// round 11
// speedup vs baseline: 1.8034x; 1.0227x over previous
#include <cuda_runtime.h>
#include <cuda_bf16.h>

#define CC    256
#define HEADS 64
#define HD    4
#define TT    32

typedef unsigned long long u64;
typedef unsigned int u32;

__device__ __align__(16) float g_q[2785280];      // (N,C,L) per level
__device__ __align__(16) float g_k[2850816];      // (n,h,m,4) per level
__device__ __align__(16) float g_v[2850816];
__device__ __align__(16) float g_attn[2785280];
__device__ float g_pooled[4 * 2 * CC];

__constant__ int c_L[4]     = {4096, 1024, 256, 64};
__constant__ int c_kvoff[4] = {0, 2113536, 2654208, 2801664};

__device__ __forceinline__ float ex2f(float x) {
    float r; asm("ex2.approx.f32 %0,%1;" : "=f"(r) : "f"(x)); return r;
}
__device__ __forceinline__ u32 pkbf(float lo, float hi) {   // low half = lo, high half = hi
    u32 r; asm("cvt.rn.bf16x2.f32 %0, %1, %2;" : "=r"(r) : "f"(hi), "f"(lo)); return r;
}
__device__ __forceinline__ float tf32f(float x) {
    u32 r; asm("cvt.rna.tf32.f32 %0,%1;" : "=r"(r) : "f"(x));
    return __uint_as_float(r);
}
__device__ __forceinline__ u32 smem_u32(const void* p) {
    u32 a; asm("{.reg .u64 t; cvta.to.shared.u64 t, %1; cvt.u32.u64 %0, t;}" : "=r"(a) : "l"(p));
    return a;
}

// ---------------- pooled mean (also zeroes ds output) ----------------
__global__ void pooled_kernel(const float* __restrict__ d0, const float* __restrict__ d1,
                              const float* __restrict__ d2, const float* __restrict__ d3,
                              float* __restrict__ dsout) {
    __shared__ float red[256];
    int lvl = blockIdx.z, n = blockIdx.y, c = blockIdx.x;
    if (lvl == 0 && n == 0 && c == 0 && threadIdx.x < 8) dsout[threadIdx.x] = 0.f;
    const float* dp = (lvl == 0) ? d0 : (lvl == 1) ? d1 : (lvl == 2) ? d2 : d3;
    int L = c_L[lvl];
    const float* p = dp + (size_t)(n * CC + c) * L;
    float s = 0.f;
    for (int i = threadIdx.x; i < L; i += blockDim.x) s += p[i];
    red[threadIdx.x] = s;
    __syncthreads();
    for (int st = blockDim.x >> 1; st > 0; st >>= 1) {
        if (threadIdx.x < st) red[threadIdx.x] += red[threadIdx.x + st];
        __syncthreads();
    }
    if (threadIdx.x == 0) g_pooled[(lvl * 2 + n) * CC + c] = red[0] / (float)L;
}

// ---------------- ds token projections -> tail of k/v ----------------
__global__ void token_kernel(const float* __restrict__ Wdsk, const float* __restrict__ bdsk,
                             const float* __restrict__ Wdsv, const float* __restrict__ bdsv,
                             const float* __restrict__ gate) {
    int kind = blockIdx.y;
    int lvl = blockIdx.z >> 1, n = blockIdx.z & 1;
    int warp = threadIdx.x >> 5, lane = threadIdx.x & 31;
    int j = blockIdx.x * 8 + warp;
    const float* Wr = (kind ? Wdsv : Wdsk) + (size_t)(lvl * 8192 + j) * 256;
    const float* pl = g_pooled + (lvl * 2 + n) * CC;
    float s = 0.f;
#pragma unroll
    for (int c = lane; c < 256; c += 32) s += Wr[c] * pl[c];
#pragma unroll
    for (int off = 16; off > 0; off >>= 1) s += __shfl_down_sync(0xffffffffu, s, off);
    if (lane == 0) {
        s += (kind ? bdsv : bdsk)[lvl * 8192 + j];
        if (kind) s *= 1.0f / (1.0f + __expf(-gate[lvl]));
        int h = j >> 7, d = (j >> 5) & 3, t = j & 31;
        int L = c_L[lvl], M = L + TT;
        size_t idx = (size_t)c_kvoff[lvl] + ((size_t)((n * HEADS + h) * M) + (L + t)) * HD + d;
        if (kind) g_v[idx] = s; else g_k[idx] = s;
    }
}

// ---------------- tf32 tensor-core GEMM, double-buffered ----------------
// CTA = 64 O-rows x 64 L-cols, 128 threads; next k-chunk is register-prefetched
// during the MMA loop, staged into the alternate smem buffer, one sync per chunk.
__global__ void __launch_bounds__(128) gemm_tc(const float* __restrict__ W,
                                               const float* __restrict__ bias,
                                               const float* __restrict__ Xext,
                                               const float* __restrict__ res,
                                               float* __restrict__ dext,
                                               int L, int M, int off, int xoff, int outsel) {
    __shared__ float As[2][16][72];   // [buf][k][o]
    __shared__ float Bs[2][16][72];   // [buf][k][l]
    int n = blockIdx.z;
    int o0 = blockIdx.y * 64, l0 = blockIdx.x * 64;
    const float* X = (outsel == 3) ? (g_attn + xoff + (size_t)n * CC * L)
                                   : (Xext + (size_t)n * CC * L);
    int tid = threadIdx.x, wid = tid >> 5, lane = tid & 31;
    int g = lane >> 2, tg = lane & 3;

    // per-thread staging coordinates (fixed)
    int wrow[2], wk[2], xrow[2], xcc[2];
#pragma unroll
    for (int r = 0; r < 2; r++) {
        int idx = tid + r * 128;
        wrow[r] = idx >> 2;  wk[r]  = (idx & 3) << 2;
        xrow[r] = idx >> 4;  xcc[r] = (idx & 15) << 2;
    }

    float acc[8][4];
#pragma unroll
    for (int i = 0; i < 8; i++)
#pragma unroll
        for (int j = 0; j < 4; j++) acc[i][j] = 0.f;

    float4 wr[2], xr[2];
    // prologue: load + stage chunk 0
#pragma unroll
    for (int r = 0; r < 2; r++) {
        wr[r] = *(const float4*)&W[(size_t)(o0 + wrow[r]) * 256 + wk[r]];
        xr[r] = *(const float4*)&X[(size_t)xrow[r] * L + l0 + xcc[r]];
    }
#pragma unroll
    for (int r = 0; r < 2; r++) {
        As[0][wk[r]][wrow[r]]     = tf32f(wr[r].x);
        As[0][wk[r] + 1][wrow[r]] = tf32f(wr[r].y);
        As[0][wk[r] + 2][wrow[r]] = tf32f(wr[r].z);
        As[0][wk[r] + 3][wrow[r]] = tf32f(wr[r].w);
        Bs[0][xrow[r]][xcc[r]]     = tf32f(xr[r].x);
        Bs[0][xrow[r]][xcc[r] + 1] = tf32f(xr[r].y);
        Bs[0][xrow[r]][xcc[r] + 2] = tf32f(xr[r].z);
        Bs[0][xrow[r]][xcc[r] + 3] = tf32f(xr[r].w);
    }
    __syncthreads();

    int buf = 0;
    for (int k0 = 0; k0 < 256; k0 += 16) {
        bool pf = (k0 + 16 < 256);
        if (pf) {
#pragma unroll
            for (int r = 0; r < 2; r++) {
                wr[r] = *(const float4*)&W[(size_t)(o0 + wrow[r]) * 256 + k0 + 16 + wk[r]];
                xr[r] = *(const float4*)&X[(size_t)(k0 + 16 + xrow[r]) * L + l0 + xcc[r]];
            }
        }
#pragma unroll
        for (int ks = 0; ks < 2; ks++) {
            int kb = ks * 8;
            u32 a0 = __float_as_uint(As[buf][kb + tg][wid * 16 + g]);
            u32 a1 = __float_as_uint(As[buf][kb + tg][wid * 16 + g + 8]);
            u32 a2 = __float_as_uint(As[buf][kb + tg + 4][wid * 16 + g]);
            u32 a3 = __float_as_uint(As[buf][kb + tg + 4][wid * 16 + g + 8]);
#pragma unroll
            for (int nt = 0; nt < 8; nt++) {
                u32 b0 = __float_as_uint(Bs[buf][kb + tg][nt * 8 + g]);
                u32 b1 = __float_as_uint(Bs[buf][kb + tg + 4][nt * 8 + g]);
                asm("mma.sync.aligned.m16n8k8.row.col.f32.tf32.tf32.f32 "
                    "{%0,%1,%2,%3},{%4,%5,%6,%7},{%8,%9},{%0,%1,%2,%3};"
                    : "+f"(acc[nt][0]), "+f"(acc[nt][1]), "+f"(acc[nt][2]), "+f"(acc[nt][3])
                    : "r"(a0), "r"(a1), "r"(a2), "r"(a3), "r"(b0), "r"(b1));
            }
        }
        if (pf) {
            int nb = buf ^ 1;
#pragma unroll
            for (int r = 0; r < 2; r++) {
                As[nb][wk[r]][wrow[r]]     = tf32f(wr[r].x);
                As[nb][wk[r] + 1][wrow[r]] = tf32f(wr[r].y);
                As[nb][wk[r] + 2][wrow[r]] = tf32f(wr[r].z);
                As[nb][wk[r] + 3][wrow[r]] = tf32f(wr[r].w);
                Bs[nb][xrow[r]][xcc[r]]     = tf32f(xr[r].x);
                Bs[nb][xrow[r]][xcc[r] + 1] = tf32f(xr[r].y);
                Bs[nb][xrow[r]][xcc[r] + 2] = tf32f(xr[r].z);
                Bs[nb][xrow[r]][xcc[r] + 3] = tf32f(xr[r].w);
            }
            __syncthreads();
        }
        buf ^= 1;
    }

    // ---- epilogue ----
    int r0 = o0 + wid * 16 + g, r1 = r0 + 8;
    float b0v = bias[r0], b1v = bias[r1];
#pragma unroll
    for (int nt = 0; nt < 8; nt++) {
        int l = l0 + nt * 8 + 2 * tg;
        float v00 = acc[nt][0] + b0v, v01 = acc[nt][1] + b0v;
        float v10 = acc[nt][2] + b1v, v11 = acc[nt][3] + b1v;
        if (outsel == 0) {
            g_q[off + (size_t)(n * CC + r0) * L + l]     = v00;
            g_q[off + (size_t)(n * CC + r0) * L + l + 1] = v01;
            g_q[off + (size_t)(n * CC + r1) * L + l]     = v10;
            g_q[off + (size_t)(n * CC + r1) * L + l + 1] = v11;
        } else if (outsel == 1 || outsel == 2) {
            float* dst = (outsel == 1) ? g_k : g_v;
            size_t i00 = (size_t)off + ((size_t)((n * HEADS + (r0 >> 2)) * M) + l) * HD + (r0 & 3);
            size_t i10 = (size_t)off + ((size_t)((n * HEADS + (r1 >> 2)) * M) + l) * HD + (r1 & 3);
            dst[i00] = v00; dst[i00 + HD] = v01;
            dst[i10] = v10; dst[i10 + HD] = v11;
        } else {
            size_t b = (size_t)(n * CC + r0) * L + l;
            size_t c = (size_t)(n * CC + r1) * L + l;
            dext[off + b]     = v00 + res[b];
            dext[off + b + 1] = v01 + res[b + 1];
            dext[off + c]     = v10 + res[c];
            dext[off + c + 1] = v11 + res[c + 1];
        }
    }
}

// ---------------- HMMA attention, double-buffered KV staging ----------------
// CTA = (n, h, 64-query tile), 4 warps x 16 queries. Compensated-S bf16 HMMA,
// single bf16 O-mma with [v, 1, ds, 0, 0] columns. Next 128-key chunk is
// register-prefetched during the block loop; one sync per chunk.
__global__ void __launch_bounds__(128) attn_mma(int qoff, int kvoff, int L, int M,
                                                float* __restrict__ dsout,
                                                float inv_hl, int lvl) {
    __shared__ __align__(16) uint4 s_k[2][128];
    __shared__ __align__(16) uint4 s_v[2][128];
    __shared__ float s_red[4];

    int tid = threadIdx.x, wid = tid >> 5, lane = tid & 31;
    int g = lane >> 2, tg = lane & 3;
    int n = blockIdx.z, h = blockIdx.y;
    int qlo = blockIdx.x * 64 + wid * 16 + g;
    int qhi = qlo + 8;

    const float SCALE = 0.5f * 1.4426950408889634f;
    size_t qbase = (size_t)qoff + ((size_t)(n * CC) + h * HD) * L;

    u32 a0, a1, a2, a3;
    {
        float hlo[4], llo[4], hhi[4], lhi[4];
#pragma unroll
        for (int d = 0; d < 4; d++) {
            float v = g_q[qbase + (size_t)d * L + qlo] * SCALE;
            float hf = __bfloat162float(__float2bfloat16(v));
            hlo[d] = hf; llo[d] = v - hf;
            v = g_q[qbase + (size_t)d * L + qhi] * SCALE;
            hf = __bfloat162float(__float2bfloat16(v));
            hhi[d] = hf; lhi[d] = v - hf;
        }
        a0 = (tg == 0) ? pkbf(hlo[0], hlo[1]) : (tg == 1) ? pkbf(hlo[2], hlo[3])
           : (tg == 2) ? pkbf(llo[0], llo[1]) : pkbf(llo[2], llo[3]);
        a1 = (tg == 0) ? pkbf(hhi[0], hhi[1]) : (tg == 1) ? pkbf(hhi[2], hhi[3])
           : (tg == 2) ? pkbf(lhi[0], lhi[1]) : pkbf(lhi[2], lhi[3]);
        a2 = (tg < 2) ? a0 : 0u;
        a3 = (tg < 2) ? a1 : 0u;
    }

    const float4* kp = (const float4*)g_k + (kvoff >> 2) + (size_t)(n * HEADS + h) * M;
    const float4* vp = (const float4*)g_v + (kvoff >> 2) + (size_t)(n * HEADS + h) * M;

    float o0 = 0.f, o1 = 0.f, o2 = 0.f, o3 = 0.f;
    u32 skb0 = smem_u32(s_k), svb0 = smem_u32(s_v);
    int nch = (M + 127) >> 7;
    const float4 FZ = make_float4(0.f, 0.f, 0.f, 0.f);

    // prologue: stage chunk 0 into buffer 0
    {
        float4 kk = (tid < M) ? kp[tid] : FZ;
        float k0h = __bfloat162float(__float2bfloat16(kk.x));
        float k1h = __bfloat162float(__float2bfloat16(kk.y));
        float k2h = __bfloat162float(__float2bfloat16(kk.z));
        float k3h = __bfloat162float(__float2bfloat16(kk.w));
        s_k[0][tid] = make_uint4(pkbf(k0h, k1h), pkbf(kk.x - k0h, kk.y - k1h),
                                 pkbf(k2h, k3h), pkbf(kk.z - k2h, kk.w - k3h));
        if (tid < 64) {
            int m0 = 2 * tid, m1 = m0 + 1;
            float4 v0 = (m0 < M) ? vp[m0] : FZ;
            float4 v1 = (m1 < M) ? vp[m1] : FZ;
            float one0 = (m0 < M) ? 1.f : 0.f, one1 = (m1 < M) ? 1.f : 0.f;
            float dsi0 = (m0 >= L && m0 < M) ? 1.f : 0.f;
            float dsi1 = (m1 >= L && m1 < M) ? 1.f : 0.f;
            s_v[0][2 * tid]     = make_uint4(pkbf(v0.x, v1.x), pkbf(v0.y, v1.y),
                                             pkbf(v0.z, v1.z), pkbf(v0.w, v1.w));
            s_v[0][2 * tid + 1] = make_uint4(pkbf(one0, one1), pkbf(dsi0, dsi1), 0u, 0u);
        }
    }
    __syncthreads();

    int buf = 0;
    for (int t = 0; t < nch; t++) {
        int base = t * 128;
        bool pf = (t + 1 < nch);
        float4 kk = FZ, v0 = FZ, v1 = FZ;
        int nb_base = base + 128;
        if (pf) {
            int m = nb_base + tid;
            if (m < M) kk = kp[m];
            if (tid < 64) {
                int m0 = nb_base + 2 * tid;
                if (m0 < M)     v0 = vp[m0];
                if (m0 + 1 < M) v1 = vp[m0 + 1];
            }
        }

        u32 skb = skb0 + (u32)buf * 2048;
        u32 svb = svb0 + (u32)buf * 2048;
#pragma unroll
        for (int blk = 0; blk < 16; blk++) {
            u32 b0, b1;
            u32 addr = skb + ((u32)(blk * 8 + g) << 4) + ((u32)(tg & 1) << 3);
            asm("ld.shared.v2.u32 {%0,%1},[%2];" : "=r"(b0), "=r"(b1) : "r"(addr));
            b1 = (tg < 2) ? b1 : 0u;
            float c0, c1, c2, c3;
            asm("mma.sync.aligned.m16n8k16.row.col.f32.bf16.bf16.f32 "
                "{%0,%1,%2,%3},{%4,%5,%6,%7},{%8,%9},{%10,%11,%12,%13};"
                : "=f"(c0), "=f"(c1), "=f"(c2), "=f"(c3)
                : "r"(a0), "r"(a1), "r"(a2), "r"(a3), "r"(b0), "r"(b1),
                  "f"(0.f), "f"(0.f), "f"(0.f), "f"(0.f));
            u32 wa0 = pkbf(ex2f(c0), ex2f(c1));
            u32 wa1 = pkbf(ex2f(c2), ex2f(c3));
            u32 vb;
            u32 vaddr = svb + ((u32)((blk * 4 + tg) * 8 + g) << 2);
            asm("ld.shared.u32 %0,[%1];" : "=r"(vb) : "r"(vaddr));
            asm("mma.sync.aligned.m16n8k8.row.col.f32.bf16.bf16.f32 "
                "{%0,%1,%2,%3},{%4,%5},{%6},{%0,%1,%2,%3};"
                : "+f"(o0), "+f"(o1), "+f"(o2), "+f"(o3)
                : "r"(wa0), "r"(wa1), "r"(vb));
        }

        if (pf) {
            int nb = buf ^ 1;
            float k0h = __bfloat162float(__float2bfloat16(kk.x));
            float k1h = __bfloat162float(__float2bfloat16(kk.y));
            float k2h = __bfloat162float(__float2bfloat16(kk.z));
            float k3h = __bfloat162float(__float2bfloat16(kk.w));
            s_k[nb][tid] = make_uint4(pkbf(k0h, k1h), pkbf(kk.x - k0h, kk.y - k1h),
                                      pkbf(k2h, k3h), pkbf(kk.z - k2h, kk.w - k3h));
            if (tid < 64) {
                int m0 = nb_base + 2 * tid, m1 = m0 + 1;
                float one0 = (m0 < M) ? 1.f : 0.f, one1 = (m1 < M) ? 1.f : 0.f;
                float dsi0 = (m0 >= L && m0 < M) ? 1.f : 0.f;
                float dsi1 = (m1 >= L && m1 < M) ? 1.f : 0.f;
                s_v[nb][2 * tid]     = make_uint4(pkbf(v0.x, v1.x), pkbf(v0.y, v1.y),
                                                  pkbf(v0.z, v1.z), pkbf(v0.w, v1.w));
                s_v[nb][2 * tid + 1] = make_uint4(pkbf(one0, one1), pkbf(dsi0, dsi1), 0u, 0u);
            }
            __syncthreads();
        }
        buf ^= 1;
    }

    // ---- epilogue ----
    u32 full = 0xffffffffu;
    int src = (lane & 0x1c) | 2;
    float den_lo = __shfl_sync(full, o0, src);
    float den_hi = __shfl_sync(full, o2, src);
    if (tg < 2) {
        float rl = 1.0f / den_lo, rh = 1.0f / den_hi;
        int d0 = tg * 2, d1 = tg * 2 + 1;
        g_attn[qbase + (size_t)d0 * L + qlo] = o0 * rl;
        g_attn[qbase + (size_t)d1 * L + qlo] = o1 * rl;
        g_attn[qbase + (size_t)d0 * L + qhi] = o2 * rh;
        g_attn[qbase + (size_t)d1 * L + qhi] = o3 * rh;
    }
    float contrib = (tg == 2) ? (o1 / o0 + o3 / o2) : 0.f;
#pragma unroll
    for (int off = 16; off > 0; off >>= 1) contrib += __shfl_down_sync(full, contrib, off);
    if (lane == 0) s_red[wid] = contrib;
    __syncthreads();
    if (tid == 0)
        atomicAdd(&dsout[lvl * 2 + n], (s_red[0] + s_red[1] + s_red[2] + s_red[3]) * inv_hl);
}

// ---------------- launch ----------------
extern "C" void kernel_launch(void* const* d_in, const int* in_sizes, int n_in,
                              void* d_out, int out_size) {
    const float* sp[4]; const float* iv[4]; const float* dd[4];
    for (int i = 0; i < 4; i++) {
        sp[i] = (const float*)d_in[i];
        iv[i] = (const float*)d_in[4 + i];
        dd[i] = (const float*)d_in[8 + i];
    }
    const float* Wq  = (const float*)d_in[12]; const float* bq  = (const float*)d_in[13];
    const float* Wk  = (const float*)d_in[14]; const float* bk  = (const float*)d_in[15];
    const float* Wv  = (const float*)d_in[16]; const float* bv  = (const float*)d_in[17];
    const float* Wo  = (const float*)d_in[18]; const float* bo  = (const float*)d_in[19];
    const float* Wdsk = (const float*)d_in[20]; const float* bdsk = (const float*)d_in[21];
    const float* Wdsv = (const float*)d_in[22]; const float* bdsv = (const float*)d_in[23];
    const float* gate = (const float*)d_in[24];
    float* out = (float*)d_out;

    static const int Lt[4]    = {4096, 1024, 256, 64};
    static const int qoff[4]  = {0, 2097152, 2621440, 2752512};
    static const int kvoff[4] = {0, 2113536, 2654208, 2801664};
    float* dsout = out + (out_size - 8);

    pooled_kernel<<<dim3(256, 2, 4), 256>>>(dd[0], dd[1], dd[2], dd[3], dsout);
    token_kernel<<<dim3(1024, 2, 8), 256>>>(Wdsk, bdsk, Wdsv, bdsv, gate);

    for (int lv = 0; lv < 4; lv++) {
        int L = Lt[lv], M = L + 32;
        dim3 grid(L / 64, 4, 2);
        gemm_tc<<<grid, 128>>>(Wq + lv * 65536, bq + lv * 256, sp[lv], nullptr, nullptr,
                               L, M, qoff[lv], 0, 0);
        gemm_tc<<<grid, 128>>>(Wk + lv * 65536, bk + lv * 256, iv[lv], nullptr, nullptr,
                               L, M, kvoff[lv], 0, 1);
        gemm_tc<<<grid, 128>>>(Wv + lv * 65536, bv + lv * 256, iv[lv], nullptr, nullptr,
                               L, M, kvoff[lv], 0, 2);
        attn_mma<<<dim3(L / 64, HEADS, 2), 128>>>(qoff[lv], kvoff[lv], L, M,
                                                  dsout, 1.0f / (64.0f * (float)L), lv);
    }
    for (int lv = 0; lv < 4; lv++) {
        int L = Lt[lv], M = L + 32;
        dim3 grid(L / 64, 4, 2);
        gemm_tc<<<grid, 128>>>(Wo + lv * 65536, bo + lv * 256, nullptr, sp[lv], out,
                               L, M, qoff[lv], qoff[lv], 3);
    }
}

// round 12
// speedup vs baseline: 2.6446x; 1.4665x over previous
#include <cuda_runtime.h>
#include <cuda_bf16.h>

#define CC    256
#define HEADS 64
#define HD    4
#define TT    32

typedef unsigned long long u64;
typedef unsigned int u32;

__device__ __align__(16) float g_q[2785280];      // (N,C,L) per level
__device__ __align__(16) float g_k[2850816];      // (n,h,m,4) per level
__device__ __align__(16) float g_v[2850816];
__device__ __align__(16) float g_attn[2785280];
__device__ float g_pooled[4 * 2 * CC];

__constant__ int c_L[4]     = {4096, 1024, 256, 64};
__constant__ int c_kvoff[4] = {0, 2113536, 2654208, 2801664};

__device__ __forceinline__ u32 pkbf(float lo, float hi) {   // bf16x2 {lo,hi}
    u32 r; asm("cvt.rn.bf16x2.f32 %0, %1, %2;" : "=r"(r) : "f"(hi), "f"(lo)); return r;
}
__device__ __forceinline__ u32 pkhf(float lo, float hi) {   // f16x2 {lo,hi}
    u32 r; asm("cvt.rn.f16x2.f32 %0, %1, %2;" : "=r"(r) : "f"(hi), "f"(lo)); return r;
}
__device__ __forceinline__ float tf32f(float x) {
    u32 r; asm("cvt.rna.tf32.f32 %0,%1;" : "=r"(r) : "f"(x));
    return __uint_as_float(r);
}
__device__ __forceinline__ u32 smem_u32(const void* p) {
    u32 a; asm("{.reg .u64 t; cvta.to.shared.u64 t, %1; cvt.u32.u64 %0, t;}" : "=r"(a) : "l"(p));
    return a;
}

// ---------------- pooled mean (also zeroes ds output) ----------------
__global__ void pooled_kernel(const float* __restrict__ d0, const float* __restrict__ d1,
                              const float* __restrict__ d2, const float* __restrict__ d3,
                              float* __restrict__ dsout) {
    __shared__ float red[256];
    int lvl = blockIdx.z, n = blockIdx.y, c = blockIdx.x;
    if (lvl == 0 && n == 0 && c == 0 && threadIdx.x < 8) dsout[threadIdx.x] = 0.f;
    const float* dp = (lvl == 0) ? d0 : (lvl == 1) ? d1 : (lvl == 2) ? d2 : d3;
    int L = c_L[lvl];
    const float* p = dp + (size_t)(n * CC + c) * L;
    float s = 0.f;
    for (int i = threadIdx.x; i < L; i += blockDim.x) s += p[i];
    red[threadIdx.x] = s;
    __syncthreads();
    for (int st = blockDim.x >> 1; st > 0; st >>= 1) {
        if (threadIdx.x < st) red[threadIdx.x] += red[threadIdx.x + st];
        __syncthreads();
    }
    if (threadIdx.x == 0) g_pooled[(lvl * 2 + n) * CC + c] = red[0] / (float)L;
}

// ---------------- ds token projections -> tail of k/v ----------------
__global__ void token_kernel(const float* __restrict__ Wdsk, const float* __restrict__ bdsk,
                             const float* __restrict__ Wdsv, const float* __restrict__ bdsv,
                             const float* __restrict__ gate) {
    int kind = blockIdx.y;
    int lvl = blockIdx.z >> 1, n = blockIdx.z & 1;
    int warp = threadIdx.x >> 5, lane = threadIdx.x & 31;
    int j = blockIdx.x * 8 + warp;
    const float* Wr = (kind ? Wdsv : Wdsk) + (size_t)(lvl * 8192 + j) * 256;
    const float* pl = g_pooled + (lvl * 2 + n) * CC;
    float s = 0.f;
#pragma unroll
    for (int c = lane; c < 256; c += 32) s += Wr[c] * pl[c];
#pragma unroll
    for (int off = 16; off > 0; off >>= 1) s += __shfl_down_sync(0xffffffffu, s, off);
    if (lane == 0) {
        s += (kind ? bdsv : bdsk)[lvl * 8192 + j];
        if (kind) s *= 1.0f / (1.0f + __expf(-gate[lvl]));
        int h = j >> 7, d = (j >> 5) & 3, t = j & 31;
        int L = c_L[lvl], M = L + TT;
        size_t idx = (size_t)c_kvoff[lvl] + ((size_t)((n * HEADS + h) * M) + (L + t)) * HD + d;
        if (kind) g_v[idx] = s; else g_k[idx] = s;
    }
}

// ---------------- shared tf32 GEMM mainloop (double-buffered) ----------------
struct GemmCoords { int wrow[2], wk[2], xrow[2], xcc[2]; };

__device__ __forceinline__ void gemm_mainloop(const float* __restrict__ W,
                                              const float* __restrict__ X,
                                              int L, int o0, int l0,
                                              float (&As)[2][16][72], float (&Bs)[2][16][72],
                                              float (&acc)[8][4],
                                              int tid, int wid, int g, int tg) {
    GemmCoords cd;
#pragma unroll
    for (int r = 0; r < 2; r++) {
        int idx = tid + r * 128;
        cd.wrow[r] = idx >> 2;  cd.wk[r]  = (idx & 3) << 2;
        cd.xrow[r] = idx >> 4;  cd.xcc[r] = (idx & 15) << 2;
    }
    float4 wr[2], xr[2];
#pragma unroll
    for (int r = 0; r < 2; r++) {
        wr[r] = *(const float4*)&W[(size_t)(o0 + cd.wrow[r]) * 256 + cd.wk[r]];
        xr[r] = *(const float4*)&X[(size_t)cd.xrow[r] * L + l0 + cd.xcc[r]];
    }
#pragma unroll
    for (int r = 0; r < 2; r++) {
        As[0][cd.wk[r]][cd.wrow[r]]     = tf32f(wr[r].x);
        As[0][cd.wk[r] + 1][cd.wrow[r]] = tf32f(wr[r].y);
        As[0][cd.wk[r] + 2][cd.wrow[r]] = tf32f(wr[r].z);
        As[0][cd.wk[r] + 3][cd.wrow[r]] = tf32f(wr[r].w);
        Bs[0][cd.xrow[r]][cd.xcc[r]]     = tf32f(xr[r].x);
        Bs[0][cd.xrow[r]][cd.xcc[r] + 1] = tf32f(xr[r].y);
        Bs[0][cd.xrow[r]][cd.xcc[r] + 2] = tf32f(xr[r].z);
        Bs[0][cd.xrow[r]][cd.xcc[r] + 3] = tf32f(xr[r].w);
    }
    __syncthreads();

    int buf = 0;
    for (int k0 = 0; k0 < 256; k0 += 16) {
        bool pf = (k0 + 16 < 256);
        if (pf) {
#pragma unroll
            for (int r = 0; r < 2; r++) {
                wr[r] = *(const float4*)&W[(size_t)(o0 + cd.wrow[r]) * 256 + k0 + 16 + cd.wk[r]];
                xr[r] = *(const float4*)&X[(size_t)(k0 + 16 + cd.xrow[r]) * L + l0 + cd.xcc[r]];
            }
        }
#pragma unroll
        for (int ks = 0; ks < 2; ks++) {
            int kb = ks * 8;
            u32 a0 = __float_as_uint(As[buf][kb + tg][wid * 16 + g]);
            u32 a1 = __float_as_uint(As[buf][kb + tg][wid * 16 + g + 8]);
            u32 a2 = __float_as_uint(As[buf][kb + tg + 4][wid * 16 + g]);
            u32 a3 = __float_as_uint(As[buf][kb + tg + 4][wid * 16 + g + 8]);
#pragma unroll
            for (int nt = 0; nt < 8; nt++) {
                u32 b0 = __float_as_uint(Bs[buf][kb + tg][nt * 8 + g]);
                u32 b1 = __float_as_uint(Bs[buf][kb + tg + 4][nt * 8 + g]);
                asm("mma.sync.aligned.m16n8k8.row.col.f32.tf32.tf32.f32 "
                    "{%0,%1,%2,%3},{%4,%5,%6,%7},{%8,%9},{%0,%1,%2,%3};"
                    : "+f"(acc[nt][0]), "+f"(acc[nt][1]), "+f"(acc[nt][2]), "+f"(acc[nt][3])
                    : "r"(a0), "r"(a1), "r"(a2), "r"(a3), "r"(b0), "r"(b1));
            }
        }
        if (pf) {
            int nb = buf ^ 1;
#pragma unroll
            for (int r = 0; r < 2; r++) {
                As[nb][cd.wk[r]][cd.wrow[r]]     = tf32f(wr[r].x);
                As[nb][cd.wk[r] + 1][cd.wrow[r]] = tf32f(wr[r].y);
                As[nb][cd.wk[r] + 2][cd.wrow[r]] = tf32f(wr[r].z);
                As[nb][cd.wk[r] + 3][cd.wrow[r]] = tf32f(wr[r].w);
                Bs[nb][cd.xrow[r]][cd.xcc[r]]     = tf32f(xr[r].x);
                Bs[nb][cd.xrow[r]][cd.xcc[r] + 1] = tf32f(xr[r].y);
                Bs[nb][cd.xrow[r]][cd.xcc[r] + 2] = tf32f(xr[r].z);
                Bs[nb][cd.xrow[r]][cd.xcc[r] + 3] = tf32f(xr[r].w);
            }
            __syncthreads();
        }
        buf ^= 1;
    }
}

// ---------------- fused q/k/v GEMM: blockIdx.y = type*4 + row-tile ----------------
__global__ void __launch_bounds__(128) gemm_qkv(const float* __restrict__ Wq,
                                                const float* __restrict__ Wk,
                                                const float* __restrict__ Wv,
                                                const float* __restrict__ bq,
                                                const float* __restrict__ bk,
                                                const float* __restrict__ bv,
                                                const float* __restrict__ sp,
                                                const float* __restrict__ iv,
                                                int L, int M, int offq, int offkv) {
    __shared__ float As[2][16][72];
    __shared__ float Bs[2][16][72];
    int n = blockIdx.z;
    int type = blockIdx.y >> 2;
    int o0 = (blockIdx.y & 3) * 64, l0 = blockIdx.x * 64;
    const float* W = (type == 0) ? Wq : (type == 1) ? Wk : Wv;
    const float* bias = (type == 0) ? bq : (type == 1) ? bk : bv;
    const float* X = ((type == 0) ? sp : iv) + (size_t)n * CC * L;
    int tid = threadIdx.x, wid = tid >> 5, lane = tid & 31;
    int g = lane >> 2, tg = lane & 3;

    float acc[8][4];
#pragma unroll
    for (int i = 0; i < 8; i++)
#pragma unroll
        for (int j = 0; j < 4; j++) acc[i][j] = 0.f;

    gemm_mainloop(W, X, L, o0, l0, As, Bs, acc, tid, wid, g, tg);

    int r0 = o0 + wid * 16 + g, r1 = r0 + 8;
    float b0v = bias[r0], b1v = bias[r1];
#pragma unroll
    for (int nt = 0; nt < 8; nt++) {
        int l = l0 + nt * 8 + 2 * tg;
        float v00 = acc[nt][0] + b0v, v01 = acc[nt][1] + b0v;
        float v10 = acc[nt][2] + b1v, v11 = acc[nt][3] + b1v;
        if (type == 0) {
            g_q[offq + (size_t)(n * CC + r0) * L + l]     = v00;
            g_q[offq + (size_t)(n * CC + r0) * L + l + 1] = v01;
            g_q[offq + (size_t)(n * CC + r1) * L + l]     = v10;
            g_q[offq + (size_t)(n * CC + r1) * L + l + 1] = v11;
        } else {
            float* dst = (type == 1) ? g_k : g_v;
            size_t i00 = (size_t)offkv + ((size_t)((n * HEADS + (r0 >> 2)) * M) + l) * HD + (r0 & 3);
            size_t i10 = (size_t)offkv + ((size_t)((n * HEADS + (r1 >> 2)) * M) + l) * HD + (r1 & 3);
            dst[i00] = v00; dst[i00 + HD] = v01;
            dst[i10] = v10; dst[i10 + HD] = v11;
        }
    }
}

// ---------------- output GEMM (+residual) ----------------
__global__ void __launch_bounds__(128) gemm_o(const float* __restrict__ W,
                                              const float* __restrict__ bias,
                                              const float* __restrict__ res,
                                              float* __restrict__ dext,
                                              int L, int off) {
    __shared__ float As[2][16][72];
    __shared__ float Bs[2][16][72];
    int n = blockIdx.z;
    int o0 = blockIdx.y * 64, l0 = blockIdx.x * 64;
    const float* X = g_attn + off + (size_t)n * CC * L;
    int tid = threadIdx.x, wid = tid >> 5, lane = tid & 31;
    int g = lane >> 2, tg = lane & 3;

    float acc[8][4];
#pragma unroll
    for (int i = 0; i < 8; i++)
#pragma unroll
        for (int j = 0; j < 4; j++) acc[i][j] = 0.f;

    gemm_mainloop(W, X, L, o0, l0, As, Bs, acc, tid, wid, g, tg);

    int r0 = o0 + wid * 16 + g, r1 = r0 + 8;
    float b0v = bias[r0], b1v = bias[r1];
#pragma unroll
    for (int nt = 0; nt < 8; nt++) {
        int l = l0 + nt * 8 + 2 * tg;
        size_t b = (size_t)(n * CC + r0) * L + l;
        size_t c = (size_t)(n * CC + r1) * L + l;
        dext[off + b]     = acc[nt][0] + b0v + res[b];
        dext[off + b + 1] = acc[nt][1] + b0v + res[b + 1];
        dext[off + c]     = acc[nt][2] + b1v + res[c];
        dext[off + c + 1] = acc[nt][3] + b1v + res[c + 1];
    }
}

// ---------------- HMMA attention, f16x2 exp path, double-buffered staging ----------
// S-mma m16n8k16 (compensated bf16 split of Q,K -> ~fp32 logits).
// exp via ex2.approx.f16x2 (2 exps per MUFU op); weights feed a single f16
// O-mma m16n8k8 directly. V cols = [v0..v3, 1, ds-indicator, 0, 0] in f16;
// den from ones column keeps normalization consistent; OOB rows zero.
__global__ void __launch_bounds__(128) attn_mma(int qoff, int kvoff, int L, int M,
                                                float* __restrict__ dsout,
                                                float inv_hl, int lvl) {
    __shared__ __align__(16) uint4 s_k[2][128];
    __shared__ __align__(16) uint4 s_v[2][128];
    __shared__ float s_red[4];

    int tid = threadIdx.x, wid = tid >> 5, lane = tid & 31;
    int g = lane >> 2, tg = lane & 3;
    int n = blockIdx.z, h = blockIdx.y;
    int qlo = blockIdx.x * 64 + wid * 16 + g;
    int qhi = qlo + 8;

    const float SCALE = 0.5f * 1.4426950408889634f;
    size_t qbase = (size_t)qoff + ((size_t)(n * CC) + h * HD) * L;

    u32 a0, a1, a2, a3;
    {
        float hlo[4], llo[4], hhi[4], lhi[4];
#pragma unroll
        for (int d = 0; d < 4; d++) {
            float v = g_q[qbase + (size_t)d * L + qlo] * SCALE;
            float hf = __bfloat162float(__float2bfloat16(v));
            hlo[d] = hf; llo[d] = v - hf;
            v = g_q[qbase + (size_t)d * L + qhi] * SCALE;
            hf = __bfloat162float(__float2bfloat16(v));
            hhi[d] = hf; lhi[d] = v - hf;
        }
        a0 = (tg == 0) ? pkbf(hlo[0], hlo[1]) : (tg == 1) ? pkbf(hlo[2], hlo[3])
           : (tg == 2) ? pkbf(llo[0], llo[1]) : pkbf(llo[2], llo[3]);
        a1 = (tg == 0) ? pkbf(hhi[0], hhi[1]) : (tg == 1) ? pkbf(hhi[2], hhi[3])
           : (tg == 2) ? pkbf(lhi[0], lhi[1]) : pkbf(lhi[2], lhi[3]);
        a2 = (tg < 2) ? a0 : 0u;
        a3 = (tg < 2) ? a1 : 0u;
    }

    const float4* kp = (const float4*)g_k + (kvoff >> 2) + (size_t)(n * HEADS + h) * M;
    const float4* vp = (const float4*)g_v + (kvoff >> 2) + (size_t)(n * HEADS + h) * M;

    float o0 = 0.f, o1 = 0.f, o2 = 0.f, o3 = 0.f;
    u32 skb0 = smem_u32(s_k), svb0 = smem_u32(s_v);
    int nch = (M + 127) >> 7;
    const float4 FZ = make_float4(0.f, 0.f, 0.f, 0.f);

    // prologue: stage chunk 0 into buffer 0
    {
        float4 kk = (tid < M) ? kp[tid] : FZ;
        float k0h = __bfloat162float(__float2bfloat16(kk.x));
        float k1h = __bfloat162float(__float2bfloat16(kk.y));
        float k2h = __bfloat162float(__float2bfloat16(kk.z));
        float k3h = __bfloat162float(__float2bfloat16(kk.w));
        s_k[0][tid] = make_uint4(pkbf(k0h, k1h), pkbf(kk.x - k0h, kk.y - k1h),
                                 pkbf(k2h, k3h), pkbf(kk.z - k2h, kk.w - k3h));
        if (tid < 64) {
            int m0 = 2 * tid, m1 = m0 + 1;
            float4 v0 = (m0 < M) ? vp[m0] : FZ;
            float4 v1 = (m1 < M) ? vp[m1] : FZ;
            float one0 = (m0 < M) ? 1.f : 0.f, one1 = (m1 < M) ? 1.f : 0.f;
            float dsi0 = (m0 >= L && m0 < M) ? 1.f : 0.f;
            float dsi1 = (m1 >= L && m1 < M) ? 1.f : 0.f;
            s_v[0][2 * tid]     = make_uint4(pkhf(v0.x, v1.x), pkhf(v0.y, v1.y),
                                             pkhf(v0.z, v1.z), pkhf(v0.w, v1.w));
            s_v[0][2 * tid + 1] = make_uint4(pkhf(one0, one1), pkhf(dsi0, dsi1), 0u, 0u);
        }
    }
    __syncthreads();

    int buf = 0;
    for (int t = 0; t < nch; t++) {
        int base = t * 128;
        bool pf = (t + 1 < nch);
        float4 kk = FZ, v0 = FZ, v1 = FZ;
        int nb_base = base + 128;
        if (pf) {
            int m = nb_base + tid;
            if (m < M) kk = kp[m];
            if (tid < 64) {
                int m0 = nb_base + 2 * tid;
                if (m0 < M)     v0 = vp[m0];
                if (m0 + 1 < M) v1 = vp[m0 + 1];
            }
        }

        u32 skb = skb0 + (u32)buf * 2048;
        u32 svb = svb0 + (u32)buf * 2048;
#pragma unroll
        for (int blk = 0; blk < 16; blk++) {
            u32 b0, b1;
            u32 addr = skb + ((u32)(blk * 8 + g) << 4) + ((u32)(tg & 1) << 3);
            asm("ld.shared.v2.u32 {%0,%1},[%2];" : "=r"(b0), "=r"(b1) : "r"(addr));
            b1 = (tg < 2) ? b1 : 0u;
            float c0, c1, c2, c3;
            asm("mma.sync.aligned.m16n8k16.row.col.f32.bf16.bf16.f32 "
                "{%0,%1,%2,%3},{%4,%5,%6,%7},{%8,%9},{%10,%11,%12,%13};"
                : "=f"(c0), "=f"(c1), "=f"(c2), "=f"(c3)
                : "r"(a0), "r"(a1), "r"(a2), "r"(a3), "r"(b0), "r"(b1),
                  "f"(0.f), "f"(0.f), "f"(0.f), "f"(0.f));
            u32 p0 = pkhf(c0, c1), p1 = pkhf(c2, c3);
            u32 wa0, wa1;
            asm("ex2.approx.f16x2 %0,%1;" : "=r"(wa0) : "r"(p0));
            asm("ex2.approx.f16x2 %0,%1;" : "=r"(wa1) : "r"(p1));
            u32 vb;
            u32 vaddr = svb + ((u32)((blk * 4 + tg) * 8 + g) << 2);
            asm("ld.shared.u32 %0,[%1];" : "=r"(vb) : "r"(vaddr));
            asm("mma.sync.aligned.m16n8k8.row.col.f32.f16.f16.f32 "
                "{%0,%1,%2,%3},{%4,%5},{%6},{%0,%1,%2,%3};"
                : "+f"(o0), "+f"(o1), "+f"(o2), "+f"(o3)
                : "r"(wa0), "r"(wa1), "r"(vb));
        }

        if (pf) {
            int nb = buf ^ 1;
            float k0h = __bfloat162float(__float2bfloat16(kk.x));
            float k1h = __bfloat162float(__float2bfloat16(kk.y));
            float k2h = __bfloat162float(__float2bfloat16(kk.z));
            float k3h = __bfloat162float(__float2bfloat16(kk.w));
            s_k[nb][tid] = make_uint4(pkbf(k0h, k1h), pkbf(kk.x - k0h, kk.y - k1h),
                                      pkbf(k2h, k3h), pkbf(kk.z - k2h, kk.w - k3h));
            if (tid < 64) {
                int m0 = nb_base + 2 * tid, m1 = m0 + 1;
                float one0 = (m0 < M) ? 1.f : 0.f, one1 = (m1 < M) ? 1.f : 0.f;
                float dsi0 = (m0 >= L && m0 < M) ? 1.f : 0.f;
                float dsi1 = (m1 >= L && m1 < M) ? 1.f : 0.f;
                s_v[nb][2 * tid]     = make_uint4(pkhf(v0.x, v1.x), pkhf(v0.y, v1.y),
                                                  pkhf(v0.z, v1.z), pkhf(v0.w, v1.w));
                s_v[nb][2 * tid + 1] = make_uint4(pkhf(one0, one1), pkhf(dsi0, dsi1), 0u, 0u);
            }
            __syncthreads();
        }
        buf ^= 1;
    }

    // ---- epilogue ----
    u32 full = 0xffffffffu;
    int src = (lane & 0x1c) | 2;
    float den_lo = __shfl_sync(full, o0, src);
    float den_hi = __shfl_sync(full, o2, src);
    if (tg < 2) {
        float rl = 1.0f / den_lo, rh = 1.0f / den_hi;
        int d0 = tg * 2, d1 = tg * 2 + 1;
        g_attn[qbase + (size_t)d0 * L + qlo] = o0 * rl;
        g_attn[qbase + (size_t)d1 * L + qlo] = o1 * rl;
        g_attn[qbase + (size_t)d0 * L + qhi] = o2 * rh;
        g_attn[qbase + (size_t)d1 * L + qhi] = o3 * rh;
    }
    float contrib = (tg == 2) ? (o1 / o0 + o3 / o2) : 0.f;
#pragma unroll
    for (int off = 16; off > 0; off >>= 1) contrib += __shfl_down_sync(full, contrib, off);
    if (lane == 0) s_red[wid] = contrib;
    __syncthreads();
    if (tid == 0)
        atomicAdd(&dsout[lvl * 2 + n], (s_red[0] + s_red[1] + s_red[2] + s_red[3]) * inv_hl);
}

// ---------------- launch ----------------
extern "C" void kernel_launch(void* const* d_in, const int* in_sizes, int n_in,
                              void* d_out, int out_size) {
    const float* sp[4]; const float* iv[4]; const float* dd[4];
    for (int i = 0; i < 4; i++) {
        sp[i] = (const float*)d_in[i];
        iv[i] = (const float*)d_in[4 + i];
        dd[i] = (const float*)d_in[8 + i];
    }
    const float* Wq  = (const float*)d_in[12]; const float* bq  = (const float*)d_in[13];
    const float* Wk  = (const float*)d_in[14]; const float* bk  = (const float*)d_in[15];
    const float* Wv  = (const float*)d_in[16]; const float* bv  = (const float*)d_in[17];
    const float* Wo  = (const float*)d_in[18]; const float* bo  = (const float*)d_in[19];
    const float* Wdsk = (const float*)d_in[20]; const float* bdsk = (const float*)d_in[21];
    const float* Wdsv = (const float*)d_in[22]; const float* bdsv = (const float*)d_in[23];
    const float* gate = (const float*)d_in[24];
    float* out = (float*)d_out;

    static const int Lt[4]    = {4096, 1024, 256, 64};
    static const int qoff[4]  = {0, 2097152, 2621440, 2752512};
    static const int kvoff[4] = {0, 2113536, 2654208, 2801664};
    float* dsout = out + (out_size - 8);

    pooled_kernel<<<dim3(256, 2, 4), 256>>>(dd[0], dd[1], dd[2], dd[3], dsout);
    token_kernel<<<dim3(1024, 2, 8), 256>>>(Wdsk, bdsk, Wdsv, bdsv, gate);

    for (int lv = 0; lv < 4; lv++) {
        int L = Lt[lv], M = L + 32;
        gemm_qkv<<<dim3(L / 64, 12, 2), 128>>>(Wq + lv * 65536, Wk + lv * 65536,
                                               Wv + lv * 65536, bq + lv * 256,
                                               bk + lv * 256, bv + lv * 256,
                                               sp[lv], iv[lv], L, M, qoff[lv], kvoff[lv]);
        attn_mma<<<dim3(L / 64, HEADS, 2), 128>>>(qoff[lv], kvoff[lv], L, M,
                                                  dsout, 1.0f / (64.0f * (float)L), lv);
    }
    for (int lv = 0; lv < 4; lv++) {
        int L = Lt[lv];
        gemm_o<<<dim3(L / 64, 4, 2), 128>>>(Wo + lv * 65536, bo + lv * 256,
                                            sp[lv], out, L, qoff[lv]);
    }
}

// round 13
// speedup vs baseline: 2.8096x; 1.0624x over previous
#include <cuda_runtime.h>
#include <cuda_bf16.h>
#include <cuda_fp16.h>

#define CC    256
#define HEADS 64
#define HD    4
#define TT    32

typedef unsigned long long u64;
typedef unsigned int u32;

__device__ __align__(16) float g_q[2785280];      // (N,C,L) per level
__device__ __align__(16) float g_k[2850816];      // (n,h,m,4) per level
__device__ __align__(16) float g_v[2850816];
__device__ __align__(16) float g_attn[2785280];
__device__ float g_pooled[4 * 2 * CC];

__constant__ int c_L[4]     = {4096, 1024, 256, 64};
__constant__ int c_kvoff[4] = {0, 2113536, 2654208, 2801664};

__device__ __forceinline__ u32 pkhf(float lo, float hi) {   // f16x2 {lo,hi}
    u32 r; asm("cvt.rn.f16x2.f32 %0, %1, %2;" : "=r"(r) : "f"(hi), "f"(lo)); return r;
}
__device__ __forceinline__ float tf32f(float x) {
    u32 r; asm("cvt.rna.tf32.f32 %0,%1;" : "=r"(r) : "f"(x));
    return __uint_as_float(r);
}
__device__ __forceinline__ u32 smem_u32(const void* p) {
    u32 a; asm("{.reg .u64 t; cvta.to.shared.u64 t, %1; cvt.u32.u64 %0, t;}" : "=r"(a) : "l"(p));
    return a;
}

// ---------------- pooled mean (also zeroes ds output) ----------------
__global__ void pooled_kernel(const float* __restrict__ d0, const float* __restrict__ d1,
                              const float* __restrict__ d2, const float* __restrict__ d3,
                              float* __restrict__ dsout) {
    __shared__ float red[256];
    int lvl = blockIdx.z, n = blockIdx.y, c = blockIdx.x;
    if (lvl == 0 && n == 0 && c == 0 && threadIdx.x < 8) dsout[threadIdx.x] = 0.f;
    const float* dp = (lvl == 0) ? d0 : (lvl == 1) ? d1 : (lvl == 2) ? d2 : d3;
    int L = c_L[lvl];
    const float* p = dp + (size_t)(n * CC + c) * L;
    float s = 0.f;
    for (int i = threadIdx.x; i < L; i += blockDim.x) s += p[i];
    red[threadIdx.x] = s;
    __syncthreads();
    for (int st = blockDim.x >> 1; st > 0; st >>= 1) {
        if (threadIdx.x < st) red[threadIdx.x] += red[threadIdx.x + st];
        __syncthreads();
    }
    if (threadIdx.x == 0) g_pooled[(lvl * 2 + n) * CC + c] = red[0] / (float)L;
}

// ---------------- ds token projections -> tail of k/v ----------------
__global__ void token_kernel(const float* __restrict__ Wdsk, const float* __restrict__ bdsk,
                             const float* __restrict__ Wdsv, const float* __restrict__ bdsv,
                             const float* __restrict__ gate) {
    int kind = blockIdx.y;
    int lvl = blockIdx.z >> 1, n = blockIdx.z & 1;
    int warp = threadIdx.x >> 5, lane = threadIdx.x & 31;
    int j = blockIdx.x * 8 + warp;
    const float* Wr = (kind ? Wdsv : Wdsk) + (size_t)(lvl * 8192 + j) * 256;
    const float* pl = g_pooled + (lvl * 2 + n) * CC;
    float s = 0.f;
#pragma unroll
    for (int c = lane; c < 256; c += 32) s += Wr[c] * pl[c];
#pragma unroll
    for (int off = 16; off > 0; off >>= 1) s += __shfl_down_sync(0xffffffffu, s, off);
    if (lane == 0) {
        s += (kind ? bdsv : bdsk)[lvl * 8192 + j];
        if (kind) s *= 1.0f / (1.0f + __expf(-gate[lvl]));
        int h = j >> 7, d = (j >> 5) & 3, t = j & 31;
        int L = c_L[lvl], M = L + TT;
        size_t idx = (size_t)c_kvoff[lvl] + ((size_t)((n * HEADS + h) * M) + (L + t)) * HD + d;
        if (kind) g_v[idx] = s; else g_k[idx] = s;
    }
}

// ---------------- shared tf32 GEMM mainloop (double-buffered) ----------------
struct GemmCoords { int wrow[2], wk[2], xrow[2], xcc[2]; };

__device__ __forceinline__ void gemm_mainloop(const float* __restrict__ W,
                                              const float* __restrict__ X,
                                              int L, int o0, int l0,
                                              float (&As)[2][16][72], float (&Bs)[2][16][72],
                                              float (&acc)[8][4],
                                              int tid, int wid, int g, int tg) {
    GemmCoords cd;
#pragma unroll
    for (int r = 0; r < 2; r++) {
        int idx = tid + r * 128;
        cd.wrow[r] = idx >> 2;  cd.wk[r]  = (idx & 3) << 2;
        cd.xrow[r] = idx >> 4;  cd.xcc[r] = (idx & 15) << 2;
    }
    float4 wr[2], xr[2];
#pragma unroll
    for (int r = 0; r < 2; r++) {
        wr[r] = *(const float4*)&W[(size_t)(o0 + cd.wrow[r]) * 256 + cd.wk[r]];
        xr[r] = *(const float4*)&X[(size_t)cd.xrow[r] * L + l0 + cd.xcc[r]];
    }
#pragma unroll
    for (int r = 0; r < 2; r++) {
        As[0][cd.wk[r]][cd.wrow[r]]     = tf32f(wr[r].x);
        As[0][cd.wk[r] + 1][cd.wrow[r]] = tf32f(wr[r].y);
        As[0][cd.wk[r] + 2][cd.wrow[r]] = tf32f(wr[r].z);
        As[0][cd.wk[r] + 3][cd.wrow[r]] = tf32f(wr[r].w);
        Bs[0][cd.xrow[r]][cd.xcc[r]]     = tf32f(xr[r].x);
        Bs[0][cd.xrow[r]][cd.xcc[r] + 1] = tf32f(xr[r].y);
        Bs[0][cd.xrow[r]][cd.xcc[r] + 2] = tf32f(xr[r].z);
        Bs[0][cd.xrow[r]][cd.xcc[r] + 3] = tf32f(xr[r].w);
    }
    __syncthreads();

    int buf = 0;
    for (int k0 = 0; k0 < 256; k0 += 16) {
        bool pf = (k0 + 16 < 256);
        if (pf) {
#pragma unroll
            for (int r = 0; r < 2; r++) {
                wr[r] = *(const float4*)&W[(size_t)(o0 + cd.wrow[r]) * 256 + k0 + 16 + cd.wk[r]];
                xr[r] = *(const float4*)&X[(size_t)(k0 + 16 + cd.xrow[r]) * L + l0 + cd.xcc[r]];
            }
        }
#pragma unroll
        for (int ks = 0; ks < 2; ks++) {
            int kb = ks * 8;
            u32 a0 = __float_as_uint(As[buf][kb + tg][wid * 16 + g]);
            u32 a1 = __float_as_uint(As[buf][kb + tg][wid * 16 + g + 8]);
            u32 a2 = __float_as_uint(As[buf][kb + tg + 4][wid * 16 + g]);
            u32 a3 = __float_as_uint(As[buf][kb + tg + 4][wid * 16 + g + 8]);
#pragma unroll
            for (int nt = 0; nt < 8; nt++) {
                u32 b0 = __float_as_uint(Bs[buf][kb + tg][nt * 8 + g]);
                u32 b1 = __float_as_uint(Bs[buf][kb + tg + 4][nt * 8 + g]);
                asm("mma.sync.aligned.m16n8k8.row.col.f32.tf32.tf32.f32 "
                    "{%0,%1,%2,%3},{%4,%5,%6,%7},{%8,%9},{%0,%1,%2,%3};"
                    : "+f"(acc[nt][0]), "+f"(acc[nt][1]), "+f"(acc[nt][2]), "+f"(acc[nt][3])
                    : "r"(a0), "r"(a1), "r"(a2), "r"(a3), "r"(b0), "r"(b1));
            }
        }
        if (pf) {
            int nb = buf ^ 1;
#pragma unroll
            for (int r = 0; r < 2; r++) {
                As[nb][cd.wk[r]][cd.wrow[r]]     = tf32f(wr[r].x);
                As[nb][cd.wk[r] + 1][cd.wrow[r]] = tf32f(wr[r].y);
                As[nb][cd.wk[r] + 2][cd.wrow[r]] = tf32f(wr[r].z);
                As[nb][cd.wk[r] + 3][cd.wrow[r]] = tf32f(wr[r].w);
                Bs[nb][cd.xrow[r]][cd.xcc[r]]     = tf32f(xr[r].x);
                Bs[nb][cd.xrow[r]][cd.xcc[r] + 1] = tf32f(xr[r].y);
                Bs[nb][cd.xrow[r]][cd.xcc[r] + 2] = tf32f(xr[r].z);
                Bs[nb][cd.xrow[r]][cd.xcc[r] + 3] = tf32f(xr[r].w);
            }
            __syncthreads();
        }
        buf ^= 1;
    }
}

// ---------------- fused q/k/v GEMM: blockIdx.y = type*4 + row-tile ----------------
__global__ void __launch_bounds__(128) gemm_qkv(const float* __restrict__ Wq,
                                                const float* __restrict__ Wk,
                                                const float* __restrict__ Wv,
                                                const float* __restrict__ bq,
                                                const float* __restrict__ bk,
                                                const float* __restrict__ bv,
                                                const float* __restrict__ sp,
                                                const float* __restrict__ iv,
                                                int L, int M, int offq, int offkv) {
    __shared__ float As[2][16][72];
    __shared__ float Bs[2][16][72];
    int n = blockIdx.z;
    int type = blockIdx.y >> 2;
    int o0 = (blockIdx.y & 3) * 64, l0 = blockIdx.x * 64;
    const float* W = (type == 0) ? Wq : (type == 1) ? Wk : Wv;
    const float* bias = (type == 0) ? bq : (type == 1) ? bk : bv;
    const float* X = ((type == 0) ? sp : iv) + (size_t)n * CC * L;
    int tid = threadIdx.x, wid = tid >> 5, lane = tid & 31;
    int g = lane >> 2, tg = lane & 3;

    float acc[8][4];
#pragma unroll
    for (int i = 0; i < 8; i++)
#pragma unroll
        for (int j = 0; j < 4; j++) acc[i][j] = 0.f;

    gemm_mainloop(W, X, L, o0, l0, As, Bs, acc, tid, wid, g, tg);

    int r0 = o0 + wid * 16 + g, r1 = r0 + 8;
    float b0v = bias[r0], b1v = bias[r1];
#pragma unroll
    for (int nt = 0; nt < 8; nt++) {
        int l = l0 + nt * 8 + 2 * tg;
        float v00 = acc[nt][0] + b0v, v01 = acc[nt][1] + b0v;
        float v10 = acc[nt][2] + b1v, v11 = acc[nt][3] + b1v;
        if (type == 0) {
            g_q[offq + (size_t)(n * CC + r0) * L + l]     = v00;
            g_q[offq + (size_t)(n * CC + r0) * L + l + 1] = v01;
            g_q[offq + (size_t)(n * CC + r1) * L + l]     = v10;
            g_q[offq + (size_t)(n * CC + r1) * L + l + 1] = v11;
        } else {
            float* dst = (type == 1) ? g_k : g_v;
            size_t i00 = (size_t)offkv + ((size_t)((n * HEADS + (r0 >> 2)) * M) + l) * HD + (r0 & 3);
            size_t i10 = (size_t)offkv + ((size_t)((n * HEADS + (r1 >> 2)) * M) + l) * HD + (r1 & 3);
            dst[i00] = v00; dst[i00 + HD] = v01;
            dst[i10] = v10; dst[i10 + HD] = v11;
        }
    }
}

// ---------------- output GEMM (+residual) ----------------
__global__ void __launch_bounds__(128) gemm_o(const float* __restrict__ W,
                                              const float* __restrict__ bias,
                                              const float* __restrict__ res,
                                              float* __restrict__ dext,
                                              int L, int off) {
    __shared__ float As[2][16][72];
    __shared__ float Bs[2][16][72];
    int n = blockIdx.z;
    int o0 = blockIdx.y * 64, l0 = blockIdx.x * 64;
    const float* X = g_attn + off + (size_t)n * CC * L;
    int tid = threadIdx.x, wid = tid >> 5, lane = tid & 31;
    int g = lane >> 2, tg = lane & 3;

    float acc[8][4];
#pragma unroll
    for (int i = 0; i < 8; i++)
#pragma unroll
        for (int j = 0; j < 4; j++) acc[i][j] = 0.f;

    gemm_mainloop(W, X, L, o0, l0, As, Bs, acc, tid, wid, g, tg);

    int r0 = o0 + wid * 16 + g, r1 = r0 + 8;
    float b0v = bias[r0], b1v = bias[r1];
#pragma unroll
    for (int nt = 0; nt < 8; nt++) {
        int l = l0 + nt * 8 + 2 * tg;
        size_t b = (size_t)(n * CC + r0) * L + l;
        size_t c = (size_t)(n * CC + r1) * L + l;
        dext[off + b]     = acc[nt][0] + b0v + res[b];
        dext[off + b + 1] = acc[nt][1] + b0v + res[b + 1];
        dext[off + c]     = acc[nt][2] + b1v + res[c];
        dext[off + c + 1] = acc[nt][3] + b1v + res[c + 1];
    }
}

// ---------------- HMMA attention: all-f16, 2 k8-MMAs per 8-key block ----------------
// S-mma m16n8k8.f16: A rows = [q_hi(4) | q_lo(4)] (f16 split), B rows =
// [k_f16(4) | k_f16(4)] -> logits accurate to ~2^-11 of |q||k|.
// exp via ex2.approx.f16x2; weights feed an f16 O-mma m16n8k8 directly.
// V cols = [v0..v3, 1, ds-indicator, 0, 0] in f16; den from ones column;
// OOB key rows zero (w=1 but V row zero => no contribution).
__global__ void __launch_bounds__(128) attn_mma(int qoff, int kvoff, int L, int M,
                                                float* __restrict__ dsout,
                                                float inv_hl, int lvl) {
    __shared__ __align__(16) uint2 s_k[2][128];   // per key: {k01_f16x2, k23_f16x2}
    __shared__ __align__(16) uint4 s_v[2][128];   // per pair: [c01..c31],[1,ds,0,0]
    __shared__ float s_red[4];

    int tid = threadIdx.x, wid = tid >> 5, lane = tid & 31;
    int g = lane >> 2, tg = lane & 3;
    int n = blockIdx.z, h = blockIdx.y;
    int qlo = blockIdx.x * 64 + wid * 16 + g;
    int qhi = qlo + 8;

    const float SCALE = 0.5f * 1.4426950408889634f;
    size_t qbase = (size_t)qoff + ((size_t)(n * CC) + h * HD) * L;

    // S-mma A fragment: k-cols 2tg,2tg+1 of [qh0..qh3, ql0..ql3]
    u32 a0, a1;
    {
        float hL[4], lL[4], hH[4], lH[4];
#pragma unroll
        for (int d = 0; d < 4; d++) {
            float v = g_q[qbase + (size_t)d * L + qlo] * SCALE;
            float hf = __half2float(__float2half(v));
            hL[d] = hf; lL[d] = v - hf;
            v = g_q[qbase + (size_t)d * L + qhi] * SCALE;
            hf = __half2float(__float2half(v));
            hH[d] = hf; lH[d] = v - hf;
        }
        a0 = (tg == 0) ? pkhf(hL[0], hL[1]) : (tg == 1) ? pkhf(hL[2], hL[3])
           : (tg == 2) ? pkhf(lL[0], lL[1]) : pkhf(lL[2], lL[3]);
        a1 = (tg == 0) ? pkhf(hH[0], hH[1]) : (tg == 1) ? pkhf(hH[2], hH[3])
           : (tg == 2) ? pkhf(lH[0], lH[1]) : pkhf(lH[2], lH[3]);
    }

    const float4* kp = (const float4*)g_k + (kvoff >> 2) + (size_t)(n * HEADS + h) * M;
    const float4* vp = (const float4*)g_v + (kvoff >> 2) + (size_t)(n * HEADS + h) * M;

    float o0 = 0.f, o1 = 0.f, o2 = 0.f, o3 = 0.f;
    u32 skb0 = smem_u32(s_k), svb0 = smem_u32(s_v);
    int nch = (M + 127) >> 7;
    const float4 FZ = make_float4(0.f, 0.f, 0.f, 0.f);

    // prologue: stage chunk 0 into buffer 0
    {
        float4 kk = (tid < M) ? kp[tid] : FZ;
        s_k[0][tid] = make_uint2(pkhf(kk.x, kk.y), pkhf(kk.z, kk.w));
        if (tid < 64) {
            int m0 = 2 * tid, m1 = m0 + 1;
            float4 v0 = (m0 < M) ? vp[m0] : FZ;
            float4 v1 = (m1 < M) ? vp[m1] : FZ;
            float one0 = (m0 < M) ? 1.f : 0.f, one1 = (m1 < M) ? 1.f : 0.f;
            float dsi0 = (m0 >= L && m0 < M) ? 1.f : 0.f;
            float dsi1 = (m1 >= L && m1 < M) ? 1.f : 0.f;
            s_v[0][2 * tid]     = make_uint4(pkhf(v0.x, v1.x), pkhf(v0.y, v1.y),
                                             pkhf(v0.z, v1.z), pkhf(v0.w, v1.w));
            s_v[0][2 * tid + 1] = make_uint4(pkhf(one0, one1), pkhf(dsi0, dsi1), 0u, 0u);
        }
    }
    __syncthreads();

    int buf = 0;
    for (int t = 0; t < nch; t++) {
        int base = t * 128;
        bool pf = (t + 1 < nch);
        float4 kk = FZ, v0 = FZ, v1 = FZ;
        int nb_base = base + 128;
        if (pf) {
            int m = nb_base + tid;
            if (m < M) kk = kp[m];
            if (tid < 64) {
                int m0 = nb_base + 2 * tid;
                if (m0 < M)     v0 = vp[m0];
                if (m0 + 1 < M) v1 = vp[m0 + 1];
            }
        }

        u32 skb = skb0 + (u32)buf * 1024;
        u32 svb = svb0 + (u32)buf * 2048;
#pragma unroll
        for (int blk = 0; blk < 16; blk++) {
            u32 b0;
            u32 addr = skb + ((u32)(blk * 8 + g) << 3) + ((u32)(tg & 1) << 2);
            asm("ld.shared.u32 %0,[%1];" : "=r"(b0) : "r"(addr));
            float c0, c1, c2, c3;
            asm("mma.sync.aligned.m16n8k8.row.col.f32.f16.f16.f32 "
                "{%0,%1,%2,%3},{%4,%5},{%6},{%7,%8,%9,%10};"
                : "=f"(c0), "=f"(c1), "=f"(c2), "=f"(c3)
                : "r"(a0), "r"(a1), "r"(b0),
                  "f"(0.f), "f"(0.f), "f"(0.f), "f"(0.f));
            u32 p0 = pkhf(c0, c1), p1 = pkhf(c2, c3);
            u32 wa0, wa1;
            asm("ex2.approx.f16x2 %0,%1;" : "=r"(wa0) : "r"(p0));
            asm("ex2.approx.f16x2 %0,%1;" : "=r"(wa1) : "r"(p1));
            u32 vb;
            u32 vaddr = svb + ((u32)((blk * 4 + tg) * 8 + g) << 2);
            asm("ld.shared.u32 %0,[%1];" : "=r"(vb) : "r"(vaddr));
            asm("mma.sync.aligned.m16n8k8.row.col.f32.f16.f16.f32 "
                "{%0,%1,%2,%3},{%4,%5},{%6},{%0,%1,%2,%3};"
                : "+f"(o0), "+f"(o1), "+f"(o2), "+f"(o3)
                : "r"(wa0), "r"(wa1), "r"(vb));
        }

        if (pf) {
            int nb = buf ^ 1;
            s_k[nb][tid] = make_uint2(pkhf(kk.x, kk.y), pkhf(kk.z, kk.w));
            if (tid < 64) {
                int m0 = nb_base + 2 * tid, m1 = m0 + 1;
                float one0 = (m0 < M) ? 1.f : 0.f, one1 = (m1 < M) ? 1.f : 0.f;
                float dsi0 = (m0 >= L && m0 < M) ? 1.f : 0.f;
                float dsi1 = (m1 >= L && m1 < M) ? 1.f : 0.f;
                s_v[nb][2 * tid]     = make_uint4(pkhf(v0.x, v1.x), pkhf(v0.y, v1.y),
                                                  pkhf(v0.z, v1.z), pkhf(v0.w, v1.w));
                s_v[nb][2 * tid + 1] = make_uint4(pkhf(one0, one1), pkhf(dsi0, dsi1), 0u, 0u);
            }
            __syncthreads();
        }
        buf ^= 1;
    }

    // ---- epilogue ----
    u32 full = 0xffffffffu;
    int src = (lane & 0x1c) | 2;
    float den_lo = __shfl_sync(full, o0, src);
    float den_hi = __shfl_sync(full, o2, src);
    if (tg < 2) {
        float rl = 1.0f / den_lo, rh = 1.0f / den_hi;
        int d0 = tg * 2, d1 = tg * 2 + 1;
        g_attn[qbase + (size_t)d0 * L + qlo] = o0 * rl;
        g_attn[qbase + (size_t)d1 * L + qlo] = o1 * rl;
        g_attn[qbase + (size_t)d0 * L + qhi] = o2 * rh;
        g_attn[qbase + (size_t)d1 * L + qhi] = o3 * rh;
    }
    float contrib = (tg == 2) ? (o1 / o0 + o3 / o2) : 0.f;
#pragma unroll
    for (int off = 16; off > 0; off >>= 1) contrib += __shfl_down_sync(full, contrib, off);
    if (lane == 0) s_red[wid] = contrib;
    __syncthreads();
    if (tid == 0)
        atomicAdd(&dsout[lvl * 2 + n], (s_red[0] + s_red[1] + s_red[2] + s_red[3]) * inv_hl);
}

// ---------------- launch ----------------
extern "C" void kernel_launch(void* const* d_in, const int* in_sizes, int n_in,
                              void* d_out, int out_size) {
    const float* sp[4]; const float* iv[4]; const float* dd[4];
    for (int i = 0; i < 4; i++) {
        sp[i] = (const float*)d_in[i];
        iv[i] = (const float*)d_in[4 + i];
        dd[i] = (const float*)d_in[8 + i];
    }
    const float* Wq  = (const float*)d_in[12]; const float* bq  = (const float*)d_in[13];
    const float* Wk  = (const float*)d_in[14]; const float* bk  = (const float*)d_in[15];
    const float* Wv  = (const float*)d_in[16]; const float* bv  = (const float*)d_in[17];
    const float* Wo  = (const float*)d_in[18]; const float* bo  = (const float*)d_in[19];
    const float* Wdsk = (const float*)d_in[20]; const float* bdsk = (const float*)d_in[21];
    const float* Wdsv = (const float*)d_in[22]; const float* bdsv = (const float*)d_in[23];
    const float* gate = (const float*)d_in[24];
    float* out = (float*)d_out;

    static const int Lt[4]    = {4096, 1024, 256, 64};
    static const int qoff[4]  = {0, 2097152, 2621440, 2752512};
    static const int kvoff[4] = {0, 2113536, 2654208, 2801664};
    float* dsout = out + (out_size - 8);

    pooled_kernel<<<dim3(256, 2, 4), 256>>>(dd[0], dd[1], dd[2], dd[3], dsout);
    token_kernel<<<dim3(1024, 2, 8), 256>>>(Wdsk, bdsk, Wdsv, bdsv, gate);

    for (int lv = 0; lv < 4; lv++) {
        int L = Lt[lv], M = L + 32;
        gemm_qkv<<<dim3(L / 64, 12, 2), 128>>>(Wq + lv * 65536, Wk + lv * 65536,
                                               Wv + lv * 65536, bq + lv * 256,
                                               bk + lv * 256, bv + lv * 256,
                                               sp[lv], iv[lv], L, M, qoff[lv], kvoff[lv]);
        attn_mma<<<dim3(L / 64, HEADS, 2), 128>>>(qoff[lv], kvoff[lv], L, M,
                                                  dsout, 1.0f / (64.0f * (float)L), lv);
    }
    for (int lv = 0; lv < 4; lv++) {
        int L = Lt[lv];
        gemm_o<<<dim3(L / 64, 4, 2), 128>>>(Wo + lv * 65536, bo + lv * 256,
                                            sp[lv], out, L, qoff[lv]);
    }
}

// round 14
// speedup vs baseline: 2.9169x; 1.0382x over previous
#include <cuda_runtime.h>
#include <cuda_bf16.h>
#include <cuda_fp16.h>

#define CC    256
#define HEADS 64
#define HD    4
#define TT    32

typedef unsigned long long u64;
typedef unsigned int u32;

__device__ __align__(16) float g_q[2785280];      // (N,C,L) per level
__device__ __align__(16) float g_k[2850816];      // (n,h,m,4) per level
__device__ __align__(16) float g_v[2850816];
__device__ __align__(16) float g_attn[2785280];
__device__ float g_pooled[4 * 2 * CC];

__constant__ int c_L[4]     = {4096, 1024, 256, 64};
__constant__ int c_kvoff[4] = {0, 2113536, 2654208, 2801664};

__device__ __forceinline__ u32 pkhf(float lo, float hi) {   // f16x2 {lo,hi}
    u32 r; asm("cvt.rn.f16x2.f32 %0, %1, %2;" : "=r"(r) : "f"(hi), "f"(lo)); return r;
}
__device__ __forceinline__ float tf32f(float x) {
    u32 r; asm("cvt.rna.tf32.f32 %0,%1;" : "=r"(r) : "f"(x));
    return __uint_as_float(r);
}
__device__ __forceinline__ u32 smem_u32(const void* p) {
    u32 a; asm("{.reg .u64 t; cvta.to.shared.u64 t, %1; cvt.u32.u64 %0, t;}" : "=r"(a) : "l"(p));
    return a;
}

// ---------------- pooled mean (also zeroes ds output) ----------------
__global__ void pooled_kernel(const float* __restrict__ d0, const float* __restrict__ d1,
                              const float* __restrict__ d2, const float* __restrict__ d3,
                              float* __restrict__ dsout) {
    __shared__ float red[256];
    int lvl = blockIdx.z, n = blockIdx.y, c = blockIdx.x;
    if (lvl == 0 && n == 0 && c == 0 && threadIdx.x < 8) dsout[threadIdx.x] = 0.f;
    const float* dp = (lvl == 0) ? d0 : (lvl == 1) ? d1 : (lvl == 2) ? d2 : d3;
    int L = c_L[lvl];
    const float* p = dp + (size_t)(n * CC + c) * L;
    float s = 0.f;
    for (int i = threadIdx.x; i < L; i += blockDim.x) s += p[i];
    red[threadIdx.x] = s;
    __syncthreads();
    for (int st = blockDim.x >> 1; st > 0; st >>= 1) {
        if (threadIdx.x < st) red[threadIdx.x] += red[threadIdx.x + st];
        __syncthreads();
    }
    if (threadIdx.x == 0) g_pooled[(lvl * 2 + n) * CC + c] = red[0] / (float)L;
}

// ---------------- ds token projections -> tail of k/v ----------------
__global__ void token_kernel(const float* __restrict__ Wdsk, const float* __restrict__ bdsk,
                             const float* __restrict__ Wdsv, const float* __restrict__ bdsv,
                             const float* __restrict__ gate) {
    int kind = blockIdx.y;
    int lvl = blockIdx.z >> 1, n = blockIdx.z & 1;
    int warp = threadIdx.x >> 5, lane = threadIdx.x & 31;
    int j = blockIdx.x * 8 + warp;
    const float* Wr = (kind ? Wdsv : Wdsk) + (size_t)(lvl * 8192 + j) * 256;
    const float* pl = g_pooled + (lvl * 2 + n) * CC;
    float s = 0.f;
#pragma unroll
    for (int c = lane; c < 256; c += 32) s += Wr[c] * pl[c];
#pragma unroll
    for (int off = 16; off > 0; off >>= 1) s += __shfl_down_sync(0xffffffffu, s, off);
    if (lane == 0) {
        s += (kind ? bdsv : bdsk)[lvl * 8192 + j];
        if (kind) s *= 1.0f / (1.0f + __expf(-gate[lvl]));
        int h = j >> 7, d = (j >> 5) & 3, t = j & 31;
        int L = c_L[lvl], M = L + TT;
        size_t idx = (size_t)c_kvoff[lvl] + ((size_t)((n * HEADS + h) * M) + (L + t)) * HD + d;
        if (kind) g_v[idx] = s; else g_k[idx] = s;
    }
}

// ---------------- shared tf32 GEMM mainloop (double-buffered) ----------------
struct GemmCoords { int wrow[2], wk[2], xrow[2], xcc[2]; };

__device__ __forceinline__ void gemm_mainloop(const float* __restrict__ W,
                                              const float* __restrict__ X,
                                              int L, int o0, int l0,
                                              float (&As)[2][16][72], float (&Bs)[2][16][72],
                                              float (&acc)[8][4],
                                              int tid, int wid, int g, int tg) {
    GemmCoords cd;
#pragma unroll
    for (int r = 0; r < 2; r++) {
        int idx = tid + r * 128;
        cd.wrow[r] = idx >> 2;  cd.wk[r]  = (idx & 3) << 2;
        cd.xrow[r] = idx >> 4;  cd.xcc[r] = (idx & 15) << 2;
    }
    float4 wr[2], xr[2];
#pragma unroll
    for (int r = 0; r < 2; r++) {
        wr[r] = *(const float4*)&W[(size_t)(o0 + cd.wrow[r]) * 256 + cd.wk[r]];
        xr[r] = *(const float4*)&X[(size_t)cd.xrow[r] * L + l0 + cd.xcc[r]];
    }
#pragma unroll
    for (int r = 0; r < 2; r++) {
        As[0][cd.wk[r]][cd.wrow[r]]     = tf32f(wr[r].x);
        As[0][cd.wk[r] + 1][cd.wrow[r]] = tf32f(wr[r].y);
        As[0][cd.wk[r] + 2][cd.wrow[r]] = tf32f(wr[r].z);
        As[0][cd.wk[r] + 3][cd.wrow[r]] = tf32f(wr[r].w);
        Bs[0][cd.xrow[r]][cd.xcc[r]]     = tf32f(xr[r].x);
        Bs[0][cd.xrow[r]][cd.xcc[r] + 1] = tf32f(xr[r].y);
        Bs[0][cd.xrow[r]][cd.xcc[r] + 2] = tf32f(xr[r].z);
        Bs[0][cd.xrow[r]][cd.xcc[r] + 3] = tf32f(xr[r].w);
    }
    __syncthreads();

    int buf = 0;
    for (int k0 = 0; k0 < 256; k0 += 16) {
        bool pf = (k0 + 16 < 256);
        if (pf) {
#pragma unroll
            for (int r = 0; r < 2; r++) {
                wr[r] = *(const float4*)&W[(size_t)(o0 + cd.wrow[r]) * 256 + k0 + 16 + cd.wk[r]];
                xr[r] = *(const float4*)&X[(size_t)(k0 + 16 + cd.xrow[r]) * L + l0 + cd.xcc[r]];
            }
        }
#pragma unroll
        for (int ks = 0; ks < 2; ks++) {
            int kb = ks * 8;
            u32 a0 = __float_as_uint(As[buf][kb + tg][wid * 16 + g]);
            u32 a1 = __float_as_uint(As[buf][kb + tg][wid * 16 + g + 8]);
            u32 a2 = __float_as_uint(As[buf][kb + tg + 4][wid * 16 + g]);
            u32 a3 = __float_as_uint(As[buf][kb + tg + 4][wid * 16 + g + 8]);
#pragma unroll
            for (int nt = 0; nt < 8; nt++) {
                u32 b0 = __float_as_uint(Bs[buf][kb + tg][nt * 8 + g]);
                u32 b1 = __float_as_uint(Bs[buf][kb + tg + 4][nt * 8 + g]);
                asm("mma.sync.aligned.m16n8k8.row.col.f32.tf32.tf32.f32 "
                    "{%0,%1,%2,%3},{%4,%5,%6,%7},{%8,%9},{%0,%1,%2,%3};"
                    : "+f"(acc[nt][0]), "+f"(acc[nt][1]), "+f"(acc[nt][2]), "+f"(acc[nt][3])
                    : "r"(a0), "r"(a1), "r"(a2), "r"(a3), "r"(b0), "r"(b1));
            }
        }
        if (pf) {
            int nb = buf ^ 1;
#pragma unroll
            for (int r = 0; r < 2; r++) {
                As[nb][cd.wk[r]][cd.wrow[r]]     = tf32f(wr[r].x);
                As[nb][cd.wk[r] + 1][cd.wrow[r]] = tf32f(wr[r].y);
                As[nb][cd.wk[r] + 2][cd.wrow[r]] = tf32f(wr[r].z);
                As[nb][cd.wk[r] + 3][cd.wrow[r]] = tf32f(wr[r].w);
                Bs[nb][cd.xrow[r]][cd.xcc[r]]     = tf32f(xr[r].x);
                Bs[nb][cd.xrow[r]][cd.xcc[r] + 1] = tf32f(xr[r].y);
                Bs[nb][cd.xrow[r]][cd.xcc[r] + 2] = tf32f(xr[r].z);
                Bs[nb][cd.xrow[r]][cd.xcc[r] + 3] = tf32f(xr[r].w);
            }
            __syncthreads();
        }
        buf ^= 1;
    }
}

// ---------------- fused q/k/v GEMM: blockIdx.y = type*4 + row-tile ----------------
__global__ void __launch_bounds__(128) gemm_qkv(const float* __restrict__ Wq,
                                                const float* __restrict__ Wk,
                                                const float* __restrict__ Wv,
                                                const float* __restrict__ bq,
                                                const float* __restrict__ bk,
                                                const float* __restrict__ bv,
                                                const float* __restrict__ sp,
                                                const float* __restrict__ iv,
                                                int L, int M, int offq, int offkv) {
    __shared__ float As[2][16][72];
    __shared__ float Bs[2][16][72];
    int n = blockIdx.z;
    int type = blockIdx.y >> 2;
    int o0 = (blockIdx.y & 3) * 64, l0 = blockIdx.x * 64;
    const float* W = (type == 0) ? Wq : (type == 1) ? Wk : Wv;
    const float* bias = (type == 0) ? bq : (type == 1) ? bk : bv;
    const float* X = ((type == 0) ? sp : iv) + (size_t)n * CC * L;
    int tid = threadIdx.x, wid = tid >> 5, lane = tid & 31;
    int g = lane >> 2, tg = lane & 3;

    float acc[8][4];
#pragma unroll
    for (int i = 0; i < 8; i++)
#pragma unroll
        for (int j = 0; j < 4; j++) acc[i][j] = 0.f;

    gemm_mainloop(W, X, L, o0, l0, As, Bs, acc, tid, wid, g, tg);

    int r0 = o0 + wid * 16 + g, r1 = r0 + 8;
    float b0v = bias[r0], b1v = bias[r1];
#pragma unroll
    for (int nt = 0; nt < 8; nt++) {
        int l = l0 + nt * 8 + 2 * tg;
        float v00 = acc[nt][0] + b0v, v01 = acc[nt][1] + b0v;
        float v10 = acc[nt][2] + b1v, v11 = acc[nt][3] + b1v;
        if (type == 0) {
            g_q[offq + (size_t)(n * CC + r0) * L + l]     = v00;
            g_q[offq + (size_t)(n * CC + r0) * L + l + 1] = v01;
            g_q[offq + (size_t)(n * CC + r1) * L + l]     = v10;
            g_q[offq + (size_t)(n * CC + r1) * L + l + 1] = v11;
        } else {
            float* dst = (type == 1) ? g_k : g_v;
            size_t i00 = (size_t)offkv + ((size_t)((n * HEADS + (r0 >> 2)) * M) + l) * HD + (r0 & 3);
            size_t i10 = (size_t)offkv + ((size_t)((n * HEADS + (r1 >> 2)) * M) + l) * HD + (r1 & 3);
            dst[i00] = v00; dst[i00 + HD] = v01;
            dst[i10] = v10; dst[i10 + HD] = v11;
        }
    }
}

// ---------------- output GEMM (+residual) ----------------
__global__ void __launch_bounds__(128) gemm_o(const float* __restrict__ W,
                                              const float* __restrict__ bias,
                                              const float* __restrict__ res,
                                              float* __restrict__ dext,
                                              int L, int off) {
    __shared__ float As[2][16][72];
    __shared__ float Bs[2][16][72];
    int n = blockIdx.z;
    int o0 = blockIdx.y * 64, l0 = blockIdx.x * 64;
    const float* X = g_attn + off + (size_t)n * CC * L;
    int tid = threadIdx.x, wid = tid >> 5, lane = tid & 31;
    int g = lane >> 2, tg = lane & 3;

    float acc[8][4];
#pragma unroll
    for (int i = 0; i < 8; i++)
#pragma unroll
        for (int j = 0; j < 4; j++) acc[i][j] = 0.f;

    gemm_mainloop(W, X, L, o0, l0, As, Bs, acc, tid, wid, g, tg);

    int r0 = o0 + wid * 16 + g, r1 = r0 + 8;
    float b0v = bias[r0], b1v = bias[r1];
#pragma unroll
    for (int nt = 0; nt < 8; nt++) {
        int l = l0 + nt * 8 + 2 * tg;
        size_t b = (size_t)(n * CC + r0) * L + l;
        size_t c = (size_t)(n * CC + r1) * L + l;
        dext[off + b]     = acc[nt][0] + b0v + res[b];
        dext[off + b + 1] = acc[nt][1] + b0v + res[b + 1];
        dext[off + c]     = acc[nt][2] + b1v + res[c];
        dext[off + c + 1] = acc[nt][3] + b1v + res[c + 1];
    }
}

// ---------------- HMMA attention: 2 query-tiles per CTA (128 q), all-f16 ------------
// Per 8-key block: 1 K LDS + 2 S-mma + 4 ex2.f16x2 + 1 V LDS + 2 O-mma.
// S-mma m16n8k8.f16: A rows = [q_hi(4) | q_lo(4)], B rows = [k(4) | k(4)].
// V cols = [v0..v3, 1, ds-indicator, 0, 0] f16; den from ones column; OOB rows zero.
__global__ void __launch_bounds__(128) attn_mma(int qoff, int kvoff, int L, int M,
                                                float* __restrict__ dsout,
                                                float inv_hl, int lvl) {
    __shared__ __align__(16) uint2 s_k[2][128];   // per key: {k01, k23} f16x2
    __shared__ __align__(16) uint4 s_v[2][128];   // per pair: [c01..c31],[1,ds,0,0]
    __shared__ float s_red[4];

    int tid = threadIdx.x, wid = tid >> 5, lane = tid & 31;
    int g = lane >> 2, tg = lane & 3;
    int n = blockIdx.z, h = blockIdx.y;
    int qA = blockIdx.x * 128 + wid * 16 + g;        // tile A rows qA, qA+8
    int qB = qA + 64;                                // tile B rows qB, qB+8
    bool tileB = (blockIdx.x * 128 + 64) < L;

    const float SCALE = 0.5f * 1.4426950408889634f;
    size_t qbase = (size_t)qoff + ((size_t)(n * CC) + h * HD) * L;

    // Build S-mma A fragments for both tiles
    u32 aA0, aA1, aB0, aB1;
    {
        int qBs = tileB ? qB : qA;   // safe load index
        float hA0[4], lA0[4], hA1[4], lA1[4], hB0[4], lB0[4], hB1[4], lB1[4];
#pragma unroll
        for (int d = 0; d < 4; d++) {
            float v = g_q[qbase + (size_t)d * L + qA] * SCALE;
            float hf = __half2float(__float2half(v));
            hA0[d] = hf; lA0[d] = v - hf;
            v = g_q[qbase + (size_t)d * L + qA + 8] * SCALE;
            hf = __half2float(__float2half(v));
            hA1[d] = hf; lA1[d] = v - hf;
            v = g_q[qbase + (size_t)d * L + qBs] * SCALE;
            hf = __half2float(__float2half(v));
            hB0[d] = hf; lB0[d] = v - hf;
            v = g_q[qbase + (size_t)d * L + qBs + 8] * SCALE;
            hf = __half2float(__float2half(v));
            hB1[d] = hf; lB1[d] = v - hf;
        }
        aA0 = (tg == 0) ? pkhf(hA0[0], hA0[1]) : (tg == 1) ? pkhf(hA0[2], hA0[3])
            : (tg == 2) ? pkhf(lA0[0], lA0[1]) : pkhf(lA0[2], lA0[3]);
        aA1 = (tg == 0) ? pkhf(hA1[0], hA1[1]) : (tg == 1) ? pkhf(hA1[2], hA1[3])
            : (tg == 2) ? pkhf(lA1[0], lA1[1]) : pkhf(lA1[2], lA1[3]);
        aB0 = (tg == 0) ? pkhf(hB0[0], hB0[1]) : (tg == 1) ? pkhf(hB0[2], hB0[3])
            : (tg == 2) ? pkhf(lB0[0], lB0[1]) : pkhf(lB0[2], lB0[3]);
        aB1 = (tg == 0) ? pkhf(hB1[0], hB1[1]) : (tg == 1) ? pkhf(hB1[2], hB1[3])
            : (tg == 2) ? pkhf(lB1[0], lB1[1]) : pkhf(lB1[2], lB1[3]);
    }

    const float4* kp = (const float4*)g_k + (kvoff >> 2) + (size_t)(n * HEADS + h) * M;
    const float4* vp = (const float4*)g_v + (kvoff >> 2) + (size_t)(n * HEADS + h) * M;

    float oA0 = 0.f, oA1 = 0.f, oA2 = 0.f, oA3 = 0.f;
    float oB0 = 0.f, oB1 = 0.f, oB2 = 0.f, oB3 = 0.f;
    u32 skb0 = smem_u32(s_k), svb0 = smem_u32(s_v);
    int nch = (M + 127) >> 7;
    const float4 FZ = make_float4(0.f, 0.f, 0.f, 0.f);

    // prologue: stage chunk 0
    {
        float4 kk = (tid < M) ? kp[tid] : FZ;
        s_k[0][tid] = make_uint2(pkhf(kk.x, kk.y), pkhf(kk.z, kk.w));
        if (tid < 64) {
            int m0 = 2 * tid, m1 = m0 + 1;
            float4 v0 = (m0 < M) ? vp[m0] : FZ;
            float4 v1 = (m1 < M) ? vp[m1] : FZ;
            float one0 = (m0 < M) ? 1.f : 0.f, one1 = (m1 < M) ? 1.f : 0.f;
            float dsi0 = (m0 >= L && m0 < M) ? 1.f : 0.f;
            float dsi1 = (m1 >= L && m1 < M) ? 1.f : 0.f;
            s_v[0][2 * tid]     = make_uint4(pkhf(v0.x, v1.x), pkhf(v0.y, v1.y),
                                             pkhf(v0.z, v1.z), pkhf(v0.w, v1.w));
            s_v[0][2 * tid + 1] = make_uint4(pkhf(one0, one1), pkhf(dsi0, dsi1), 0u, 0u);
        }
    }
    __syncthreads();

    int buf = 0;
    for (int t = 0; t < nch; t++) {
        bool pf = (t + 1 < nch);
        float4 kk = FZ, v0 = FZ, v1 = FZ;
        int nb_base = t * 128 + 128;
        if (pf) {
            int m = nb_base + tid;
            if (m < M) kk = kp[m];
            if (tid < 64) {
                int m0 = nb_base + 2 * tid;
                if (m0 < M)     v0 = vp[m0];
                if (m0 + 1 < M) v1 = vp[m0 + 1];
            }
        }

        u32 skb = skb0 + (u32)buf * 1024;
        u32 svb = svb0 + (u32)buf * 2048;
#pragma unroll
        for (int blk = 0; blk < 16; blk++) {
            u32 b0;
            u32 addr = skb + ((u32)(blk * 8 + g) << 3) + ((u32)(tg & 1) << 2);
            asm("ld.shared.u32 %0,[%1];" : "=r"(b0) : "r"(addr));
            u32 vb;
            u32 vaddr = svb + ((u32)((blk * 4 + tg) * 8 + g) << 2);
            asm("ld.shared.u32 %0,[%1];" : "=r"(vb) : "r"(vaddr));

            float cA0, cA1, cA2, cA3, cB0, cB1, cB2, cB3;
            asm("mma.sync.aligned.m16n8k8.row.col.f32.f16.f16.f32 "
                "{%0,%1,%2,%3},{%4,%5},{%6},{%7,%7,%7,%7};"
                : "=f"(cA0), "=f"(cA1), "=f"(cA2), "=f"(cA3)
                : "r"(aA0), "r"(aA1), "r"(b0), "f"(0.f));
            asm("mma.sync.aligned.m16n8k8.row.col.f32.f16.f16.f32 "
                "{%0,%1,%2,%3},{%4,%5},{%6},{%7,%7,%7,%7};"
                : "=f"(cB0), "=f"(cB1), "=f"(cB2), "=f"(cB3)
                : "r"(aB0), "r"(aB1), "r"(b0), "f"(0.f));

            u32 pA0 = pkhf(cA0, cA1), pA1 = pkhf(cA2, cA3);
            u32 pB0 = pkhf(cB0, cB1), pB1 = pkhf(cB2, cB3);
            u32 wA0, wA1, wB0, wB1;
            asm("ex2.approx.f16x2 %0,%1;" : "=r"(wA0) : "r"(pA0));
            asm("ex2.approx.f16x2 %0,%1;" : "=r"(wA1) : "r"(pA1));
            asm("ex2.approx.f16x2 %0,%1;" : "=r"(wB0) : "r"(pB0));
            asm("ex2.approx.f16x2 %0,%1;" : "=r"(wB1) : "r"(pB1));

            asm("mma.sync.aligned.m16n8k8.row.col.f32.f16.f16.f32 "
                "{%0,%1,%2,%3},{%4,%5},{%6},{%0,%1,%2,%3};"
                : "+f"(oA0), "+f"(oA1), "+f"(oA2), "+f"(oA3)
                : "r"(wA0), "r"(wA1), "r"(vb));
            asm("mma.sync.aligned.m16n8k8.row.col.f32.f16.f16.f32 "
                "{%0,%1,%2,%3},{%4,%5},{%6},{%0,%1,%2,%3};"
                : "+f"(oB0), "+f"(oB1), "+f"(oB2), "+f"(oB3)
                : "r"(wB0), "r"(wB1), "r"(vb));
        }

        if (pf) {
            int nb = buf ^ 1;
            s_k[nb][tid] = make_uint2(pkhf(kk.x, kk.y), pkhf(kk.z, kk.w));
            if (tid < 64) {
                int m0 = nb_base + 2 * tid, m1 = m0 + 1;
                float one0 = (m0 < M) ? 1.f : 0.f, one1 = (m1 < M) ? 1.f : 0.f;
                float dsi0 = (m0 >= L && m0 < M) ? 1.f : 0.f;
                float dsi1 = (m1 >= L && m1 < M) ? 1.f : 0.f;
                s_v[nb][2 * tid]     = make_uint4(pkhf(v0.x, v1.x), pkhf(v0.y, v1.y),
                                                  pkhf(v0.z, v1.z), pkhf(v0.w, v1.w));
                s_v[nb][2 * tid + 1] = make_uint4(pkhf(one0, one1), pkhf(dsi0, dsi1), 0u, 0u);
            }
            __syncthreads();
        }
        buf ^= 1;
    }

    // ---- epilogue: per-tile normalization + store; den/ds on tg==2 threads ----
    u32 full = 0xffffffffu;
    int src = (lane & 0x1c) | 2;
    float denA_lo = __shfl_sync(full, oA0, src);
    float denA_hi = __shfl_sync(full, oA2, src);
    float denB_lo = __shfl_sync(full, oB0, src);
    float denB_hi = __shfl_sync(full, oB2, src);
    if (tg < 2) {
        int d0 = tg * 2, d1 = tg * 2 + 1;
        float rl = 1.0f / denA_lo, rh = 1.0f / denA_hi;
        g_attn[qbase + (size_t)d0 * L + qA]     = oA0 * rl;
        g_attn[qbase + (size_t)d1 * L + qA]     = oA1 * rl;
        g_attn[qbase + (size_t)d0 * L + qA + 8] = oA2 * rh;
        g_attn[qbase + (size_t)d1 * L + qA + 8] = oA3 * rh;
        if (tileB) {
            rl = 1.0f / denB_lo; rh = 1.0f / denB_hi;
            g_attn[qbase + (size_t)d0 * L + qB]     = oB0 * rl;
            g_attn[qbase + (size_t)d1 * L + qB]     = oB1 * rl;
            g_attn[qbase + (size_t)d0 * L + qB + 8] = oB2 * rh;
            g_attn[qbase + (size_t)d1 * L + qB + 8] = oB3 * rh;
        }
    }
    float contrib = 0.f;
    if (tg == 2) {
        contrib = oA1 / oA0 + oA3 / oA2;
        if (tileB) contrib += oB1 / oB0 + oB3 / oB2;
    }
#pragma unroll
    for (int off = 16; off > 0; off >>= 1) contrib += __shfl_down_sync(full, contrib, off);
    if (lane == 0) s_red[wid] = contrib;
    __syncthreads();
    if (tid == 0)
        atomicAdd(&dsout[lvl * 2 + n], (s_red[0] + s_red[1] + s_red[2] + s_red[3]) * inv_hl);
}

// ---------------- launch ----------------
extern "C" void kernel_launch(void* const* d_in, const int* in_sizes, int n_in,
                              void* d_out, int out_size) {
    const float* sp[4]; const float* iv[4]; const float* dd[4];
    for (int i = 0; i < 4; i++) {
        sp[i] = (const float*)d_in[i];
        iv[i] = (const float*)d_in[4 + i];
        dd[i] = (const float*)d_in[8 + i];
    }
    const float* Wq  = (const float*)d_in[12]; const float* bq  = (const float*)d_in[13];
    const float* Wk  = (const float*)d_in[14]; const float* bk  = (const float*)d_in[15];
    const float* Wv  = (const float*)d_in[16]; const float* bv  = (const float*)d_in[17];
    const float* Wo  = (const float*)d_in[18]; const float* bo  = (const float*)d_in[19];
    const float* Wdsk = (const float*)d_in[20]; const float* bdsk = (const float*)d_in[21];
    const float* Wdsv = (const float*)d_in[22]; const float* bdsv = (const float*)d_in[23];
    const float* gate = (const float*)d_in[24];
    float* out = (float*)d_out;

    static const int Lt[4]    = {4096, 1024, 256, 64};
    static const int qoff[4]  = {0, 2097152, 2621440, 2752512};
    static const int kvoff[4] = {0, 2113536, 2654208, 2801664};
    float* dsout = out + (out_size - 8);

    pooled_kernel<<<dim3(256, 2, 4), 256>>>(dd[0], dd[1], dd[2], dd[3], dsout);
    token_kernel<<<dim3(1024, 2, 8), 256>>>(Wdsk, bdsk, Wdsv, bdsv, gate);

    for (int lv = 0; lv < 4; lv++) {
        int L = Lt[lv], M = L + 32;
        gemm_qkv<<<dim3(L / 64, 12, 2), 128>>>(Wq + lv * 65536, Wk + lv * 65536,
                                               Wv + lv * 65536, bq + lv * 256,
                                               bk + lv * 256, bv + lv * 256,
                                               sp[lv], iv[lv], L, M, qoff[lv], kvoff[lv]);
        int gx = (L + 127) / 128;
        attn_mma<<<dim3(gx, HEADS, 2), 128>>>(qoff[lv], kvoff[lv], L, M,
                                              dsout, 1.0f / (64.0f * (float)L), lv);
    }
    for (int lv = 0; lv < 4; lv++) {
        int L = Lt[lv];
        gemm_o<<<dim3(L / 64, 4, 2), 128>>>(Wo + lv * 65536, bo + lv * 256,
                                            sp[lv], out, L, qoff[lv]);
    }
}

// round 15
// speedup vs baseline: 3.0846x; 1.0575x over previous
#include <cuda_runtime.h>
#include <cuda_bf16.h>
#include <cuda_fp16.h>

#define CC    256
#define HEADS 64
#define HD    4
#define TT    32

typedef unsigned long long u64;
typedef unsigned int u32;

__device__ __align__(16) float g_q[2785280];      // (N,C,L) per level
__device__ __align__(16) float g_k[2850816];      // (n,h,m,4) per level
__device__ __align__(16) float g_v[2850816];
__device__ __align__(16) float g_attn[2785280];
__device__ float g_pooled[4 * 2 * CC];

__constant__ int c_L[4]     = {4096, 1024, 256, 64};
__constant__ int c_kvoff[4] = {0, 2113536, 2654208, 2801664};

__device__ __forceinline__ u32 pkhf(float lo, float hi) {   // f16x2 {lo,hi}
    u32 r; asm("cvt.rn.f16x2.f32 %0, %1, %2;" : "=r"(r) : "f"(hi), "f"(lo)); return r;
}
__device__ __forceinline__ float tf32f(float x) {
    u32 r; asm("cvt.rna.tf32.f32 %0,%1;" : "=r"(r) : "f"(x));
    return __uint_as_float(r);
}
__device__ __forceinline__ u32 smem_u32(const void* p) {
    u32 a; asm("{.reg .u64 t; cvta.to.shared.u64 t, %1; cvt.u32.u64 %0, t;}" : "=r"(a) : "l"(p));
    return a;
}

// ---------------- pooled mean (also zeroes ds output) ----------------
__global__ void pooled_kernel(const float* __restrict__ d0, const float* __restrict__ d1,
                              const float* __restrict__ d2, const float* __restrict__ d3,
                              float* __restrict__ dsout) {
    __shared__ float red[256];
    int lvl = blockIdx.z, n = blockIdx.y, c = blockIdx.x;
    if (lvl == 0 && n == 0 && c == 0 && threadIdx.x < 8) dsout[threadIdx.x] = 0.f;
    const float* dp = (lvl == 0) ? d0 : (lvl == 1) ? d1 : (lvl == 2) ? d2 : d3;
    int L = c_L[lvl];
    const float* p = dp + (size_t)(n * CC + c) * L;
    float s = 0.f;
    for (int i = threadIdx.x; i < L; i += blockDim.x) s += p[i];
    red[threadIdx.x] = s;
    __syncthreads();
    for (int st = blockDim.x >> 1; st > 0; st >>= 1) {
        if (threadIdx.x < st) red[threadIdx.x] += red[threadIdx.x + st];
        __syncthreads();
    }
    if (threadIdx.x == 0) g_pooled[(lvl * 2 + n) * CC + c] = red[0] / (float)L;
}

// ---------------- ds token projections -> tail of k/v ----------------
__global__ void token_kernel(const float* __restrict__ Wdsk, const float* __restrict__ bdsk,
                             const float* __restrict__ Wdsv, const float* __restrict__ bdsv,
                             const float* __restrict__ gate) {
    int kind = blockIdx.y;
    int lvl = blockIdx.z >> 1, n = blockIdx.z & 1;
    int warp = threadIdx.x >> 5, lane = threadIdx.x & 31;
    int j = blockIdx.x * 8 + warp;
    const float* Wr = (kind ? Wdsv : Wdsk) + (size_t)(lvl * 8192 + j) * 256;
    const float* pl = g_pooled + (lvl * 2 + n) * CC;
    float s = 0.f;
#pragma unroll
    for (int c = lane; c < 256; c += 32) s += Wr[c] * pl[c];
#pragma unroll
    for (int off = 16; off > 0; off >>= 1) s += __shfl_down_sync(0xffffffffu, s, off);
    if (lane == 0) {
        s += (kind ? bdsv : bdsk)[lvl * 8192 + j];
        if (kind) s *= 1.0f / (1.0f + __expf(-gate[lvl]));
        int h = j >> 7, d = (j >> 5) & 3, t = j & 31;
        int L = c_L[lvl], M = L + TT;
        size_t idx = (size_t)c_kvoff[lvl] + ((size_t)((n * HEADS + h) * M) + (L + t)) * HD + d;
        if (kind) g_v[idx] = s; else g_k[idx] = s;
    }
}

// ---------------- shared tf32 GEMM mainloop (double-buffered) ----------------
struct GemmCoords { int wrow[2], wk[2], xrow[2], xcc[2]; };

__device__ __forceinline__ void gemm_mainloop(const float* __restrict__ W,
                                              const float* __restrict__ X,
                                              int L, int o0, int l0,
                                              float (&As)[2][16][72], float (&Bs)[2][16][72],
                                              float (&acc)[8][4],
                                              int tid, int wid, int g, int tg) {
    GemmCoords cd;
#pragma unroll
    for (int r = 0; r < 2; r++) {
        int idx = tid + r * 128;
        cd.wrow[r] = idx >> 2;  cd.wk[r]  = (idx & 3) << 2;
        cd.xrow[r] = idx >> 4;  cd.xcc[r] = (idx & 15) << 2;
    }
    float4 wr[2], xr[2];
#pragma unroll
    for (int r = 0; r < 2; r++) {
        wr[r] = *(const float4*)&W[(size_t)(o0 + cd.wrow[r]) * 256 + cd.wk[r]];
        xr[r] = *(const float4*)&X[(size_t)cd.xrow[r] * L + l0 + cd.xcc[r]];
    }
#pragma unroll
    for (int r = 0; r < 2; r++) {
        As[0][cd.wk[r]][cd.wrow[r]]     = tf32f(wr[r].x);
        As[0][cd.wk[r] + 1][cd.wrow[r]] = tf32f(wr[r].y);
        As[0][cd.wk[r] + 2][cd.wrow[r]] = tf32f(wr[r].z);
        As[0][cd.wk[r] + 3][cd.wrow[r]] = tf32f(wr[r].w);
        Bs[0][cd.xrow[r]][cd.xcc[r]]     = tf32f(xr[r].x);
        Bs[0][cd.xrow[r]][cd.xcc[r] + 1] = tf32f(xr[r].y);
        Bs[0][cd.xrow[r]][cd.xcc[r] + 2] = tf32f(xr[r].z);
        Bs[0][cd.xrow[r]][cd.xcc[r] + 3] = tf32f(xr[r].w);
    }
    __syncthreads();

    int buf = 0;
    for (int k0 = 0; k0 < 256; k0 += 16) {
        bool pf = (k0 + 16 < 256);
        if (pf) {
#pragma unroll
            for (int r = 0; r < 2; r++) {
                wr[r] = *(const float4*)&W[(size_t)(o0 + cd.wrow[r]) * 256 + k0 + 16 + cd.wk[r]];
                xr[r] = *(const float4*)&X[(size_t)(k0 + 16 + cd.xrow[r]) * L + l0 + cd.xcc[r]];
            }
        }
#pragma unroll
        for (int ks = 0; ks < 2; ks++) {
            int kb = ks * 8;
            u32 a0 = __float_as_uint(As[buf][kb + tg][wid * 16 + g]);
            u32 a1 = __float_as_uint(As[buf][kb + tg][wid * 16 + g + 8]);
            u32 a2 = __float_as_uint(As[buf][kb + tg + 4][wid * 16 + g]);
            u32 a3 = __float_as_uint(As[buf][kb + tg + 4][wid * 16 + g + 8]);
#pragma unroll
            for (int nt = 0; nt < 8; nt++) {
                u32 b0 = __float_as_uint(Bs[buf][kb + tg][nt * 8 + g]);
                u32 b1 = __float_as_uint(Bs[buf][kb + tg + 4][nt * 8 + g]);
                asm("mma.sync.aligned.m16n8k8.row.col.f32.tf32.tf32.f32 "
                    "{%0,%1,%2,%3},{%4,%5,%6,%7},{%8,%9},{%0,%1,%2,%3};"
                    : "+f"(acc[nt][0]), "+f"(acc[nt][1]), "+f"(acc[nt][2]), "+f"(acc[nt][3])
                    : "r"(a0), "r"(a1), "r"(a2), "r"(a3), "r"(b0), "r"(b1));
            }
        }
        if (pf) {
            int nb = buf ^ 1;
#pragma unroll
            for (int r = 0; r < 2; r++) {
                As[nb][cd.wk[r]][cd.wrow[r]]     = tf32f(wr[r].x);
                As[nb][cd.wk[r] + 1][cd.wrow[r]] = tf32f(wr[r].y);
                As[nb][cd.wk[r] + 2][cd.wrow[r]] = tf32f(wr[r].z);
                As[nb][cd.wk[r] + 3][cd.wrow[r]] = tf32f(wr[r].w);
                Bs[nb][cd.xrow[r]][cd.xcc[r]]     = tf32f(xr[r].x);
                Bs[nb][cd.xrow[r]][cd.xcc[r] + 1] = tf32f(xr[r].y);
                Bs[nb][cd.xrow[r]][cd.xcc[r] + 2] = tf32f(xr[r].z);
                Bs[nb][cd.xrow[r]][cd.xcc[r] + 3] = tf32f(xr[r].w);
            }
            __syncthreads();
        }
        buf ^= 1;
    }
}

// ---------------- fused q/k/v GEMM: blockIdx.y = type*4 + row-tile ----------------
__global__ void __launch_bounds__(128) gemm_qkv(const float* __restrict__ Wq,
                                                const float* __restrict__ Wk,
                                                const float* __restrict__ Wv,
                                                const float* __restrict__ bq,
                                                const float* __restrict__ bk,
                                                const float* __restrict__ bv,
                                                const float* __restrict__ sp,
                                                const float* __restrict__ iv,
                                                int L, int M, int offq, int offkv) {
    __shared__ float As[2][16][72];
    __shared__ float Bs[2][16][72];
    int n = blockIdx.z;
    int type = blockIdx.y >> 2;
    int o0 = (blockIdx.y & 3) * 64, l0 = blockIdx.x * 64;
    const float* W = (type == 0) ? Wq : (type == 1) ? Wk : Wv;
    const float* bias = (type == 0) ? bq : (type == 1) ? bk : bv;
    const float* X = ((type == 0) ? sp : iv) + (size_t)n * CC * L;
    int tid = threadIdx.x, wid = tid >> 5, lane = tid & 31;
    int g = lane >> 2, tg = lane & 3;

    float acc[8][4];
#pragma unroll
    for (int i = 0; i < 8; i++)
#pragma unroll
        for (int j = 0; j < 4; j++) acc[i][j] = 0.f;

    gemm_mainloop(W, X, L, o0, l0, As, Bs, acc, tid, wid, g, tg);

    int r0 = o0 + wid * 16 + g, r1 = r0 + 8;
    float b0v = bias[r0], b1v = bias[r1];
#pragma unroll
    for (int nt = 0; nt < 8; nt++) {
        int l = l0 + nt * 8 + 2 * tg;
        float v00 = acc[nt][0] + b0v, v01 = acc[nt][1] + b0v;
        float v10 = acc[nt][2] + b1v, v11 = acc[nt][3] + b1v;
        if (type == 0) {
            g_q[offq + (size_t)(n * CC + r0) * L + l]     = v00;
            g_q[offq + (size_t)(n * CC + r0) * L + l + 1] = v01;
            g_q[offq + (size_t)(n * CC + r1) * L + l]     = v10;
            g_q[offq + (size_t)(n * CC + r1) * L + l + 1] = v11;
        } else {
            float* dst = (type == 1) ? g_k : g_v;
            size_t i00 = (size_t)offkv + ((size_t)((n * HEADS + (r0 >> 2)) * M) + l) * HD + (r0 & 3);
            size_t i10 = (size_t)offkv + ((size_t)((n * HEADS + (r1 >> 2)) * M) + l) * HD + (r1 & 3);
            dst[i00] = v00; dst[i00 + HD] = v01;
            dst[i10] = v10; dst[i10 + HD] = v11;
        }
    }
}

// ---------------- output GEMM (+residual) ----------------
__global__ void __launch_bounds__(128) gemm_o(const float* __restrict__ W,
                                              const float* __restrict__ bias,
                                              const float* __restrict__ res,
                                              float* __restrict__ dext,
                                              int L, int off) {
    __shared__ float As[2][16][72];
    __shared__ float Bs[2][16][72];
    int n = blockIdx.z;
    int o0 = blockIdx.y * 64, l0 = blockIdx.x * 64;
    const float* X = g_attn + off + (size_t)n * CC * L;
    int tid = threadIdx.x, wid = tid >> 5, lane = tid & 31;
    int g = lane >> 2, tg = lane & 3;

    float acc[8][4];
#pragma unroll
    for (int i = 0; i < 8; i++)
#pragma unroll
        for (int j = 0; j < 4; j++) acc[i][j] = 0.f;

    gemm_mainloop(W, X, L, o0, l0, As, Bs, acc, tid, wid, g, tg);

    int r0 = o0 + wid * 16 + g, r1 = r0 + 8;
    float b0v = bias[r0], b1v = bias[r1];
#pragma unroll
    for (int nt = 0; nt < 8; nt++) {
        int l = l0 + nt * 8 + 2 * tg;
        size_t b = (size_t)(n * CC + r0) * L + l;
        size_t c = (size_t)(n * CC + r1) * L + l;
        dext[off + b]     = acc[nt][0] + b0v + res[b];
        dext[off + b + 1] = acc[nt][1] + b0v + res[b + 1];
        dext[off + c]     = acc[nt][2] + b1v + res[c];
        dext[off + c + 1] = acc[nt][3] + b1v + res[c + 1];
    }
}

// ---------------- HMMA attention: 2 q-tiles/CTA, k16 O-mma (16 keys/accumulate) -----
// Per 16-key double-block per tile: 2 S-mma(k8) + 1 O-mma(k16) = 3 MMAs.
// S-mma A rows = [q_hi(4) | q_lo(4)] f16 split; weights from the two 8-key
// S outputs form exactly the a0..a3 of the k16 O-mma A fragment; the two V
// registers are b0 (keys 0-7) and b1 (keys 8-15).
// V cols = [v0..v3, 1, ds-indicator, 0, 0] f16; den from ones column; OOB rows zero.
__global__ void __launch_bounds__(128) attn_mma(int qoff, int kvoff, int L, int M,
                                                float* __restrict__ dsout,
                                                float inv_hl, int lvl) {
    __shared__ __align__(16) uint2 s_k[2][128];   // per key: {k01, k23} f16x2
    __shared__ __align__(16) uint4 s_v[2][128];   // per pair: [c01..c31],[1,ds,0,0]
    __shared__ float s_red[4];

    int tid = threadIdx.x, wid = tid >> 5, lane = tid & 31;
    int g = lane >> 2, tg = lane & 3;
    int n = blockIdx.z, h = blockIdx.y;
    int qA = blockIdx.x * 128 + wid * 16 + g;        // tile A rows qA, qA+8
    int qB = qA + 64;                                // tile B rows qB, qB+8
    bool tileB = (blockIdx.x * 128 + 64) < L;

    const float SCALE = 0.5f * 1.4426950408889634f;
    size_t qbase = (size_t)qoff + ((size_t)(n * CC) + h * HD) * L;

    // Build S-mma A fragments for both tiles
    u32 aA0, aA1, aB0, aB1;
    {
        int qBs = tileB ? qB : qA;   // safe load index
        float hA0[4], lA0[4], hA1[4], lA1[4], hB0[4], lB0[4], hB1[4], lB1[4];
#pragma unroll
        for (int d = 0; d < 4; d++) {
            float v = g_q[qbase + (size_t)d * L + qA] * SCALE;
            float hf = __half2float(__float2half(v));
            hA0[d] = hf; lA0[d] = v - hf;
            v = g_q[qbase + (size_t)d * L + qA + 8] * SCALE;
            hf = __half2float(__float2half(v));
            hA1[d] = hf; lA1[d] = v - hf;
            v = g_q[qbase + (size_t)d * L + qBs] * SCALE;
            hf = __half2float(__float2half(v));
            hB0[d] = hf; lB0[d] = v - hf;
            v = g_q[qbase + (size_t)d * L + qBs + 8] * SCALE;
            hf = __half2float(__float2half(v));
            hB1[d] = hf; lB1[d] = v - hf;
        }
        aA0 = (tg == 0) ? pkhf(hA0[0], hA0[1]) : (tg == 1) ? pkhf(hA0[2], hA0[3])
            : (tg == 2) ? pkhf(lA0[0], lA0[1]) : pkhf(lA0[2], lA0[3]);
        aA1 = (tg == 0) ? pkhf(hA1[0], hA1[1]) : (tg == 1) ? pkhf(hA1[2], hA1[3])
            : (tg == 2) ? pkhf(lA1[0], lA1[1]) : pkhf(lA1[2], lA1[3]);
        aB0 = (tg == 0) ? pkhf(hB0[0], hB0[1]) : (tg == 1) ? pkhf(hB0[2], hB0[3])
            : (tg == 2) ? pkhf(lB0[0], lB0[1]) : pkhf(lB0[2], lB0[3]);
        aB1 = (tg == 0) ? pkhf(hB1[0], hB1[1]) : (tg == 1) ? pkhf(hB1[2], hB1[3])
            : (tg == 2) ? pkhf(lB1[0], lB1[1]) : pkhf(lB1[2], lB1[3]);
    }

    const float4* kp = (const float4*)g_k + (kvoff >> 2) + (size_t)(n * HEADS + h) * M;
    const float4* vp = (const float4*)g_v + (kvoff >> 2) + (size_t)(n * HEADS + h) * M;

    float oA0 = 0.f, oA1 = 0.f, oA2 = 0.f, oA3 = 0.f;
    float oB0 = 0.f, oB1 = 0.f, oB2 = 0.f, oB3 = 0.f;
    u32 skb0 = smem_u32(s_k), svb0 = smem_u32(s_v);
    int nch = (M + 127) >> 7;
    const float4 FZ = make_float4(0.f, 0.f, 0.f, 0.f);

    // prologue: stage chunk 0
    {
        float4 kk = (tid < M) ? kp[tid] : FZ;
        s_k[0][tid] = make_uint2(pkhf(kk.x, kk.y), pkhf(kk.z, kk.w));
        if (tid < 64) {
            int m0 = 2 * tid, m1 = m0 + 1;
            float4 v0 = (m0 < M) ? vp[m0] : FZ;
            float4 v1 = (m1 < M) ? vp[m1] : FZ;
            float one0 = (m0 < M) ? 1.f : 0.f, one1 = (m1 < M) ? 1.f : 0.f;
            float dsi0 = (m0 >= L && m0 < M) ? 1.f : 0.f;
            float dsi1 = (m1 >= L && m1 < M) ? 1.f : 0.f;
            s_v[0][2 * tid]     = make_uint4(pkhf(v0.x, v1.x), pkhf(v0.y, v1.y),
                                             pkhf(v0.z, v1.z), pkhf(v0.w, v1.w));
            s_v[0][2 * tid + 1] = make_uint4(pkhf(one0, one1), pkhf(dsi0, dsi1), 0u, 0u);
        }
    }
    __syncthreads();

    int buf = 0;
    for (int t = 0; t < nch; t++) {
        bool pf = (t + 1 < nch);
        float4 kk = FZ, v0 = FZ, v1 = FZ;
        int nb_base = t * 128 + 128;
        if (pf) {
            int m = nb_base + tid;
            if (m < M) kk = kp[m];
            if (tid < 64) {
                int m0 = nb_base + 2 * tid;
                if (m0 < M)     v0 = vp[m0];
                if (m0 + 1 < M) v1 = vp[m0 + 1];
            }
        }

        u32 skb = skb0 + (u32)buf * 1024;
        u32 svb = svb0 + (u32)buf * 2048;
#pragma unroll
        for (int blk = 0; blk < 8; blk++) {      // 16 keys per iteration
            // K fragments for the two 8-key halves
            u32 k0f, k1f;
            u32 ka0 = skb + ((u32)(blk * 16 + g) << 3) + ((u32)(tg & 1) << 2);
            u32 ka1 = ka0 + (8u << 3);
            asm("ld.shared.u32 %0,[%1];" : "=r"(k0f) : "r"(ka0));
            asm("ld.shared.u32 %0,[%1];" : "=r"(k1f) : "r"(ka1));
            // V fragments: b0 = keys 0-7 half, b1 = keys 8-15 half
            u32 vb0, vb1;
            u32 va0 = svb + ((u32)(((blk * 2) * 4 + tg) * 8 + g) << 2);
            u32 va1 = va0 + (32u << 2);
            asm("ld.shared.u32 %0,[%1];" : "=r"(vb0) : "r"(va0));
            asm("ld.shared.u32 %0,[%1];" : "=r"(vb1) : "r"(va1));

            // Tile A: two S-mmas, exp, one k16 O-mma
            float c0, c1, c2, c3, d0, d1, d2, d3;
            asm("mma.sync.aligned.m16n8k8.row.col.f32.f16.f16.f32 "
                "{%0,%1,%2,%3},{%4,%5},{%6},{%7,%7,%7,%7};"
                : "=f"(c0), "=f"(c1), "=f"(c2), "=f"(c3)
                : "r"(aA0), "r"(aA1), "r"(k0f), "f"(0.f));
            asm("mma.sync.aligned.m16n8k8.row.col.f32.f16.f16.f32 "
                "{%0,%1,%2,%3},{%4,%5},{%6},{%7,%7,%7,%7};"
                : "=f"(d0), "=f"(d1), "=f"(d2), "=f"(d3)
                : "r"(aA0), "r"(aA1), "r"(k1f), "f"(0.f));
            u32 w0, w1, w2, w3;
            {
                u32 p0 = pkhf(c0, c1), p1 = pkhf(c2, c3);
                u32 p2 = pkhf(d0, d1), p3 = pkhf(d2, d3);
                asm("ex2.approx.f16x2 %0,%1;" : "=r"(w0) : "r"(p0));
                asm("ex2.approx.f16x2 %0,%1;" : "=r"(w1) : "r"(p1));
                asm("ex2.approx.f16x2 %0,%1;" : "=r"(w2) : "r"(p2));
                asm("ex2.approx.f16x2 %0,%1;" : "=r"(w3) : "r"(p3));
            }
            asm("mma.sync.aligned.m16n8k16.row.col.f32.f16.f16.f32 "
                "{%0,%1,%2,%3},{%4,%5,%6,%7},{%8,%9},{%0,%1,%2,%3};"
                : "+f"(oA0), "+f"(oA1), "+f"(oA2), "+f"(oA3)
                : "r"(w0), "r"(w1), "r"(w2), "r"(w3), "r"(vb0), "r"(vb1));

            // Tile B: same
            asm("mma.sync.aligned.m16n8k8.row.col.f32.f16.f16.f32 "
                "{%0,%1,%2,%3},{%4,%5},{%6},{%7,%7,%7,%7};"
                : "=f"(c0), "=f"(c1), "=f"(c2), "=f"(c3)
                : "r"(aB0), "r"(aB1), "r"(k0f), "f"(0.f));
            asm("mma.sync.aligned.m16n8k8.row.col.f32.f16.f16.f32 "
                "{%0,%1,%2,%3},{%4,%5},{%6},{%7,%7,%7,%7};"
                : "=f"(d0), "=f"(d1), "=f"(d2), "=f"(d3)
                : "r"(aB0), "r"(aB1), "r"(k1f), "f"(0.f));
            {
                u32 p0 = pkhf(c0, c1), p1 = pkhf(c2, c3);
                u32 p2 = pkhf(d0, d1), p3 = pkhf(d2, d3);
                asm("ex2.approx.f16x2 %0,%1;" : "=r"(w0) : "r"(p0));
                asm("ex2.approx.f16x2 %0,%1;" : "=r"(w1) : "r"(p1));
                asm("ex2.approx.f16x2 %0,%1;" : "=r"(w2) : "r"(p2));
                asm("ex2.approx.f16x2 %0,%1;" : "=r"(w3) : "r"(p3));
            }
            asm("mma.sync.aligned.m16n8k16.row.col.f32.f16.f16.f32 "
                "{%0,%1,%2,%3},{%4,%5,%6,%7},{%8,%9},{%0,%1,%2,%3};"
                : "+f"(oB0), "+f"(oB1), "+f"(oB2), "+f"(oB3)
                : "r"(w0), "r"(w1), "r"(w2), "r"(w3), "r"(vb0), "r"(vb1));
        }

        if (pf) {
            int nb = buf ^ 1;
            s_k[nb][tid] = make_uint2(pkhf(kk.x, kk.y), pkhf(kk.z, kk.w));
            if (tid < 64) {
                int m0 = nb_base + 2 * tid, m1 = m0 + 1;
                float one0 = (m0 < M) ? 1.f : 0.f, one1 = (m1 < M) ? 1.f : 0.f;
                float dsi0 = (m0 >= L && m0 < M) ? 1.f : 0.f;
                float dsi1 = (m1 >= L && m1 < M) ? 1.f : 0.f;
                s_v[nb][2 * tid]     = make_uint4(pkhf(v0.x, v1.x), pkhf(v0.y, v1.y),
                                                  pkhf(v0.z, v1.z), pkhf(v0.w, v1.w));
                s_v[nb][2 * tid + 1] = make_uint4(pkhf(one0, one1), pkhf(dsi0, dsi1), 0u, 0u);
            }
            __syncthreads();
        }
        buf ^= 1;
    }

    // ---- epilogue: per-tile normalization + store; den/ds on tg==2 threads ----
    u32 full = 0xffffffffu;
    int src = (lane & 0x1c) | 2;
    float denA_lo = __shfl_sync(full, oA0, src);
    float denA_hi = __shfl_sync(full, oA2, src);
    float denB_lo = __shfl_sync(full, oB0, src);
    float denB_hi = __shfl_sync(full, oB2, src);
    if (tg < 2) {
        int d0 = tg * 2, d1 = tg * 2 + 1;
        float rl = 1.0f / denA_lo, rh = 1.0f / denA_hi;
        g_attn[qbase + (size_t)d0 * L + qA]     = oA0 * rl;
        g_attn[qbase + (size_t)d1 * L + qA]     = oA1 * rl;
        g_attn[qbase + (size_t)d0 * L + qA + 8] = oA2 * rh;
        g_attn[qbase + (size_t)d1 * L + qA + 8] = oA3 * rh;
        if (tileB) {
            rl = 1.0f / denB_lo; rh = 1.0f / denB_hi;
            g_attn[qbase + (size_t)d0 * L + qB]     = oB0 * rl;
            g_attn[qbase + (size_t)d1 * L + qB]     = oB1 * rl;
            g_attn[qbase + (size_t)d0 * L + qB + 8] = oB2 * rh;
            g_attn[qbase + (size_t)d1 * L + qB + 8] = oB3 * rh;
        }
    }
    float contrib = 0.f;
    if (tg == 2) {
        contrib = oA1 / oA0 + oA3 / oA2;
        if (tileB) contrib += oB1 / oB0 + oB3 / oB2;
    }
#pragma unroll
    for (int off = 16; off > 0; off >>= 1) contrib += __shfl_down_sync(full, contrib, off);
    if (lane == 0) s_red[wid] = contrib;
    __syncthreads();
    if (tid == 0)
        atomicAdd(&dsout[lvl * 2 + n], (s_red[0] + s_red[1] + s_red[2] + s_red[3]) * inv_hl);
}

// ---------------- launch ----------------
extern "C" void kernel_launch(void* const* d_in, const int* in_sizes, int n_in,
                              void* d_out, int out_size) {
    const float* sp[4]; const float* iv[4]; const float* dd[4];
    for (int i = 0; i < 4; i++) {
        sp[i] = (const float*)d_in[i];
        iv[i] = (const float*)d_in[4 + i];
        dd[i] = (const float*)d_in[8 + i];
    }
    const float* Wq  = (const float*)d_in[12]; const float* bq  = (const float*)d_in[13];
    const float* Wk  = (const float*)d_in[14]; const float* bk  = (const float*)d_in[15];
    const float* Wv  = (const float*)d_in[16]; const float* bv  = (const float*)d_in[17];
    const float* Wo  = (const float*)d_in[18]; const float* bo  = (const float*)d_in[19];
    const float* Wdsk = (const float*)d_in[20]; const float* bdsk = (const float*)d_in[21];
    const float* Wdsv = (const float*)d_in[22]; const float* bdsv = (const float*)d_in[23];
    const float* gate = (const float*)d_in[24];
    float* out = (float*)d_out;

    static const int Lt[4]    = {4096, 1024, 256, 64};
    static const int qoff[4]  = {0, 2097152, 2621440, 2752512};
    static const int kvoff[4] = {0, 2113536, 2654208, 2801664};
    float* dsout = out + (out_size - 8);

    pooled_kernel<<<dim3(256, 2, 4), 256>>>(dd[0], dd[1], dd[2], dd[3], dsout);
    token_kernel<<<dim3(1024, 2, 8), 256>>>(Wdsk, bdsk, Wdsv, bdsv, gate);

    for (int lv = 0; lv < 4; lv++) {
        int L = Lt[lv], M = L + 32;
        gemm_qkv<<<dim3(L / 64, 12, 2), 128>>>(Wq + lv * 65536, Wk + lv * 65536,
                                               Wv + lv * 65536, bq + lv * 256,
                                               bk + lv * 256, bv + lv * 256,
                                               sp[lv], iv[lv], L, M, qoff[lv], kvoff[lv]);
        int gx = (L + 127) / 128;
        attn_mma<<<dim3(gx, HEADS, 2), 128>>>(qoff[lv], kvoff[lv], L, M,
                                              dsout, 1.0f / (64.0f * (float)L), lv);
    }
    for (int lv = 0; lv < 4; lv++) {
        int L = Lt[lv];
        gemm_o<<<dim3(L / 64, 4, 2), 128>>>(Wo + lv * 65536, bo + lv * 256,
                                            sp[lv], out, L, qoff[lv]);
    }
}

// round 16
// speedup vs baseline: 3.1461x; 1.0199x over previous
#include <cuda_runtime.h>
#include <cuda_bf16.h>
#include <cuda_fp16.h>

#define CC    256
#define HEADS 64
#define HD    4
#define TT    32

typedef unsigned long long u64;
typedef unsigned int u32;

__device__ __align__(16) float g_q[2785280];      // (N,C,L) per level
__device__ __align__(16) float g_k[2850816];      // (n,h,m,4) per level
__device__ __align__(16) float g_v[2850816];
__device__ __align__(16) float g_attn[2785280];
__device__ float g_pooled[4 * 2 * CC];

__constant__ int c_L[4]     = {4096, 1024, 256, 64};
__constant__ int c_kvoff[4] = {0, 2113536, 2654208, 2801664};

__device__ __forceinline__ u32 pkhf(float lo, float hi) {   // f16x2 {lo,hi}
    u32 r; asm("cvt.rn.f16x2.f32 %0, %1, %2;" : "=r"(r) : "f"(hi), "f"(lo)); return r;
}
__device__ __forceinline__ float tf32f(float x) {
    u32 r; asm("cvt.rna.tf32.f32 %0,%1;" : "=r"(r) : "f"(x));
    return __uint_as_float(r);
}
__device__ __forceinline__ u32 smem_u32(const void* p) {
    u32 a; asm("{.reg .u64 t; cvta.to.shared.u64 t, %1; cvt.u32.u64 %0, t;}" : "=r"(a) : "l"(p));
    return a;
}

// ---------------- pooled mean (also zeroes ds output) ----------------
__global__ void pooled_kernel(const float* __restrict__ d0, const float* __restrict__ d1,
                              const float* __restrict__ d2, const float* __restrict__ d3,
                              float* __restrict__ dsout) {
    __shared__ float red[256];
    int lvl = blockIdx.z, n = blockIdx.y, c = blockIdx.x;
    if (lvl == 0 && n == 0 && c == 0 && threadIdx.x < 8) dsout[threadIdx.x] = 0.f;
    const float* dp = (lvl == 0) ? d0 : (lvl == 1) ? d1 : (lvl == 2) ? d2 : d3;
    int L = c_L[lvl];
    const float* p = dp + (size_t)(n * CC + c) * L;
    float s = 0.f;
    for (int i = threadIdx.x; i < L; i += blockDim.x) s += p[i];
    red[threadIdx.x] = s;
    __syncthreads();
    for (int st = blockDim.x >> 1; st > 0; st >>= 1) {
        if (threadIdx.x < st) red[threadIdx.x] += red[threadIdx.x + st];
        __syncthreads();
    }
    if (threadIdx.x == 0) g_pooled[(lvl * 2 + n) * CC + c] = red[0] / (float)L;
}

// ---------------- ds token projections -> tail of k/v ----------------
__global__ void token_kernel(const float* __restrict__ Wdsk, const float* __restrict__ bdsk,
                             const float* __restrict__ Wdsv, const float* __restrict__ bdsv,
                             const float* __restrict__ gate) {
    int kind = blockIdx.y;
    int lvl = blockIdx.z >> 1, n = blockIdx.z & 1;
    int warp = threadIdx.x >> 5, lane = threadIdx.x & 31;
    int j = blockIdx.x * 8 + warp;
    const float* Wr = (kind ? Wdsv : Wdsk) + (size_t)(lvl * 8192 + j) * 256;
    const float* pl = g_pooled + (lvl * 2 + n) * CC;
    float s = 0.f;
#pragma unroll
    for (int c = lane; c < 256; c += 32) s += Wr[c] * pl[c];
#pragma unroll
    for (int off = 16; off > 0; off >>= 1) s += __shfl_down_sync(0xffffffffu, s, off);
    if (lane == 0) {
        s += (kind ? bdsv : bdsk)[lvl * 8192 + j];
        if (kind) s *= 1.0f / (1.0f + __expf(-gate[lvl]));
        int h = j >> 7, d = (j >> 5) & 3, t = j & 31;
        int L = c_L[lvl], M = L + TT;
        size_t idx = (size_t)c_kvoff[lvl] + ((size_t)((n * HEADS + h) * M) + (L + t)) * HD + d;
        if (kind) g_v[idx] = s; else g_k[idx] = s;
    }
}

// ---------------- shared tf32 GEMM mainloop (double-buffered) ----------------
struct GemmCoords { int wrow[2], wk[2], xrow[2], xcc[2]; };

__device__ __forceinline__ void gemm_mainloop(const float* __restrict__ W,
                                              const float* __restrict__ X,
                                              int L, int o0, int l0,
                                              float (&As)[2][16][72], float (&Bs)[2][16][72],
                                              float (&acc)[8][4],
                                              int tid, int wid, int g, int tg) {
    GemmCoords cd;
#pragma unroll
    for (int r = 0; r < 2; r++) {
        int idx = tid + r * 128;
        cd.wrow[r] = idx >> 2;  cd.wk[r]  = (idx & 3) << 2;
        cd.xrow[r] = idx >> 4;  cd.xcc[r] = (idx & 15) << 2;
    }
    float4 wr[2], xr[2];
#pragma unroll
    for (int r = 0; r < 2; r++) {
        wr[r] = *(const float4*)&W[(size_t)(o0 + cd.wrow[r]) * 256 + cd.wk[r]];
        xr[r] = *(const float4*)&X[(size_t)cd.xrow[r] * L + l0 + cd.xcc[r]];
    }
#pragma unroll
    for (int r = 0; r < 2; r++) {
        As[0][cd.wk[r]][cd.wrow[r]]     = tf32f(wr[r].x);
        As[0][cd.wk[r] + 1][cd.wrow[r]] = tf32f(wr[r].y);
        As[0][cd.wk[r] + 2][cd.wrow[r]] = tf32f(wr[r].z);
        As[0][cd.wk[r] + 3][cd.wrow[r]] = tf32f(wr[r].w);
        Bs[0][cd.xrow[r]][cd.xcc[r]]     = tf32f(xr[r].x);
        Bs[0][cd.xrow[r]][cd.xcc[r] + 1] = tf32f(xr[r].y);
        Bs[0][cd.xrow[r]][cd.xcc[r] + 2] = tf32f(xr[r].z);
        Bs[0][cd.xrow[r]][cd.xcc[r] + 3] = tf32f(xr[r].w);
    }
    __syncthreads();

    int buf = 0;
    for (int k0 = 0; k0 < 256; k0 += 16) {
        bool pf = (k0 + 16 < 256);
        if (pf) {
#pragma unroll
            for (int r = 0; r < 2; r++) {
                wr[r] = *(const float4*)&W[(size_t)(o0 + cd.wrow[r]) * 256 + k0 + 16 + cd.wk[r]];
                xr[r] = *(const float4*)&X[(size_t)(k0 + 16 + cd.xrow[r]) * L + l0 + cd.xcc[r]];
            }
        }
#pragma unroll
        for (int ks = 0; ks < 2; ks++) {
            int kb = ks * 8;
            u32 a0 = __float_as_uint(As[buf][kb + tg][wid * 16 + g]);
            u32 a1 = __float_as_uint(As[buf][kb + tg][wid * 16 + g + 8]);
            u32 a2 = __float_as_uint(As[buf][kb + tg + 4][wid * 16 + g]);
            u32 a3 = __float_as_uint(As[buf][kb + tg + 4][wid * 16 + g + 8]);
#pragma unroll
            for (int nt = 0; nt < 8; nt++) {
                u32 b0 = __float_as_uint(Bs[buf][kb + tg][nt * 8 + g]);
                u32 b1 = __float_as_uint(Bs[buf][kb + tg + 4][nt * 8 + g]);
                asm("mma.sync.aligned.m16n8k8.row.col.f32.tf32.tf32.f32 "
                    "{%0,%1,%2,%3},{%4,%5,%6,%7},{%8,%9},{%0,%1,%2,%3};"
                    : "+f"(acc[nt][0]), "+f"(acc[nt][1]), "+f"(acc[nt][2]), "+f"(acc[nt][3])
                    : "r"(a0), "r"(a1), "r"(a2), "r"(a3), "r"(b0), "r"(b1));
            }
        }
        if (pf) {
            int nb = buf ^ 1;
#pragma unroll
            for (int r = 0; r < 2; r++) {
                As[nb][cd.wk[r]][cd.wrow[r]]     = tf32f(wr[r].x);
                As[nb][cd.wk[r] + 1][cd.wrow[r]] = tf32f(wr[r].y);
                As[nb][cd.wk[r] + 2][cd.wrow[r]] = tf32f(wr[r].z);
                As[nb][cd.wk[r] + 3][cd.wrow[r]] = tf32f(wr[r].w);
                Bs[nb][cd.xrow[r]][cd.xcc[r]]     = tf32f(xr[r].x);
                Bs[nb][cd.xrow[r]][cd.xcc[r] + 1] = tf32f(xr[r].y);
                Bs[nb][cd.xrow[r]][cd.xcc[r] + 2] = tf32f(xr[r].z);
                Bs[nb][cd.xrow[r]][cd.xcc[r] + 3] = tf32f(xr[r].w);
            }
            __syncthreads();
        }
        buf ^= 1;
    }
}

// ---------------- fused q/k/v GEMM: blockIdx.y = type*4 + row-tile ----------------
__global__ void __launch_bounds__(128) gemm_qkv(const float* __restrict__ Wq,
                                                const float* __restrict__ Wk,
                                                const float* __restrict__ Wv,
                                                const float* __restrict__ bq,
                                                const float* __restrict__ bk,
                                                const float* __restrict__ bv,
                                                const float* __restrict__ sp,
                                                const float* __restrict__ iv,
                                                int L, int M, int offq, int offkv) {
    __shared__ float As[2][16][72];
    __shared__ float Bs[2][16][72];
    int n = blockIdx.z;
    int type = blockIdx.y >> 2;
    int o0 = (blockIdx.y & 3) * 64, l0 = blockIdx.x * 64;
    const float* W = (type == 0) ? Wq : (type == 1) ? Wk : Wv;
    const float* bias = (type == 0) ? bq : (type == 1) ? bk : bv;
    const float* X = ((type == 0) ? sp : iv) + (size_t)n * CC * L;
    int tid = threadIdx.x, wid = tid >> 5, lane = tid & 31;
    int g = lane >> 2, tg = lane & 3;

    float acc[8][4];
#pragma unroll
    for (int i = 0; i < 8; i++)
#pragma unroll
        for (int j = 0; j < 4; j++) acc[i][j] = 0.f;

    gemm_mainloop(W, X, L, o0, l0, As, Bs, acc, tid, wid, g, tg);

    int r0 = o0 + wid * 16 + g, r1 = r0 + 8;
    float b0v = bias[r0], b1v = bias[r1];
#pragma unroll
    for (int nt = 0; nt < 8; nt++) {
        int l = l0 + nt * 8 + 2 * tg;
        float v00 = acc[nt][0] + b0v, v01 = acc[nt][1] + b0v;
        float v10 = acc[nt][2] + b1v, v11 = acc[nt][3] + b1v;
        if (type == 0) {
            g_q[offq + (size_t)(n * CC + r0) * L + l]     = v00;
            g_q[offq + (size_t)(n * CC + r0) * L + l + 1] = v01;
            g_q[offq + (size_t)(n * CC + r1) * L + l]     = v10;
            g_q[offq + (size_t)(n * CC + r1) * L + l + 1] = v11;
        } else {
            float* dst = (type == 1) ? g_k : g_v;
            size_t i00 = (size_t)offkv + ((size_t)((n * HEADS + (r0 >> 2)) * M) + l) * HD + (r0 & 3);
            size_t i10 = (size_t)offkv + ((size_t)((n * HEADS + (r1 >> 2)) * M) + l) * HD + (r1 & 3);
            dst[i00] = v00; dst[i00 + HD] = v01;
            dst[i10] = v10; dst[i10 + HD] = v11;
        }
    }
}

// ---------------- output GEMM (+residual) ----------------
__global__ void __launch_bounds__(128) gemm_o(const float* __restrict__ W,
                                              const float* __restrict__ bias,
                                              const float* __restrict__ res,
                                              float* __restrict__ dext,
                                              int L, int off) {
    __shared__ float As[2][16][72];
    __shared__ float Bs[2][16][72];
    int n = blockIdx.z;
    int o0 = blockIdx.y * 64, l0 = blockIdx.x * 64;
    const float* X = g_attn + off + (size_t)n * CC * L;
    int tid = threadIdx.x, wid = tid >> 5, lane = tid & 31;
    int g = lane >> 2, tg = lane & 3;

    float acc[8][4];
#pragma unroll
    for (int i = 0; i < 8; i++)
#pragma unroll
        for (int j = 0; j < 4; j++) acc[i][j] = 0.f;

    gemm_mainloop(W, X, L, o0, l0, As, Bs, acc, tid, wid, g, tg);

    int r0 = o0 + wid * 16 + g, r1 = r0 + 8;
    float b0v = bias[r0], b1v = bias[r1];
#pragma unroll
    for (int nt = 0; nt < 8; nt++) {
        int l = l0 + nt * 8 + 2 * tg;
        size_t b = (size_t)(n * CC + r0) * L + l;
        size_t c = (size_t)(n * CC + r1) * L + l;
        dext[off + b]     = acc[nt][0] + b0v + res[b];
        dext[off + b + 1] = acc[nt][1] + b0v + res[b + 1];
        dext[off + c]     = acc[nt][2] + b1v + res[c];
        dext[off + c + 1] = acc[nt][3] + b1v + res[c + 1];
    }
}

// ---------------- HMMA attention: f16-accum S-mma, zero repack -------------------
// Per 16-key iter per tile: 2 S-mma (f16 D, outputs ARE the O-mma A fragment),
// 2 ex2.approx.f16x2 in-place, 1 k16 O-mma (fp32 accum). No cvt in the chain.
// V cols = [v0..v3, 1, ds-indicator, 0, 0] f16; den from ones column; OOB rows zero.
__global__ void __launch_bounds__(128) attn_mma(int qoff, int kvoff, int L, int M,
                                                float* __restrict__ dsout,
                                                float inv_hl, int lvl) {
    __shared__ __align__(16) uint2 s_k[2][128];   // per key: {k01, k23} f16x2
    __shared__ __align__(16) uint4 s_v[2][128];   // per pair: [c01..c31],[1,ds,0,0]
    __shared__ float s_red[4];

    int tid = threadIdx.x, wid = tid >> 5, lane = tid & 31;
    int g = lane >> 2, tg = lane & 3;
    int n = blockIdx.z, h = blockIdx.y;
    int qA = blockIdx.x * 128 + wid * 16 + g;        // tile A rows qA, qA+8
    int qB = qA + 64;                                // tile B rows qB, qB+8
    bool tileB = (blockIdx.x * 128 + 64) < L;

    const float SCALE = 0.5f * 1.4426950408889634f;
    size_t qbase = (size_t)qoff + ((size_t)(n * CC) + h * HD) * L;

    // Build S-mma A fragments for both tiles
    u32 aA0, aA1, aB0, aB1;
    {
        int qBs = tileB ? qB : qA;   // safe load index
        float hA0[4], lA0[4], hA1[4], lA1[4], hB0[4], lB0[4], hB1[4], lB1[4];
#pragma unroll
        for (int d = 0; d < 4; d++) {
            float v = g_q[qbase + (size_t)d * L + qA] * SCALE;
            float hf = __half2float(__float2half(v));
            hA0[d] = hf; lA0[d] = v - hf;
            v = g_q[qbase + (size_t)d * L + qA + 8] * SCALE;
            hf = __half2float(__float2half(v));
            hA1[d] = hf; lA1[d] = v - hf;
            v = g_q[qbase + (size_t)d * L + qBs] * SCALE;
            hf = __half2float(__float2half(v));
            hB0[d] = hf; lB0[d] = v - hf;
            v = g_q[qbase + (size_t)d * L + qBs + 8] * SCALE;
            hf = __half2float(__float2half(v));
            hB1[d] = hf; lB1[d] = v - hf;
        }
        aA0 = (tg == 0) ? pkhf(hA0[0], hA0[1]) : (tg == 1) ? pkhf(hA0[2], hA0[3])
            : (tg == 2) ? pkhf(lA0[0], lA0[1]) : pkhf(lA0[2], lA0[3]);
        aA1 = (tg == 0) ? pkhf(hA1[0], hA1[1]) : (tg == 1) ? pkhf(hA1[2], hA1[3])
            : (tg == 2) ? pkhf(lA1[0], lA1[1]) : pkhf(lA1[2], lA1[3]);
        aB0 = (tg == 0) ? pkhf(hB0[0], hB0[1]) : (tg == 1) ? pkhf(hB0[2], hB0[3])
            : (tg == 2) ? pkhf(lB0[0], lB0[1]) : pkhf(lB0[2], lB0[3]);
        aB1 = (tg == 0) ? pkhf(hB1[0], hB1[1]) : (tg == 1) ? pkhf(hB1[2], hB1[3])
            : (tg == 2) ? pkhf(lB1[0], lB1[1]) : pkhf(lB1[2], lB1[3]);
    }

    const float4* kp = (const float4*)g_k + (kvoff >> 2) + (size_t)(n * HEADS + h) * M;
    const float4* vp = (const float4*)g_v + (kvoff >> 2) + (size_t)(n * HEADS + h) * M;

    float oA0 = 0.f, oA1 = 0.f, oA2 = 0.f, oA3 = 0.f;
    float oB0 = 0.f, oB1 = 0.f, oB2 = 0.f, oB3 = 0.f;
    u32 skb0 = smem_u32(s_k), svb0 = smem_u32(s_v);
    int nch = (M + 127) >> 7;
    const float4 FZ = make_float4(0.f, 0.f, 0.f, 0.f);

    // prologue: stage chunk 0
    {
        float4 kk = (tid < M) ? kp[tid] : FZ;
        s_k[0][tid] = make_uint2(pkhf(kk.x, kk.y), pkhf(kk.z, kk.w));
        if (tid < 64) {
            int m0 = 2 * tid, m1 = m0 + 1;
            float4 v0 = (m0 < M) ? vp[m0] : FZ;
            float4 v1 = (m1 < M) ? vp[m1] : FZ;
            float one0 = (m0 < M) ? 1.f : 0.f, one1 = (m1 < M) ? 1.f : 0.f;
            float dsi0 = (m0 >= L && m0 < M) ? 1.f : 0.f;
            float dsi1 = (m1 >= L && m1 < M) ? 1.f : 0.f;
            s_v[0][2 * tid]     = make_uint4(pkhf(v0.x, v1.x), pkhf(v0.y, v1.y),
                                             pkhf(v0.z, v1.z), pkhf(v0.w, v1.w));
            s_v[0][2 * tid + 1] = make_uint4(pkhf(one0, one1), pkhf(dsi0, dsi1), 0u, 0u);
        }
    }
    __syncthreads();

    int buf = 0;
    for (int t = 0; t < nch; t++) {
        bool pf = (t + 1 < nch);
        float4 kk = FZ, v0 = FZ, v1 = FZ;
        int nb_base = t * 128 + 128;
        if (pf) {
            int m = nb_base + tid;
            if (m < M) kk = kp[m];
            if (tid < 64) {
                int m0 = nb_base + 2 * tid;
                if (m0 < M)     v0 = vp[m0];
                if (m0 + 1 < M) v1 = vp[m0 + 1];
            }
        }

        u32 skb = skb0 + (u32)buf * 1024;
        u32 svb = svb0 + (u32)buf * 2048;
#pragma unroll
        for (int blk = 0; blk < 8; blk++) {      // 16 keys per iteration
            u32 k0f, k1f;
            u32 ka0 = skb + ((u32)(blk * 16 + g) << 3) + ((u32)(tg & 1) << 2);
            u32 ka1 = ka0 + (8u << 3);
            asm("ld.shared.u32 %0,[%1];" : "=r"(k0f) : "r"(ka0));
            asm("ld.shared.u32 %0,[%1];" : "=r"(k1f) : "r"(ka1));
            u32 vb0, vb1;
            u32 va0 = svb + ((u32)(((blk * 2) * 4 + tg) * 8 + g) << 2);
            u32 va1 = va0 + (32u << 2);
            asm("ld.shared.u32 %0,[%1];" : "=r"(vb0) : "r"(va0));
            asm("ld.shared.u32 %0,[%1];" : "=r"(vb1) : "r"(va1));

            // Tile A: 2 S-mma (f16 accum), ex2 in place, 1 k16 O-mma
            u32 w0, w1, w2, w3;
            asm("mma.sync.aligned.m16n8k8.row.col.f16.f16.f16.f16 "
                "{%0,%1},{%2,%3},{%4},{%5,%5};"
                : "=r"(w0), "=r"(w1)
                : "r"(aA0), "r"(aA1), "r"(k0f), "r"(0u));
            asm("mma.sync.aligned.m16n8k8.row.col.f16.f16.f16.f16 "
                "{%0,%1},{%2,%3},{%4},{%5,%5};"
                : "=r"(w2), "=r"(w3)
                : "r"(aA0), "r"(aA1), "r"(k1f), "r"(0u));
            asm("ex2.approx.f16x2 %0,%0;" : "+r"(w0));
            asm("ex2.approx.f16x2 %0,%0;" : "+r"(w1));
            asm("ex2.approx.f16x2 %0,%0;" : "+r"(w2));
            asm("ex2.approx.f16x2 %0,%0;" : "+r"(w3));
            asm("mma.sync.aligned.m16n8k16.row.col.f32.f16.f16.f32 "
                "{%0,%1,%2,%3},{%4,%5,%6,%7},{%8,%9},{%0,%1,%2,%3};"
                : "+f"(oA0), "+f"(oA1), "+f"(oA2), "+f"(oA3)
                : "r"(w0), "r"(w1), "r"(w2), "r"(w3), "r"(vb0), "r"(vb1));

            // Tile B: same
            asm("mma.sync.aligned.m16n8k8.row.col.f16.f16.f16.f16 "
                "{%0,%1},{%2,%3},{%4},{%5,%5};"
                : "=r"(w0), "=r"(w1)
                : "r"(aB0), "r"(aB1), "r"(k0f), "r"(0u));
            asm("mma.sync.aligned.m16n8k8.row.col.f16.f16.f16.f16 "
                "{%0,%1},{%2,%3},{%4},{%5,%5};"
                : "=r"(w2), "=r"(w3)
                : "r"(aB0), "r"(aB1), "r"(k1f), "r"(0u));
            asm("ex2.approx.f16x2 %0,%0;" : "+r"(w0));
            asm("ex2.approx.f16x2 %0,%0;" : "+r"(w1));
            asm("ex2.approx.f16x2 %0,%0;" : "+r"(w2));
            asm("ex2.approx.f16x2 %0,%0;" : "+r"(w3));
            asm("mma.sync.aligned.m16n8k16.row.col.f32.f16.f16.f32 "
                "{%0,%1,%2,%3},{%4,%5,%6,%7},{%8,%9},{%0,%1,%2,%3};"
                : "+f"(oB0), "+f"(oB1), "+f"(oB2), "+f"(oB3)
                : "r"(w0), "r"(w1), "r"(w2), "r"(w3), "r"(vb0), "r"(vb1));
        }

        if (pf) {
            int nb = buf ^ 1;
            s_k[nb][tid] = make_uint2(pkhf(kk.x, kk.y), pkhf(kk.z, kk.w));
            if (tid < 64) {
                int m0 = nb_base + 2 * tid, m1 = m0 + 1;
                float one0 = (m0 < M) ? 1.f : 0.f, one1 = (m1 < M) ? 1.f : 0.f;
                float dsi0 = (m0 >= L && m0 < M) ? 1.f : 0.f;
                float dsi1 = (m1 >= L && m1 < M) ? 1.f : 0.f;
                s_v[nb][2 * tid]     = make_uint4(pkhf(v0.x, v1.x), pkhf(v0.y, v1.y),
                                                  pkhf(v0.z, v1.z), pkhf(v0.w, v1.w));
                s_v[nb][2 * tid + 1] = make_uint4(pkhf(one0, one1), pkhf(dsi0, dsi1), 0u, 0u);
            }
            __syncthreads();
        }
        buf ^= 1;
    }

    // ---- epilogue: per-tile normalization + store; den/ds on tg==2 threads ----
    u32 full = 0xffffffffu;
    int src = (lane & 0x1c) | 2;
    float denA_lo = __shfl_sync(full, oA0, src);
    float denA_hi = __shfl_sync(full, oA2, src);
    float denB_lo = __shfl_sync(full, oB0, src);
    float denB_hi = __shfl_sync(full, oB2, src);
    if (tg < 2) {
        int d0 = tg * 2, d1 = tg * 2 + 1;
        float rl = 1.0f / denA_lo, rh = 1.0f / denA_hi;
        g_attn[qbase + (size_t)d0 * L + qA]     = oA0 * rl;
        g_attn[qbase + (size_t)d1 * L + qA]     = oA1 * rl;
        g_attn[qbase + (size_t)d0 * L + qA + 8] = oA2 * rh;
        g_attn[qbase + (size_t)d1 * L + qA + 8] = oA3 * rh;
        if (tileB) {
            rl = 1.0f / denB_lo; rh = 1.0f / denB_hi;
            g_attn[qbase + (size_t)d0 * L + qB]     = oB0 * rl;
            g_attn[qbase + (size_t)d1 * L + qB]     = oB1 * rl;
            g_attn[qbase + (size_t)d0 * L + qB + 8] = oB2 * rh;
            g_attn[qbase + (size_t)d1 * L + qB + 8] = oB3 * rh;
        }
    }
    float contrib = 0.f;
    if (tg == 2) {
        contrib = oA1 / oA0 + oA3 / oA2;
        if (tileB) contrib += oB1 / oB0 + oB3 / oB2;
    }
#pragma unroll
    for (int off = 16; off > 0; off >>= 1) contrib += __shfl_down_sync(full, contrib, off);
    if (lane == 0) s_red[wid] = contrib;
    __syncthreads();
    if (tid == 0)
        atomicAdd(&dsout[lvl * 2 + n], (s_red[0] + s_red[1] + s_red[2] + s_red[3]) * inv_hl);
}

// ---------------- launch ----------------
extern "C" void kernel_launch(void* const* d_in, const int* in_sizes, int n_in,
                              void* d_out, int out_size) {
    const float* sp[4]; const float* iv[4]; const float* dd[4];
    for (int i = 0; i < 4; i++) {
        sp[i] = (const float*)d_in[i];
        iv[i] = (const float*)d_in[4 + i];
        dd[i] = (const float*)d_in[8 + i];
    }
    const float* Wq  = (const float*)d_in[12]; const float* bq  = (const float*)d_in[13];
    const float* Wk  = (const float*)d_in[14]; const float* bk  = (const float*)d_in[15];
    const float* Wv  = (const float*)d_in[16]; const float* bv  = (const float*)d_in[17];
    const float* Wo  = (const float*)d_in[18]; const float* bo  = (const float*)d_in[19];
    const float* Wdsk = (const float*)d_in[20]; const float* bdsk = (const float*)d_in[21];
    const float* Wdsv = (const float*)d_in[22]; const float* bdsv = (const float*)d_in[23];
    const float* gate = (const float*)d_in[24];
    float* out = (float*)d_out;

    static const int Lt[4]    = {4096, 1024, 256, 64};
    static const int qoff[4]  = {0, 2097152, 2621440, 2752512};
    static const int kvoff[4] = {0, 2113536, 2654208, 2801664};
    float* dsout = out + (out_size - 8);

    pooled_kernel<<<dim3(256, 2, 4), 256>>>(dd[0], dd[1], dd[2], dd[3], dsout);
    token_kernel<<<dim3(1024, 2, 8), 256>>>(Wdsk, bdsk, Wdsv, bdsv, gate);

    for (int lv = 0; lv < 4; lv++) {
        int L = Lt[lv], M = L + 32;
        gemm_qkv<<<dim3(L / 64, 12, 2), 128>>>(Wq + lv * 65536, Wk + lv * 65536,
                                               Wv + lv * 65536, bq + lv * 256,
                                               bk + lv * 256, bv + lv * 256,
                                               sp[lv], iv[lv], L, M, qoff[lv], kvoff[lv]);
        int gx = (L + 127) / 128;
        attn_mma<<<dim3(gx, HEADS, 2), 128>>>(qoff[lv], kvoff[lv], L, M,
                                              dsout, 1.0f / (64.0f * (float)L), lv);
    }
    for (int lv = 0; lv < 4; lv++) {
        int L = Lt[lv];
        gemm_o<<<dim3(L / 64, 4, 2), 128>>>(Wo + lv * 65536, bo + lv * 256,
                                            sp[lv], out, L, qoff[lv]);
    }
}